// round 9
// baseline (speedup 1.0000x reference)
#include <cuda_runtime.h>
#include <math.h>

#define NN 32768
#define EE 524288
#define EENP (EE + NN)          // padded src-sorted capacity (557056 = 256*2176)
#define CC 16
#define MIDD 32
#define HH 8
#define Y0F 0.28209479177387814f
#define CUTOFFF 4.6f
#define KCOULF 0.529f

typedef unsigned long long ull;

// ---------------- device scratch ----------------
__device__ __align__(16) float g_x[NN * CC];
__device__ __align__(16) float g_S[NN * CC];
__device__ __align__(16) float g_q[NN * HH];
__device__ __align__(16) float g_u[NN * MIDD];
__device__ __align__(16) float g_P[NN * 512];     // pair-interleaved
__device__ __align__(16) float g_PB[NN * CC];     // pair-interleaved
__device__ __align__(16) float g_feats[NN * CC];
__device__ __align__(16) float g_vk[(size_t)EENP * CC]; // padded src-sorted {val,key} pairs
__device__ float g_distS[EENP];
__device__ float g_scaleS[EENP];
__device__ __align__(8) int2 g_es[EE];            // dst-order: {src-order idx, scale bits}
__device__ float g_coulN[NN];
__device__ int g_srcS[EENP];
__device__ int g_csrc[NN], g_cdst[NN];
__device__ int g_rdst[NN + 1];
__device__ int g_cursrc[NN], g_curdst[NN];

// ---------------- f32x2 helpers ----------------
__device__ __forceinline__ ull pack2(float a, float b) {
    ull r;
    asm("mov.b64 %0, {%1, %2};" : "=l"(r) : "f"(a), "f"(b));
    return r;
}
__device__ __forceinline__ ull fma2(ull a, ull b, ull c) {
    ull d;
    asm("fma.rn.f32x2 %0, %1, %2, %3;" : "=l"(d) : "l"(a), "l"(b), "l"(c));
    return d;
}
__device__ __forceinline__ void unpack2(ull v, float& lo, float& hi) {
    asm("mov.b64 {%0, %1}, %2;" : "=f"(lo), "=f"(hi) : "l"(v));
}

// ---------------- init: node init + edge histogram ----------------
__global__ void k_init(const int* __restrict__ species, const float* __restrict__ emb,
                       float* __restrict__ out,
                       const int* __restrict__ src, const int* __restrict__ dst) {
    int e = blockIdx.x * 256 + threadIdx.x;
    if (e < NN) {
        int sp = species[e] - 1;
#pragma unroll
        for (int c = 0; c < CC; c++) {
            g_x[e * CC + c] = emb[sp * CC + c];
            g_S[e * CC + c] = 0.f;
        }
        g_coulN[e] = 0.f;
        if (e == 0) out[0] = 0.f;
    }
    atomicAdd(&g_csrc[src[e]], 1);
    atomicAdd(&g_cdst[dst[e]], 1);
}

// ---------------- scan: src side padded to even; counters reset ----------------
__global__ void k_scan() {
    const int T = 1024, PER = NN / 1024;
    __shared__ int part[T];
    int t = threadIdx.x;
    int base = t * PER;
    if (blockIdx.x == 0) {
        int loc[PER], locp[PER];
        int s = 0;
#pragma unroll
        for (int i = 0; i < PER; i++) {
            loc[i] = g_csrc[base + i];
            g_csrc[base + i] = 0;
            locp[i] = (loc[i] + 1) & ~1;
            s += locp[i];
        }
        part[t] = s;
        __syncthreads();
        for (int off = 1; off < T; off <<= 1) {
            int v = (t >= off) ? part[t - off] : 0;
            __syncthreads();
            part[t] += v;
            __syncthreads();
        }
        int run = part[t] - s;
#pragma unroll
        for (int i = 0; i < PER; i++) {
            g_cursrc[base + i] = run;
            if (loc[i] & 1) g_srcS[run + loc[i]] = base + i;
            run += locp[i];
        }
    } else {
        int loc[PER];
        int s = 0;
#pragma unroll
        for (int i = 0; i < PER; i++) {
            loc[i] = g_cdst[base + i];
            g_cdst[base + i] = 0;
            s += loc[i];
        }
        part[t] = s;
        __syncthreads();
        for (int off = 1; off < T; off <<= 1) {
            int v = (t >= off) ? part[t - off] : 0;
            __syncthreads();
            part[t] += v;
            __syncthreads();
        }
        int run = part[t] - s;
#pragma unroll
        for (int i = 0; i < PER; i++) {
            g_rdst[base + i] = run;
            g_curdst[base + i] = run;
            run += loc[i];
        }
        if (t == T - 1) g_rdst[NN] = run;
    }
}

// ---------------- scatter: sorted orders + geometry + coulomb atomics ----------------
__global__ void __launch_bounds__(256)
k_scatter(const int* __restrict__ src, const int* __restrict__ dst,
          const float* __restrict__ rel_pos, const int* __restrict__ species) {
    int e = blockIdx.x * 256 + threadIdx.x;
    int s = src[e], d = dst[e];
    float px = rel_pos[e * 3 + 0], py = rel_pos[e * 3 + 1], pz = rel_pos[e * 3 + 2];
    float dist = sqrtf(px * px + py * py + pz * pz);
    float xc = dist / CUTOFFF;
    bool in_cut = dist < CUTOFFF;
    float x2 = in_cut ? fminf(xc * xc, 1.f - 1e-6f) : 0.f;
    float scale = in_cut ? expf(3.f - 3.f / (1.f - x2)) : 0.f;

    int ps = atomicAdd(&g_cursrc[s], 1);
    int pd = atomicAdd(&g_curdst[d], 1);
    g_srcS[ps] = s;
    g_distS[ps] = dist;
    g_scaleS[ps] = scale;
    g_es[pd] = make_int2(ps, __float_as_int(scale));

    float Zu = (float)species[s];
    float Zv = (float)species[d];
    float raw = KCOULF * Zu * Zv / (2.f * dist);
    float au = 0.8854f * 0.529f / (__powf(Zu, 0.23f) + __powf(Zv, 0.23f));
    float xx = dist / au;
    float screen = 0.1818f * __expf(-3.2f * xx) + 0.5099f * __expf(-0.9423f * xx)
                 + 0.2802f * __expf(-0.4028f * xx) + 0.02817f * __expf(-0.2016f * xx);
    float contrib = raw * screen * scale;
    if (contrib != 0.f) atomicAdd(&g_coulN[d], contrib);
}

// ---------------- shared node-prep helpers ----------------
#define W3P_STRIDE 1036
#define NLT 512                 // node-layer threads
#define NLN 64                  // nodes per node-layer block

__device__ __forceinline__ void load_node_weights(
    int tid, int nth, const float* __restrict__ W3, const float* __restrict__ b3,
    const float* __restrict__ W1n, const float* __restrict__ b1n,
    const float* __restrict__ Wq, const float* __restrict__ Wself,
    float* sW3p, float* sW1, float* sWq, float* sb3, float* sb1, float* sWself) {
    for (int idx = tid; idx < MIDD * 256; idx += nth) {
        int m = idx >> 8, k = idx & 255;
        int o = k >> 4, i = k & 15;
        sW3p[(o & 7) * W3P_STRIDE + i * 64 + m * 2 + (o >> 3)] = W3[idx];
    }
    for (int idx = tid; idx < CC * MIDD; idx += nth) sW1[idx] = W1n[idx];
    if (Wq && tid < HH * CC) sWq[tid] = Wq[tid];
    if (tid < 256) sb3[tid] = b3[tid];
    if (tid < MIDD) sb1[tid] = b1n[tid];
    if (Wself && tid < CC * CC) sWself[tid] = Wself[tid];
}

__device__ __forceinline__ void node_prep(
    int n, int nloc, int j, bool do_q, bool do_feats,
    const float* sW3p, const float* sW1, const float* sWq,
    const float* sb3, const float* sb1, const float* sWself,
    const float* sXn, const float* sSn) {
    if (do_q) {
        float qa = 0.f;
#pragma unroll
        for (int c = 0; c < CC; c++) qa = fmaf(sWq[j * CC + c], sXn[nloc * CC + c], qa);
        g_q[n * HH + j] = qa;
    }
    {
        float u0 = sb1[j], u1 = sb1[j + 8], u2 = sb1[j + 16], u3 = sb1[j + 24];
#pragma unroll
        for (int c = 0; c < CC; c++) {
            float sv = sSn[nloc * CC + c];
            u0 = fmaf(sv, sW1[c * MIDD + j], u0);
            u1 = fmaf(sv, sW1[c * MIDD + j + 8], u1);
            u2 = fmaf(sv, sW1[c * MIDD + j + 16], u2);
            u3 = fmaf(sv, sW1[c * MIDD + j + 24], u3);
        }
        g_u[n * MIDD + j] = u0;
        g_u[n * MIDD + j + 8] = u1;
        g_u[n * MIDD + j + 16] = u2;
        g_u[n * MIDD + j + 24] = u3;
    }
    {
        float pb0 = 0.f, pb1 = 0.f;
#pragma unroll
        for (int i = 0; i < CC; i++) {
            float xv = sXn[nloc * CC + i];
            pb0 = fmaf(sb3[j * CC + i], xv, pb0);
            pb1 = fmaf(sb3[(j + 8) * CC + i], xv, pb1);
        }
        g_PB[n * CC + j * 2] = pb0;
        g_PB[n * CC + j * 2 + 1] = pb1;
    }
    if (do_feats) {
        float f0 = 0.f, f1 = 0.f;
#pragma unroll
        for (int i = 0; i < CC; i++) {
            float xv = sXn[nloc * CC + i];
            f0 = fmaf(sWself[j * CC + i], xv, f0);
            f1 = fmaf(sWself[(j + 8) * CC + i], xv, f1);
        }
        g_feats[n * CC + j] = f0;
        g_feats[n * CC + 8 + j] = f1;
    }
    {
        ull acc[8][4];
#pragma unroll
        for (int mq = 0; mq < 8; mq++)
#pragma unroll
            for (int r = 0; r < 4; r++) acc[mq][r] = 0ULL;
#pragma unroll
        for (int i = 0; i < CC; i++) {
            float xv = sXn[nloc * CC + i];
            ull xx = pack2(xv, xv);
            const ull* wp = (const ull*)&sW3p[j * W3P_STRIDE + i * 64];
#pragma unroll
            for (int mq = 0; mq < 8; mq++) {
                acc[mq][0] = fma2(xx, wp[mq * 4 + 0], acc[mq][0]);
                acc[mq][1] = fma2(xx, wp[mq * 4 + 1], acc[mq][1]);
                acc[mq][2] = fma2(xx, wp[mq * 4 + 2], acc[mq][2]);
                acc[mq][3] = fma2(xx, wp[mq * 4 + 3], acc[mq][3]);
            }
        }
        float* Pn = g_P + (size_t)n * 512;
#pragma unroll
        for (int mq = 0; mq < 8; mq++) {
            *(ulonglong2*)(Pn + mq * 64 + j * 8)     = make_ulonglong2(acc[mq][0], acc[mq][1]);
            *(ulonglong2*)(Pn + mq * 64 + j * 8 + 4) = make_ulonglong2(acc[mq][2], acc[mq][3]);
        }
    }
}

// ---------------- initial node prep (layer 0, x=emb, S=0) ----------------
__global__ void __launch_bounds__(NLT)
k_nodeprep0(const float* __restrict__ Wq, const float* __restrict__ W3,
            const float* __restrict__ b3, const float* __restrict__ W1n,
            const float* __restrict__ b1n) {
    __shared__ float sW3p[8 * W3P_STRIDE];
    __shared__ float sW1[CC * MIDD];
    __shared__ float sWq[HH * CC];
    __shared__ float sb3[256];
    __shared__ float sb1[MIDD];
    __shared__ float sXn[NLN * CC];
    __shared__ float sSn[NLN * CC];
    int tid = threadIdx.x;
    load_node_weights(tid, NLT, W3, b3, W1n, b1n, Wq, nullptr,
                      sW3p, sW1, sWq, sb3, sb1, nullptr);
    int nloc = tid >> 3, j = tid & 7;
    int n = blockIdx.x * NLN + nloc;
    sXn[nloc * CC + j] = g_x[n * CC + j];
    sXn[nloc * CC + 8 + j] = g_x[n * CC + 8 + j];
    sSn[nloc * CC + j] = 0.f;
    sSn[nloc * CC + 8 + j] = 0.f;
    __syncthreads();
    node_prep(n, nloc, j, true, false, sW3p, sW1, sWq, sb3, sb1, nullptr, sXn, sSn);
}

// ---------------- node layer: one-pass online-softmax attention + Wproj + prep ----------------
__global__ void __launch_bounds__(NLT)
k_node_layer(int mode,
             const float* __restrict__ Wproj,
             const float* __restrict__ Wq,
             const float* __restrict__ W3,
             const float* __restrict__ b3,
             const float* __restrict__ W1n,
             const float* __restrict__ b1n,
             const float* __restrict__ Wself) {
    __shared__ float sW3p[8 * W3P_STRIDE];
    __shared__ float sW1[CC * MIDD];
    __shared__ float sWq[HH * CC];
    __shared__ float sWproj[CC * 24];
    __shared__ float sb3[256];
    __shared__ float sb1[MIDD];
    __shared__ float sWself[CC * CC];
    __shared__ float sAgg[NLN * HH];
    __shared__ float sXold[NLN * CC];
    __shared__ float sXn[NLN * CC];
    __shared__ float sSn[NLN * CC];

    int tid = threadIdx.x;
    int nloc = tid >> 3, j = tid & 7;
    int n = blockIdx.x * NLN + nloc;

    load_node_weights(tid, NLT, W3, b3, W1n, b1n,
                      mode != 2 ? Wq : nullptr,
                      mode == 2 ? Wself : nullptr,
                      sW3p, sW1, sWq, sb3, sb1, sWself);
    for (int idx = tid; idx < CC * 24; idx += NLT) sWproj[idx] = Wproj[idx];

    {
        int beg = g_rdst[n], end = g_rdst[n + 1];
        float qj = g_q[n * HH + j];
        float m = -INFINITY, num = 0.f, den = 0.f;
#pragma unroll 2
        for (int i = beg; i < end; i++) {
            int2 es = g_es[i];
            float2 vk = *(const float2*)(g_vk + (size_t)es.x * CC + j * 2);
            float sc = __int_as_float(es.y);
            float l = vk.y * qj;
            float mn = fmaxf(m, l);
            float corr = __expf(m - mn);
            float p = sc * __expf(l - mn);
            den = den * corr + p;
            num = fmaf(num, corr, p * vk.x);
            m = mn;
        }
        sAgg[nloc * HH + j] = num / fmaxf(den, 1e-20f);
        sXold[nloc * CC + j] = g_x[n * CC + j];
        sXold[nloc * CC + 8 + j] = g_x[n * CC + 8 + j];
        __syncthreads();
        float xn0 = 0.f, xn1 = 0.f;
#pragma unroll
        for (int k = 0; k < 8; k++) {
            float a = sAgg[nloc * HH + k];
            xn0 = fmaf(sWproj[j * 24 + k], a, xn0);
            xn1 = fmaf(sWproj[(j + 8) * 24 + k], a, xn1);
        }
#pragma unroll
        for (int k = 0; k < CC; k++) {
            float xo = sXold[nloc * CC + k];
            xn0 = fmaf(sWproj[j * 24 + 8 + k], xo, xn0);
            xn1 = fmaf(sWproj[(j + 8) * 24 + 8 + k], xo, xn1);
        }
        float s0 = g_S[n * CC + j] + xn0;
        float s1 = g_S[n * CC + 8 + j] + xn1;
        g_x[n * CC + j] = xn0;     g_x[n * CC + 8 + j] = xn1;
        g_S[n * CC + j] = s0;      g_S[n * CC + 8 + j] = s1;
        sXn[nloc * CC + j] = xn0;  sXn[nloc * CC + 8 + j] = xn1;
        sSn[nloc * CC + j] = s0;   sSn[nloc * CC + 8 + j] = s1;
        __syncthreads();
    }

    node_prep(n, nloc, j, mode != 2, mode == 2,
              sW3p, sW1, sWq, sb3, sb1, sWself, sXn, sSn);
}

// ---------------- edge kernel: 2 same-src edges/thread, smem-staged coalesced stores ----------------
__global__ void __launch_bounds__(128, 4)
k_edge(const float* __restrict__ W1, const float* __restrict__ W2,
       const float* __restrict__ b2) {
    __shared__ __align__(16) ull sW2p[512];   // [i2][jp]
    __shared__ float sw15[MIDD];
    __shared__ __align__(16) ull sB2p[16];
    __shared__ __align__(16) float sSt[4][32 * 36];
    int tid = threadIdx.x;
    for (int i = tid; i < 512; i += 128) sW2p[i] = ((const ull*)W2)[i];
    if (tid < MIDD) sw15[tid] = W1[15 * MIDD + tid];
    if (tid < 16) sB2p[tid] = ((const ull*)b2)[tid];
    __syncthreads();

    int t = blockIdx.x * 128 + tid;
    int e0 = 2 * t;
    int s = g_srcS[e0];
    float2 dd = *(const float2*)(g_distS + e0);
    float2 sc = *(const float2*)(g_scaleS + e0);
    float da = dd.x, db = dd.y;
    float bsa = Y0F * sc.x, bsb = Y0F * sc.y;

    float u[MIDD];
    {
        const float4* up = (const float4*)(g_u + (size_t)s * MIDD);
#pragma unroll
        for (int k = 0; k < 8; k++) {
            float4 v = up[k];
            u[4 * k] = v.x; u[4 * k + 1] = v.y; u[4 * k + 2] = v.z; u[4 * k + 3] = v.w;
        }
    }

    ull acca[16], accb[16];
#pragma unroll
    for (int jp = 0; jp < 16; jp++) { acca[jp] = sB2p[jp]; accb[jp] = sB2p[jp]; }
#pragma unroll
    for (int i2 = 0; i2 < MIDD; i2++) {
        float w15v = sw15[i2];
        float ha = fmaxf(fmaf(da, w15v, u[i2]), 0.f);
        float hb = fmaxf(fmaf(db, w15v, u[i2]), 0.f);
        ull xa = pack2(ha, ha);
        ull xb = pack2(hb, hb);
#pragma unroll
        for (int jq = 0; jq < 8; jq++) {
            ulonglong2 w = *(const ulonglong2*)&sW2p[i2 * 16 + jq * 2];
            acca[2 * jq]     = fma2(xa, w.x, acca[2 * jq]);
            acca[2 * jq + 1] = fma2(xa, w.y, acca[2 * jq + 1]);
            accb[2 * jq]     = fma2(xb, w.x, accb[2 * jq]);
            accb[2 * jq + 1] = fma2(xb, w.y, accb[2 * jq + 1]);
        }
    }
    float h2a[MIDD], h2b[MIDD];
#pragma unroll
    for (int jp = 0; jp < 16; jp++) {
        float lo, hi;
        unpack2(acca[jp], lo, hi);
        h2a[2 * jp] = fmaxf(lo, 0.f); h2a[2 * jp + 1] = fmaxf(hi, 0.f);
        unpack2(accb[jp], lo, hi);
        h2b[2 * jp] = fmaxf(lo, 0.f); h2b[2 * jp + 1] = fmaxf(hi, 0.f);
    }

    ull ka[8], kb[8];
    {
        const ulonglong2* pbp = (const ulonglong2*)(g_PB + (size_t)s * CC);
#pragma unroll
        for (int q = 0; q < 4; q++) {
            ulonglong2 pb = pbp[q];
            ka[2 * q] = pb.x; ka[2 * q + 1] = pb.y;
            kb[2 * q] = pb.x; kb[2 * q + 1] = pb.y;
        }
    }
    const ull* Pp = (const ull*)(g_P + (size_t)s * 512);
#pragma unroll
    for (int mq = 0; mq < 8; mq++) {
        ull xa0 = pack2(h2a[mq * 4 + 0], h2a[mq * 4 + 0]);
        ull xa1 = pack2(h2a[mq * 4 + 1], h2a[mq * 4 + 1]);
        ull xa2 = pack2(h2a[mq * 4 + 2], h2a[mq * 4 + 2]);
        ull xa3 = pack2(h2a[mq * 4 + 3], h2a[mq * 4 + 3]);
        ull xb0 = pack2(h2b[mq * 4 + 0], h2b[mq * 4 + 0]);
        ull xb1 = pack2(h2b[mq * 4 + 1], h2b[mq * 4 + 1]);
        ull xb2 = pack2(h2b[mq * 4 + 2], h2b[mq * 4 + 2]);
        ull xb3 = pack2(h2b[mq * 4 + 3], h2b[mq * 4 + 3]);
#pragma unroll
        for (int j = 0; j < 8; j++) {
            ulonglong2 pA = *(const ulonglong2*)(Pp + mq * 32 + j * 4);
            ulonglong2 pB = *(const ulonglong2*)(Pp + mq * 32 + j * 4 + 2);
            ka[j] = fma2(xa0, pA.x, ka[j]);
            ka[j] = fma2(xa1, pA.y, ka[j]);
            ka[j] = fma2(xa2, pB.x, ka[j]);
            ka[j] = fma2(xa3, pB.y, ka[j]);
            kb[j] = fma2(xb0, pA.x, kb[j]);
            kb[j] = fma2(xb1, pA.y, kb[j]);
            kb[j] = fma2(xb2, pB.x, kb[j]);
            kb[j] = fma2(xb3, pB.y, kb[j]);
        }
    }

    int lane = tid & 31, w = tid >> 5;
    float* st = sSt[w];
#pragma unroll
    for (int q = 0; q < 4; q++) {
        float a0, a1, a2, a3;
        unpack2(ka[2 * q], a0, a1);
        unpack2(ka[2 * q + 1], a2, a3);
        *(float4*)&st[lane * 36 + q * 4] = make_float4(a0 * bsa, a1 * bsa, a2 * bsa, a3 * bsa);
    }
#pragma unroll
    for (int q = 0; q < 4; q++) {
        float a0, a1, a2, a3;
        unpack2(kb[2 * q], a0, a1);
        unpack2(kb[2 * q + 1], a2, a3);
        *(float4*)&st[lane * 36 + 16 + q * 4] = make_float4(a0 * bsb, a1 * bsb, a2 * bsb, a3 * bsb);
    }
    __syncwarp();
    float4* gbase = (float4*)(g_vk + (size_t)(blockIdx.x * 256 + w * 64) * CC);
#pragma unroll
    for (int g = 0; g < 8; g++) {
        int f = g * 32 + lane;
        int owner = f >> 3, q = f & 7;
        gbase[f] = *(const float4*)&st[owner * 36 + q * 4];
    }
}

// ---------------- final ----------------
__device__ __forceinline__ float siluf(float x) { return x / (1.f + __expf(-x)); }

__global__ void k_final(const int* __restrict__ species, const float* __restrict__ emb,
                        const float* __restrict__ W1, const float* __restrict__ b1,
                        const float* __restrict__ W2, const float* __restrict__ b2,
                        const float* __restrict__ W3, const float* __restrict__ b3,
                        float* __restrict__ out) {
    __shared__ float sFeat[16 * 17];
    __shared__ float sEmb[16 * 17];
    __shared__ float sH[16 * 17];
    __shared__ float sRed[16];
    int tid = threadIdx.x;
    int nloc = tid >> 4, o = tid & 15;
    int n = blockIdx.x * 16 + nloc;
    int beg = g_rdst[n], end = g_rdst[n + 1];
    int o2 = (o < 8) ? o * 2 : (o - 8) * 2 + 1;
    float f = g_feats[n * CC + o];
    for (int i = beg; i < end; i++) {
        int ei = g_es[i].x;
        f += g_vk[(size_t)ei * CC + o2];
    }
    sFeat[nloc * 17 + o] = f;
    int sp = species[n] - 1;
    sEmb[nloc * 17 + o] = emb[sp * CC + o];
    __syncthreads();

    float h1 = b1[o];
#pragma unroll
    for (int k = 0; k < CC; k++) h1 = fmaf(sEmb[nloc * 17 + k], W1[k * CC + o], h1);
#pragma unroll
    for (int k = 0; k < CC; k++) h1 = fmaf(sFeat[nloc * 17 + k], W1[(CC + k) * CC + o], h1);
    sH[nloc * 17 + o] = siluf(h1);
    __syncthreads();

    float h2 = b2[o];
#pragma unroll
    for (int k = 0; k < CC; k++) h2 = fmaf(sH[nloc * 17 + k], W2[k * CC + o], h2);
    h2 = siluf(h2);

    float part = h2 * W3[o];
#pragma unroll
    for (int off = 8; off > 0; off >>= 1)
        part += __shfl_down_sync(0xffffffffu, part, off, 16);
    if (o == 0) sRed[nloc] = part + b3[0] + g_coulN[n];
    __syncthreads();
    if (tid == 0) {
        float acc = 0.f;
#pragma unroll
        for (int k = 0; k < 16; k++) acc += sRed[k];
        atomicAdd(out, acc);
    }
}

// ---------------- host launch ----------------
extern "C" void kernel_launch(void* const* d_in, const int* in_sizes, int n_in,
                              void* d_out, int out_size) {
    const int* species  = (const int*)d_in[0];
    const int* src      = (const int*)d_in[1];
    const int* dst      = (const int*)d_in[2];
    const float* rel_pos = (const float*)d_in[3];
    const float* emb    = (const float*)d_in[4];
    const float* kv_W1  = (const float*)d_in[5];
    const float* kv_b1  = (const float*)d_in[6];
    const float* kv_W2  = (const float*)d_in[7];
    const float* kv_b2  = (const float*)d_in[8];
    const float* kv_W3  = (const float*)d_in[9];
    const float* kv_b3  = (const float*)d_in[10];
    const float* Wq     = (const float*)d_in[11];
    const float* Wproj  = (const float*)d_in[12];
    const float* fin_W1 = (const float*)d_in[13];
    const float* fin_b1 = (const float*)d_in[14];
    const float* fin_W2 = (const float*)d_in[15];
    const float* fin_b2 = (const float*)d_in[16];
    const float* fin_W3 = (const float*)d_in[17];
    const float* fin_b3 = (const float*)d_in[18];
    const float* Wself  = (const float*)d_in[19];
    const float* mlp_W1 = (const float*)d_in[20];
    const float* mlp_b1 = (const float*)d_in[21];
    const float* mlp_W2 = (const float*)d_in[22];
    const float* mlp_b2 = (const float*)d_in[23];
    const float* mlp_W3 = (const float*)d_in[24];
    const float* mlp_b3 = (const float*)d_in[25];
    float* out = (float*)d_out;

    const int EB = EE / 256;         // 2048
    const int LB = NN / NLN;         // 512
    const int EDGB = EENP / 256;     // 2176

    k_init<<<EB, 256>>>(species, emb, out, src, dst);
    k_scan<<<2, 1024>>>();
    k_scatter<<<EB, 256>>>(src, dst, rel_pos, species);
    k_nodeprep0<<<LB, NLT>>>(Wq, kv_W3, kv_b3, kv_W1, kv_b1);

    for (int l = 0; l < 4; l++) {
        k_edge<<<EDGB, 128>>>(kv_W1 + (size_t)l * CC * MIDD,
                              kv_W2 + (size_t)l * MIDD * MIDD,
                              kv_b2 + (size_t)l * MIDD);
        if (l < 3) {
            k_node_layer<<<LB, NLT>>>(1,
                Wproj + (size_t)l * CC * 24,
                Wq + (size_t)(l + 1) * HH * CC,
                kv_W3 + (size_t)(l + 1) * MIDD * 256,
                kv_b3 + (size_t)(l + 1) * 256,
                kv_W1 + (size_t)(l + 1) * CC * MIDD,
                kv_b1 + (size_t)(l + 1) * MIDD,
                nullptr);
        } else {
            k_node_layer<<<LB, NLT>>>(2,
                Wproj + (size_t)l * CC * 24,
                nullptr,
                fin_W3, fin_b3, fin_W1, fin_b1, Wself);
        }
    }
    k_edge<<<EDGB, 128>>>(fin_W1, fin_W2, fin_b2);
    k_final<<<NN / 16, 256>>>(species, emb, mlp_W1, mlp_b1, mlp_W2, mlp_b2,
                              mlp_W3, mlp_b3, out);
}

// round 11
// speedup vs baseline: 1.1137x; 1.1137x over previous
#include <cuda_runtime.h>
#include <math.h>

#define NN 32768
#define EE 524288
#define EENP (EE + NN)          // padded src-sorted capacity (557056 = 256*2176)
#define CC 16
#define MIDD 32
#define HH 8
#define Y0F 0.28209479177387814f
#define CUTOFFF 4.6f
#define KCOULF 0.529f

typedef unsigned long long ull;

// ---------------- device scratch ----------------
__device__ __align__(16) float g_x[NN * CC];
__device__ __align__(16) float g_S[NN * CC];
__device__ __align__(16) float g_q[NN * HH];
__device__ __align__(16) float g_u[NN * MIDD];
__device__ __align__(16) float g_P[NN * 512];     // pair-interleaved
__device__ __align__(16) float g_PB[NN * CC];     // pair-interleaved
__device__ __align__(16) float g_feats[NN * CC];
__device__ __align__(16) float g_vk[(size_t)EENP * CC]; // padded src-sorted {val,key}
__device__ float g_distS[EENP];
__device__ float g_scaleS[EENP];
__device__ __align__(8) int2 g_es[EE];            // dst-order: {src-order idx, scale bits}
__device__ float g_coulN[NN];
__device__ int g_srcS[EENP];
__device__ int g_csrc[NN], g_cdst[NN];
__device__ int g_rdst[NN + 1];
__device__ int g_cursrc[NN], g_curdst[NN];

// ---------------- f32x2 helpers ----------------
__device__ __forceinline__ ull pack2(float a, float b) {
    ull r;
    asm("mov.b64 %0, {%1, %2};" : "=l"(r) : "f"(a), "f"(b));
    return r;
}
__device__ __forceinline__ ull fma2(ull a, ull b, ull c) {
    ull d;
    asm("fma.rn.f32x2 %0, %1, %2, %3;" : "=l"(d) : "l"(a), "l"(b), "l"(c));
    return d;
}
__device__ __forceinline__ void unpack2(ull v, float& lo, float& hi) {
    asm("mov.b64 {%0, %1}, %2;" : "=f"(lo), "=f"(hi) : "l"(v));
}

// ---------------- init ----------------
__global__ void k_init(const int* __restrict__ species, const float* __restrict__ emb,
                       float* __restrict__ out,
                       const int* __restrict__ src, const int* __restrict__ dst) {
    int e = blockIdx.x * 256 + threadIdx.x;
    if (e < NN) {
        int sp = species[e] - 1;
#pragma unroll
        for (int c = 0; c < CC; c++) {
            g_x[e * CC + c] = emb[sp * CC + c];
            g_S[e * CC + c] = 0.f;
        }
        g_coulN[e] = 0.f;
        if (e == 0) out[0] = 0.f;
    }
    atomicAdd(&g_csrc[src[e]], 1);
    atomicAdd(&g_cdst[dst[e]], 1);
}

// ---------------- scan ----------------
__global__ void k_scan() {
    const int T = 1024, PER = NN / 1024;
    __shared__ int part[T];
    int t = threadIdx.x;
    int base = t * PER;
    if (blockIdx.x == 0) {
        int loc[PER], locp[PER];
        int s = 0;
#pragma unroll
        for (int i = 0; i < PER; i++) {
            loc[i] = g_csrc[base + i];
            g_csrc[base + i] = 0;
            locp[i] = (loc[i] + 1) & ~1;
            s += locp[i];
        }
        part[t] = s;
        __syncthreads();
        for (int off = 1; off < T; off <<= 1) {
            int v = (t >= off) ? part[t - off] : 0;
            __syncthreads();
            part[t] += v;
            __syncthreads();
        }
        int run = part[t] - s;
#pragma unroll
        for (int i = 0; i < PER; i++) {
            g_cursrc[base + i] = run;
            if (loc[i] & 1) g_srcS[run + loc[i]] = base + i;
            run += locp[i];
        }
    } else {
        int loc[PER];
        int s = 0;
#pragma unroll
        for (int i = 0; i < PER; i++) {
            loc[i] = g_cdst[base + i];
            g_cdst[base + i] = 0;
            s += loc[i];
        }
        part[t] = s;
        __syncthreads();
        for (int off = 1; off < T; off <<= 1) {
            int v = (t >= off) ? part[t - off] : 0;
            __syncthreads();
            part[t] += v;
            __syncthreads();
        }
        int run = part[t] - s;
#pragma unroll
        for (int i = 0; i < PER; i++) {
            g_rdst[base + i] = run;
            g_curdst[base + i] = run;
            run += loc[i];
        }
        if (t == T - 1) g_rdst[NN] = run;
    }
}

// ---------------- scatter ----------------
__global__ void __launch_bounds__(256)
k_scatter(const int* __restrict__ src, const int* __restrict__ dst,
          const float* __restrict__ rel_pos, const int* __restrict__ species) {
    int e = blockIdx.x * 256 + threadIdx.x;
    int s = src[e], d = dst[e];
    float px = rel_pos[e * 3 + 0], py = rel_pos[e * 3 + 1], pz = rel_pos[e * 3 + 2];
    float dist = sqrtf(px * px + py * py + pz * pz);
    float xc = dist / CUTOFFF;
    bool in_cut = dist < CUTOFFF;
    float x2 = in_cut ? fminf(xc * xc, 1.f - 1e-6f) : 0.f;
    float scale = in_cut ? expf(3.f - 3.f / (1.f - x2)) : 0.f;

    int ps = atomicAdd(&g_cursrc[s], 1);
    int pd = atomicAdd(&g_curdst[d], 1);
    g_srcS[ps] = s;
    g_distS[ps] = dist;
    g_scaleS[ps] = scale;
    g_es[pd] = make_int2(ps, __float_as_int(scale));

    float Zu = (float)species[s];
    float Zv = (float)species[d];
    float raw = KCOULF * Zu * Zv / (2.f * dist);
    float au = 0.8854f * 0.529f / (__powf(Zu, 0.23f) + __powf(Zv, 0.23f));
    float xx = dist / au;
    float screen = 0.1818f * __expf(-3.2f * xx) + 0.5099f * __expf(-0.9423f * xx)
                 + 0.2802f * __expf(-0.4028f * xx) + 0.02817f * __expf(-0.2016f * xx);
    float contrib = raw * screen * scale;
    if (contrib != 0.f) atomicAdd(&g_coulN[d], contrib);
}

// ---------------- node-prep helpers (conflict-free padded layouts) ----------------
#define NLT 256                 // node-layer threads
#define NLN 32                  // nodes per block
#define W3S 288                 // per-m stride: 16 o-slots of 18

__device__ __forceinline__ void load_node_weights(
    int tid, const float* __restrict__ W3, const float* __restrict__ b3,
    const float* __restrict__ W1n, const float* __restrict__ b1n,
    const float* __restrict__ Wq, const float* __restrict__ Wself,
    float* sW3, float* sW1, float* sWq, float* sb3, float* sb1, float* sWself) {
    // sW3[m*288 + o*18 + i] — near-linear writes, coalesced LDG
    for (int idx = tid; idx < MIDD * 256; idx += NLT) {
        int m = idx >> 8, k = idx & 255;
        int o = k >> 4, i = k & 15;
        sW3[m * W3S + o * 18 + i] = W3[idx];
    }
    for (int idx = tid; idx < CC * MIDD; idx += NLT) sW1[idx] = W1n[idx];
    if (Wq && tid < HH * CC) sWq[(tid >> 4) * 18 + (tid & 15)] = Wq[tid];
    { int o = tid >> 4, i = tid & 15; sb3[o * 18 + i] = b3[tid]; }
    if (tid < MIDD) sb1[tid] = b1n[tid];
    if (Wself && tid < CC * CC) sWself[(tid >> 4) * 18 + (tid & 15)] = Wself[tid];
}

__device__ __forceinline__ void node_prep(
    int n, int nloc, int j, bool do_q, bool do_feats,
    const float* sW3, const float* sW1, const float* sWq,
    const float* sb3, const float* sb1, const float* sWself,
    const float* sXn, const float* sSn) {
    // x pairs for i-paired fma2
    ull xx[8];
#pragma unroll
    for (int ip = 0; ip < 8; ip++)
        xx[ip] = *(const ull*)&sXn[nloc * CC + 2 * ip];

    if (do_q) {
        float qa = 0.f;
#pragma unroll
        for (int c = 0; c < CC; c++) qa = fmaf(sWq[j * 18 + c], sXn[nloc * CC + c], qa);
        g_q[n * HH + j] = qa;
    }
    {
        float u0 = sb1[j], u1 = sb1[j + 8], u2 = sb1[j + 16], u3 = sb1[j + 24];
#pragma unroll
        for (int c = 0; c < CC; c++) {
            float sv = sSn[nloc * CC + c];
            u0 = fmaf(sv, sW1[c * MIDD + j], u0);
            u1 = fmaf(sv, sW1[c * MIDD + j + 8], u1);
            u2 = fmaf(sv, sW1[c * MIDD + j + 16], u2);
            u3 = fmaf(sv, sW1[c * MIDD + j + 24], u3);
        }
        g_u[n * MIDD + j] = u0;
        g_u[n * MIDD + j + 8] = u1;
        g_u[n * MIDD + j + 16] = u2;
        g_u[n * MIDD + j + 24] = u3;
    }
    {
        ull a0 = 0ULL, a1 = 0ULL;
#pragma unroll
        for (int ip = 0; ip < 8; ip++) {
            a0 = fma2(xx[ip], *(const ull*)&sb3[j * 18 + 2 * ip], a0);
            a1 = fma2(xx[ip], *(const ull*)&sb3[(j + 8) * 18 + 2 * ip], a1);
        }
        float l0, h0, l1, h1;
        unpack2(a0, l0, h0);
        unpack2(a1, l1, h1);
        g_PB[n * CC + j * 2] = l0 + h0;
        g_PB[n * CC + j * 2 + 1] = l1 + h1;
    }
    if (do_feats) {
        ull a0 = 0ULL, a1 = 0ULL;
#pragma unroll
        for (int ip = 0; ip < 8; ip++) {
            a0 = fma2(xx[ip], *(const ull*)&sWself[j * 18 + 2 * ip], a0);
            a1 = fma2(xx[ip], *(const ull*)&sWself[(j + 8) * 18 + 2 * ip], a1);
        }
        float l0, h0, l1, h1;
        unpack2(a0, l0, h0);
        unpack2(a1, l1, h1);
        g_feats[n * CC + j] = l0 + h0;
        g_feats[n * CC + 8 + j] = l1 + h1;
    }
    {
        ull outp[8][4];
#pragma unroll
        for (int mq = 0; mq < 8; mq++) {
#pragma unroll
            for (int r = 0; r < 4; r++) {
                int m = mq * 4 + r;
                const float* wa = &sW3[m * W3S + j * 18];
                const float* wb = &sW3[m * W3S + (j + 8) * 18];
                ull aA = 0ULL, aB = 0ULL;
#pragma unroll
                for (int ip = 0; ip < 8; ip++) {
                    aA = fma2(xx[ip], *(const ull*)&wa[2 * ip], aA);
                    aB = fma2(xx[ip], *(const ull*)&wb[2 * ip], aB);
                }
                float la, ha, lb, hb;
                unpack2(aA, la, ha);
                unpack2(aB, lb, hb);
                outp[mq][r] = pack2(la + ha, lb + hb);
            }
        }
        float* Pn = g_P + (size_t)n * 512;
#pragma unroll
        for (int mq = 0; mq < 8; mq++) {
            *(ulonglong2*)(Pn + mq * 64 + j * 8)     = make_ulonglong2(outp[mq][0], outp[mq][1]);
            *(ulonglong2*)(Pn + mq * 64 + j * 8 + 4) = make_ulonglong2(outp[mq][2], outp[mq][3]);
        }
    }
}

// ---------------- initial node prep (layer 0) ----------------
__global__ void __launch_bounds__(NLT)
k_nodeprep0(const float* __restrict__ Wq, const float* __restrict__ W3,
            const float* __restrict__ b3, const float* __restrict__ W1n,
            const float* __restrict__ b1n) {
    __shared__ __align__(16) float sW3[MIDD * W3S];
    __shared__ __align__(16) float sW1[CC * MIDD];
    __shared__ __align__(16) float sWq[HH * 18];
    __shared__ __align__(16) float sb3[16 * 18];
    __shared__ __align__(16) float sb1[MIDD];
    __shared__ __align__(16) float sXn[NLN * CC];
    __shared__ __align__(16) float sSn[NLN * CC];
    int tid = threadIdx.x;
    load_node_weights(tid, W3, b3, W1n, b1n, Wq, nullptr,
                      sW3, sW1, sWq, sb3, sb1, nullptr);
    int nloc = tid >> 3, j = tid & 7;
    int n = blockIdx.x * NLN + nloc;
    sXn[nloc * CC + j] = g_x[n * CC + j];
    sXn[nloc * CC + 8 + j] = g_x[n * CC + 8 + j];
    sSn[nloc * CC + j] = 0.f;
    sSn[nloc * CC + 8 + j] = 0.f;
    __syncthreads();
    node_prep(n, nloc, j, true, false, sW3, sW1, sWq, sb3, sb1, nullptr, sXn, sSn);
}

// ---------------- node layer: one-pass online-softmax attention + Wproj + prep ----------------
__global__ void __launch_bounds__(NLT)
k_node_layer(int mode,
             const float* __restrict__ Wproj,
             const float* __restrict__ Wq,
             const float* __restrict__ W3,
             const float* __restrict__ b3,
             const float* __restrict__ W1n,
             const float* __restrict__ b1n,
             const float* __restrict__ Wself) {
    __shared__ __align__(16) float sW3[MIDD * W3S];
    __shared__ __align__(16) float sW1[CC * MIDD];
    __shared__ __align__(16) float sWq[HH * 18];
    __shared__ __align__(16) float sWproj[CC * 25];
    __shared__ __align__(16) float sb3[16 * 18];
    __shared__ __align__(16) float sb1[MIDD];
    __shared__ __align__(16) float sWself[16 * 18];
    __shared__ __align__(16) float sAgg[NLN * HH];
    __shared__ __align__(16) float sXold[NLN * CC];
    __shared__ __align__(16) float sXn[NLN * CC];
    __shared__ __align__(16) float sSn[NLN * CC];

    int tid = threadIdx.x;
    int nloc = tid >> 3, j = tid & 7;
    int n = blockIdx.x * NLN + nloc;

    load_node_weights(tid, W3, b3, W1n, b1n,
                      mode != 2 ? Wq : nullptr,
                      mode == 2 ? Wself : nullptr,
                      sW3, sW1, sWq, sb3, sb1, sWself);
    for (int idx = tid; idx < CC * 24; idx += NLT)
        sWproj[(idx / 24) * 25 + (idx % 24)] = Wproj[idx];

    {
        int beg = g_rdst[n], end = g_rdst[n + 1];
        float qj = g_q[n * HH + j];
        float m = -INFINITY, num = 0.f, den = 0.f;
#pragma unroll 2
        for (int i = beg; i < end; i++) {
            int2 es = g_es[i];
            float2 vk = *(const float2*)(g_vk + (size_t)es.x * CC + j * 2);
            float sc = __int_as_float(es.y);
            float l = vk.y * qj;
            float mn = fmaxf(m, l);
            float corr = __expf(m - mn);
            float p = sc * __expf(l - mn);
            den = den * corr + p;
            num = fmaf(num, corr, p * vk.x);
            m = mn;
        }
        sAgg[nloc * HH + j] = num / fmaxf(den, 1e-20f);
        sXold[nloc * CC + j] = g_x[n * CC + j];
        sXold[nloc * CC + 8 + j] = g_x[n * CC + 8 + j];
        __syncthreads();
        float xn0 = 0.f, xn1 = 0.f;
#pragma unroll
        for (int k = 0; k < 8; k++) {
            float a = sAgg[nloc * HH + k];
            xn0 = fmaf(sWproj[j * 25 + k], a, xn0);
            xn1 = fmaf(sWproj[(j + 8) * 25 + k], a, xn1);
        }
#pragma unroll
        for (int k = 0; k < CC; k++) {
            float xo = sXold[nloc * CC + k];
            xn0 = fmaf(sWproj[j * 25 + 8 + k], xo, xn0);
            xn1 = fmaf(sWproj[(j + 8) * 25 + 8 + k], xo, xn1);
        }
        float s0 = g_S[n * CC + j] + xn0;
        float s1 = g_S[n * CC + 8 + j] + xn1;
        g_x[n * CC + j] = xn0;     g_x[n * CC + 8 + j] = xn1;
        g_S[n * CC + j] = s0;      g_S[n * CC + 8 + j] = s1;
        sXn[nloc * CC + j] = xn0;  sXn[nloc * CC + 8 + j] = xn1;
        sSn[nloc * CC + j] = s0;   sSn[nloc * CC + 8 + j] = s1;
        __syncthreads();
    }

    node_prep(n, nloc, j, mode != 2, mode == 2,
              sW3, sW1, sWq, sb3, sb1, sWself, sXn, sSn);
}

// ---------------- edge kernel (R8 best, unchanged) ----------------
__global__ void __launch_bounds__(128, 4)
k_edge(const float* __restrict__ W1, const float* __restrict__ W2,
       const float* __restrict__ b2) {
    __shared__ __align__(16) ull sW2p[512];
    __shared__ float sw15[MIDD];
    __shared__ __align__(16) ull sB2p[16];
    __shared__ __align__(16) float sSt[4][32 * 36];
    int tid = threadIdx.x;
    for (int i = tid; i < 512; i += 128) sW2p[i] = ((const ull*)W2)[i];
    if (tid < MIDD) sw15[tid] = W1[15 * MIDD + tid];
    if (tid < 16) sB2p[tid] = ((const ull*)b2)[tid];
    __syncthreads();

    int t = blockIdx.x * 128 + tid;
    int e0 = 2 * t;
    int s = g_srcS[e0];
    float2 dd = *(const float2*)(g_distS + e0);
    float2 sc = *(const float2*)(g_scaleS + e0);
    float da = dd.x, db = dd.y;
    float bsa = Y0F * sc.x, bsb = Y0F * sc.y;

    float u[MIDD];
    {
        const float4* up = (const float4*)(g_u + (size_t)s * MIDD);
#pragma unroll
        for (int k = 0; k < 8; k++) {
            float4 v = up[k];
            u[4 * k] = v.x; u[4 * k + 1] = v.y; u[4 * k + 2] = v.z; u[4 * k + 3] = v.w;
        }
    }

    ull acca[16], accb[16];
#pragma unroll
    for (int jp = 0; jp < 16; jp++) { acca[jp] = sB2p[jp]; accb[jp] = sB2p[jp]; }
#pragma unroll
    for (int i2 = 0; i2 < MIDD; i2++) {
        float w15v = sw15[i2];
        float ha = fmaxf(fmaf(da, w15v, u[i2]), 0.f);
        float hb = fmaxf(fmaf(db, w15v, u[i2]), 0.f);
        ull xa = pack2(ha, ha);
        ull xb = pack2(hb, hb);
#pragma unroll
        for (int jq = 0; jq < 8; jq++) {
            ulonglong2 w = *(const ulonglong2*)&sW2p[i2 * 16 + jq * 2];
            acca[2 * jq]     = fma2(xa, w.x, acca[2 * jq]);
            acca[2 * jq + 1] = fma2(xa, w.y, acca[2 * jq + 1]);
            accb[2 * jq]     = fma2(xb, w.x, accb[2 * jq]);
            accb[2 * jq + 1] = fma2(xb, w.y, accb[2 * jq + 1]);
        }
    }
    float h2a[MIDD], h2b[MIDD];
#pragma unroll
    for (int jp = 0; jp < 16; jp++) {
        float lo, hi;
        unpack2(acca[jp], lo, hi);
        h2a[2 * jp] = fmaxf(lo, 0.f); h2a[2 * jp + 1] = fmaxf(hi, 0.f);
        unpack2(accb[jp], lo, hi);
        h2b[2 * jp] = fmaxf(lo, 0.f); h2b[2 * jp + 1] = fmaxf(hi, 0.f);
    }

    ull ka[8], kb[8];
    {
        const ulonglong2* pbp = (const ulonglong2*)(g_PB + (size_t)s * CC);
#pragma unroll
        for (int q = 0; q < 4; q++) {
            ulonglong2 pb = pbp[q];
            ka[2 * q] = pb.x; ka[2 * q + 1] = pb.y;
            kb[2 * q] = pb.x; kb[2 * q + 1] = pb.y;
        }
    }
    const ull* Pp = (const ull*)(g_P + (size_t)s * 512);
#pragma unroll
    for (int mq = 0; mq < 8; mq++) {
        ull xa0 = pack2(h2a[mq * 4 + 0], h2a[mq * 4 + 0]);
        ull xa1 = pack2(h2a[mq * 4 + 1], h2a[mq * 4 + 1]);
        ull xa2 = pack2(h2a[mq * 4 + 2], h2a[mq * 4 + 2]);
        ull xa3 = pack2(h2a[mq * 4 + 3], h2a[mq * 4 + 3]);
        ull xb0 = pack2(h2b[mq * 4 + 0], h2b[mq * 4 + 0]);
        ull xb1 = pack2(h2b[mq * 4 + 1], h2b[mq * 4 + 1]);
        ull xb2 = pack2(h2b[mq * 4 + 2], h2b[mq * 4 + 2]);
        ull xb3 = pack2(h2b[mq * 4 + 3], h2b[mq * 4 + 3]);
#pragma unroll
        for (int j = 0; j < 8; j++) {
            ulonglong2 pA = *(const ulonglong2*)(Pp + mq * 32 + j * 4);
            ulonglong2 pB = *(const ulonglong2*)(Pp + mq * 32 + j * 4 + 2);
            ka[j] = fma2(xa0, pA.x, ka[j]);
            ka[j] = fma2(xa1, pA.y, ka[j]);
            ka[j] = fma2(xa2, pB.x, ka[j]);
            ka[j] = fma2(xa3, pB.y, ka[j]);
            kb[j] = fma2(xb0, pA.x, kb[j]);
            kb[j] = fma2(xb1, pA.y, kb[j]);
            kb[j] = fma2(xb2, pB.x, kb[j]);
            kb[j] = fma2(xb3, pB.y, kb[j]);
        }
    }

    int lane = tid & 31, w = tid >> 5;
    float* st = sSt[w];
#pragma unroll
    for (int q = 0; q < 4; q++) {
        float a0, a1, a2, a3;
        unpack2(ka[2 * q], a0, a1);
        unpack2(ka[2 * q + 1], a2, a3);
        *(float4*)&st[lane * 36 + q * 4] = make_float4(a0 * bsa, a1 * bsa, a2 * bsa, a3 * bsa);
    }
#pragma unroll
    for (int q = 0; q < 4; q++) {
        float a0, a1, a2, a3;
        unpack2(kb[2 * q], a0, a1);
        unpack2(kb[2 * q + 1], a2, a3);
        *(float4*)&st[lane * 36 + 16 + q * 4] = make_float4(a0 * bsb, a1 * bsb, a2 * bsb, a3 * bsb);
    }
    __syncwarp();
    float4* gbase = (float4*)(g_vk + (size_t)(blockIdx.x * 256 + w * 64) * CC);
#pragma unroll
    for (int g = 0; g < 8; g++) {
        int f = g * 32 + lane;
        int owner = f >> 3, q = f & 7;
        gbase[f] = *(const float4*)&st[owner * 36 + q * 4];
    }
}

// ---------------- final ----------------
__device__ __forceinline__ float siluf(float x) { return x / (1.f + __expf(-x)); }

__global__ void k_final(const int* __restrict__ species, const float* __restrict__ emb,
                        const float* __restrict__ W1, const float* __restrict__ b1,
                        const float* __restrict__ W2, const float* __restrict__ b2,
                        const float* __restrict__ W3, const float* __restrict__ b3,
                        float* __restrict__ out) {
    __shared__ float sFeat[16 * 17];
    __shared__ float sEmb[16 * 17];
    __shared__ float sH[16 * 17];
    __shared__ float sRed[16];
    int tid = threadIdx.x;
    int nloc = tid >> 4, o = tid & 15;
    int n = blockIdx.x * 16 + nloc;
    int beg = g_rdst[n], end = g_rdst[n + 1];
    int o2 = (o < 8) ? o * 2 : (o - 8) * 2 + 1;
    float f = g_feats[n * CC + o];
    for (int i = beg; i < end; i++) {
        int ei = g_es[i].x;
        f += g_vk[(size_t)ei * CC + o2];
    }
    sFeat[nloc * 17 + o] = f;
    int sp = species[n] - 1;
    sEmb[nloc * 17 + o] = emb[sp * CC + o];
    __syncthreads();

    float h1 = b1[o];
#pragma unroll
    for (int k = 0; k < CC; k++) h1 = fmaf(sEmb[nloc * 17 + k], W1[k * CC + o], h1);
#pragma unroll
    for (int k = 0; k < CC; k++) h1 = fmaf(sFeat[nloc * 17 + k], W1[(CC + k) * CC + o], h1);
    sH[nloc * 17 + o] = siluf(h1);
    __syncthreads();

    float h2 = b2[o];
#pragma unroll
    for (int k = 0; k < CC; k++) h2 = fmaf(sH[nloc * 17 + k], W2[k * CC + o], h2);
    h2 = siluf(h2);

    float part = h2 * W3[o];
#pragma unroll
    for (int off = 8; off > 0; off >>= 1)
        part += __shfl_down_sync(0xffffffffu, part, off, 16);
    if (o == 0) sRed[nloc] = part + b3[0] + g_coulN[n];
    __syncthreads();
    if (tid == 0) {
        float acc = 0.f;
#pragma unroll
        for (int k = 0; k < 16; k++) acc += sRed[k];
        atomicAdd(out, acc);
    }
}

// ---------------- host launch ----------------
extern "C" void kernel_launch(void* const* d_in, const int* in_sizes, int n_in,
                              void* d_out, int out_size) {
    const int* species  = (const int*)d_in[0];
    const int* src      = (const int*)d_in[1];
    const int* dst      = (const int*)d_in[2];
    const float* rel_pos = (const float*)d_in[3];
    const float* emb    = (const float*)d_in[4];
    const float* kv_W1  = (const float*)d_in[5];
    const float* kv_b1  = (const float*)d_in[6];
    const float* kv_W2  = (const float*)d_in[7];
    const float* kv_b2  = (const float*)d_in[8];
    const float* kv_W3  = (const float*)d_in[9];
    const float* kv_b3  = (const float*)d_in[10];
    const float* Wq     = (const float*)d_in[11];
    const float* Wproj  = (const float*)d_in[12];
    const float* fin_W1 = (const float*)d_in[13];
    const float* fin_b1 = (const float*)d_in[14];
    const float* fin_W2 = (const float*)d_in[15];
    const float* fin_b2 = (const float*)d_in[16];
    const float* fin_W3 = (const float*)d_in[17];
    const float* fin_b3 = (const float*)d_in[18];
    const float* Wself  = (const float*)d_in[19];
    const float* mlp_W1 = (const float*)d_in[20];
    const float* mlp_b1 = (const float*)d_in[21];
    const float* mlp_W2 = (const float*)d_in[22];
    const float* mlp_b2 = (const float*)d_in[23];
    const float* mlp_W3 = (const float*)d_in[24];
    const float* mlp_b3 = (const float*)d_in[25];
    float* out = (float*)d_out;

    const int EB = EE / 256;         // 2048
    const int LB = NN / NLN;         // 1024
    const int EDGB = EENP / 256;     // 2176

    k_init<<<EB, 256>>>(species, emb, out, src, dst);
    k_scan<<<2, 1024>>>();
    k_scatter<<<EB, 256>>>(src, dst, rel_pos, species);
    k_nodeprep0<<<LB, NLT>>>(Wq, kv_W3, kv_b3, kv_W1, kv_b1);

    for (int l = 0; l < 4; l++) {
        k_edge<<<EDGB, 128>>>(kv_W1 + (size_t)l * CC * MIDD,
                              kv_W2 + (size_t)l * MIDD * MIDD,
                              kv_b2 + (size_t)l * MIDD);
        if (l < 3) {
            k_node_layer<<<LB, NLT>>>(1,
                Wproj + (size_t)l * CC * 24,
                Wq + (size_t)(l + 1) * HH * CC,
                kv_W3 + (size_t)(l + 1) * MIDD * 256,
                kv_b3 + (size_t)(l + 1) * 256,
                kv_W1 + (size_t)(l + 1) * CC * MIDD,
                kv_b1 + (size_t)(l + 1) * MIDD,
                nullptr);
        } else {
            k_node_layer<<<LB, NLT>>>(2,
                Wproj + (size_t)l * CC * 24,
                nullptr,
                fin_W3, fin_b3, fin_W1, fin_b1, Wself);
        }
    }
    k_edge<<<EDGB, 128>>>(fin_W1, fin_W2, fin_b2);
    k_final<<<NN / 16, 256>>>(species, emb, mlp_W1, mlp_b1, mlp_W2, mlp_b2,
                              mlp_W3, mlp_b3, out);
}

// round 12
// speedup vs baseline: 1.1421x; 1.0255x over previous
#include <cuda_runtime.h>
#include <math.h>

#define NN 32768
#define EE 524288
#define EENP (EE + NN)          // padded src-sorted capacity (557056 = 256*2176)
#define CC 16
#define MIDD 32
#define HH 8
#define Y0F 0.28209479177387814f
#define CUTOFFF 4.6f
#define KCOULF 0.529f

typedef unsigned long long ull;

// ---------------- device scratch ----------------
__device__ __align__(16) float g_x[NN * CC];
__device__ __align__(16) float g_S[NN * CC];
__device__ __align__(16) float g_q[NN * HH];
__device__ __align__(16) float g_u[NN * MIDD];
__device__ __align__(16) float g_P[NN * 512];     // pair-interleaved
__device__ __align__(16) float g_PB[NN * CC];     // pair-interleaved
__device__ __align__(16) float g_feats[NN * CC];
__device__ __align__(16) float g_vk[(size_t)EENP * CC]; // padded src-sorted {val,key}
__device__ float g_distS[EENP];
__device__ float g_scaleS[EENP];
__device__ __align__(8) int2 g_es[EE];            // dst-order: {src-order idx, scale bits}
__device__ float g_coulN[NN];
__device__ int g_srcS[EENP];
__device__ int g_csrc[NN], g_cdst[NN];
__device__ int g_rdst[NN + 1];
__device__ int g_cursrc[NN], g_curdst[NN];

// ---------------- f32x2 helpers ----------------
__device__ __forceinline__ ull pack2(float a, float b) {
    ull r;
    asm("mov.b64 %0, {%1, %2};" : "=l"(r) : "f"(a), "f"(b));
    return r;
}
__device__ __forceinline__ ull fma2(ull a, ull b, ull c) {
    ull d;
    asm("fma.rn.f32x2 %0, %1, %2, %3;" : "=l"(d) : "l"(a), "l"(b), "l"(c));
    return d;
}
__device__ __forceinline__ void unpack2(ull v, float& lo, float& hi) {
    asm("mov.b64 {%0, %1}, %2;" : "=f"(lo), "=f"(hi) : "l"(v));
}

// ---------------- init ----------------
__global__ void k_init(const int* __restrict__ species, const float* __restrict__ emb,
                       float* __restrict__ out,
                       const int* __restrict__ src, const int* __restrict__ dst) {
    int e = blockIdx.x * 256 + threadIdx.x;
    if (e < NN) {
        int sp = species[e] - 1;
#pragma unroll
        for (int c = 0; c < CC; c++) {
            g_x[e * CC + c] = emb[sp * CC + c];
            g_S[e * CC + c] = 0.f;
        }
        g_coulN[e] = 0.f;
        if (e == 0) out[0] = 0.f;
    }
    atomicAdd(&g_csrc[src[e]], 1);
    atomicAdd(&g_cdst[dst[e]], 1);
}

// ---------------- scan ----------------
__global__ void k_scan() {
    const int T = 1024, PER = NN / 1024;
    __shared__ int part[T];
    int t = threadIdx.x;
    int base = t * PER;
    if (blockIdx.x == 0) {
        int loc[PER], locp[PER];
        int s = 0;
#pragma unroll
        for (int i = 0; i < PER; i++) {
            loc[i] = g_csrc[base + i];
            g_csrc[base + i] = 0;
            locp[i] = (loc[i] + 1) & ~1;
            s += locp[i];
        }
        part[t] = s;
        __syncthreads();
        for (int off = 1; off < T; off <<= 1) {
            int v = (t >= off) ? part[t - off] : 0;
            __syncthreads();
            part[t] += v;
            __syncthreads();
        }
        int run = part[t] - s;
#pragma unroll
        for (int i = 0; i < PER; i++) {
            g_cursrc[base + i] = run;
            if (loc[i] & 1) g_srcS[run + loc[i]] = base + i;
            run += locp[i];
        }
    } else {
        int loc[PER];
        int s = 0;
#pragma unroll
        for (int i = 0; i < PER; i++) {
            loc[i] = g_cdst[base + i];
            g_cdst[base + i] = 0;
            s += loc[i];
        }
        part[t] = s;
        __syncthreads();
        for (int off = 1; off < T; off <<= 1) {
            int v = (t >= off) ? part[t - off] : 0;
            __syncthreads();
            part[t] += v;
            __syncthreads();
        }
        int run = part[t] - s;
#pragma unroll
        for (int i = 0; i < PER; i++) {
            g_rdst[base + i] = run;
            g_curdst[base + i] = run;
            run += loc[i];
        }
        if (t == T - 1) g_rdst[NN] = run;
    }
}

// ---------------- scatter ----------------
__global__ void __launch_bounds__(256)
k_scatter(const int* __restrict__ src, const int* __restrict__ dst,
          const float* __restrict__ rel_pos, const int* __restrict__ species) {
    int e = blockIdx.x * 256 + threadIdx.x;
    int s = src[e], d = dst[e];
    float px = rel_pos[e * 3 + 0], py = rel_pos[e * 3 + 1], pz = rel_pos[e * 3 + 2];
    float dist = sqrtf(px * px + py * py + pz * pz);
    float xc = dist / CUTOFFF;
    bool in_cut = dist < CUTOFFF;
    float x2 = in_cut ? fminf(xc * xc, 1.f - 1e-6f) : 0.f;
    float scale = in_cut ? expf(3.f - 3.f / (1.f - x2)) : 0.f;

    int ps = atomicAdd(&g_cursrc[s], 1);
    int pd = atomicAdd(&g_curdst[d], 1);
    g_srcS[ps] = s;
    g_distS[ps] = dist;
    g_scaleS[ps] = scale;
    g_es[pd] = make_int2(ps, __float_as_int(scale));

    float Zu = (float)species[s];
    float Zv = (float)species[d];
    float raw = KCOULF * Zu * Zv / (2.f * dist);
    float au = 0.8854f * 0.529f / (__powf(Zu, 0.23f) + __powf(Zv, 0.23f));
    float xx = dist / au;
    float screen = 0.1818f * __expf(-3.2f * xx) + 0.5099f * __expf(-0.9423f * xx)
                 + 0.2802f * __expf(-0.4028f * xx) + 0.02817f * __expf(-0.2016f * xx);
    float contrib = raw * screen * scale;
    if (contrib != 0.f) atomicAdd(&g_coulN[d], contrib);
}

// ---------------- node-prep helpers ----------------
#define NLT 256                 // node-layer threads
#define NLN 32                  // nodes per tile
#define NTILES (NN / NLN)       // 1024
#define NGRID 296               // 2 blocks/SM x 148
#define W3S 288                 // per-m stride: 16 o-slots of 18

__device__ __forceinline__ void load_node_weights(
    int tid, const float* __restrict__ W3, const float* __restrict__ b3,
    const float* __restrict__ W1n, const float* __restrict__ b1n,
    const float* __restrict__ Wq, const float* __restrict__ Wself,
    float* sW3, float* sW1, float* sWq, float* sb3, float* sb1, float* sWself) {
    for (int idx = tid; idx < MIDD * 256; idx += NLT) {
        int m = idx >> 8, k = idx & 255;
        int o = k >> 4, i = k & 15;
        sW3[m * W3S + o * 18 + i] = W3[idx];
    }
    for (int idx = tid; idx < CC * MIDD; idx += NLT) sW1[idx] = W1n[idx];
    if (Wq && tid < HH * CC) sWq[(tid >> 4) * 18 + (tid & 15)] = Wq[tid];
    { int o = tid >> 4, i = tid & 15; sb3[o * 18 + i] = b3[tid]; }
    if (tid < MIDD) sb1[tid] = b1n[tid];
    if (Wself && tid < CC * CC) sWself[(tid >> 4) * 18 + (tid & 15)] = Wself[tid];
}

__device__ __forceinline__ void node_prep(
    int n, int nloc, int j, bool do_q, bool do_feats,
    const float* sW3, const float* sW1, const float* sWq,
    const float* sb3, const float* sb1, const float* sWself,
    const float* sXn, const float* sSn) {
    ull xx[8];
#pragma unroll
    for (int ip = 0; ip < 8; ip++)
        xx[ip] = *(const ull*)&sXn[nloc * CC + 2 * ip];

    if (do_q) {
        float qa = 0.f;
#pragma unroll
        for (int c = 0; c < CC; c++) qa = fmaf(sWq[j * 18 + c], sXn[nloc * CC + c], qa);
        g_q[n * HH + j] = qa;
    }
    {
        float u0 = sb1[j], u1 = sb1[j + 8], u2 = sb1[j + 16], u3 = sb1[j + 24];
#pragma unroll
        for (int c = 0; c < CC; c++) {
            float sv = sSn[nloc * CC + c];
            u0 = fmaf(sv, sW1[c * MIDD + j], u0);
            u1 = fmaf(sv, sW1[c * MIDD + j + 8], u1);
            u2 = fmaf(sv, sW1[c * MIDD + j + 16], u2);
            u3 = fmaf(sv, sW1[c * MIDD + j + 24], u3);
        }
        g_u[n * MIDD + j] = u0;
        g_u[n * MIDD + j + 8] = u1;
        g_u[n * MIDD + j + 16] = u2;
        g_u[n * MIDD + j + 24] = u3;
    }
    {
        ull a0 = 0ULL, a1 = 0ULL;
#pragma unroll
        for (int ip = 0; ip < 8; ip++) {
            a0 = fma2(xx[ip], *(const ull*)&sb3[j * 18 + 2 * ip], a0);
            a1 = fma2(xx[ip], *(const ull*)&sb3[(j + 8) * 18 + 2 * ip], a1);
        }
        float l0, h0, l1, h1;
        unpack2(a0, l0, h0);
        unpack2(a1, l1, h1);
        g_PB[n * CC + j * 2] = l0 + h0;
        g_PB[n * CC + j * 2 + 1] = l1 + h1;
    }
    if (do_feats) {
        ull a0 = 0ULL, a1 = 0ULL;
#pragma unroll
        for (int ip = 0; ip < 8; ip++) {
            a0 = fma2(xx[ip], *(const ull*)&sWself[j * 18 + 2 * ip], a0);
            a1 = fma2(xx[ip], *(const ull*)&sWself[(j + 8) * 18 + 2 * ip], a1);
        }
        float l0, h0, l1, h1;
        unpack2(a0, l0, h0);
        unpack2(a1, l1, h1);
        g_feats[n * CC + j] = l0 + h0;
        g_feats[n * CC + 8 + j] = l1 + h1;
    }
    {
        ull outp[8][4];
#pragma unroll
        for (int mq = 0; mq < 8; mq++) {
#pragma unroll
            for (int r = 0; r < 4; r++) {
                int m = mq * 4 + r;
                const float* wa = &sW3[m * W3S + j * 18];
                const float* wb = &sW3[m * W3S + (j + 8) * 18];
                ull aA = 0ULL, aB = 0ULL;
#pragma unroll
                for (int ip = 0; ip < 8; ip++) {
                    aA = fma2(xx[ip], *(const ull*)&wa[2 * ip], aA);
                    aB = fma2(xx[ip], *(const ull*)&wb[2 * ip], aB);
                }
                float la, ha, lb, hb;
                unpack2(aA, la, ha);
                unpack2(aB, lb, hb);
                outp[mq][r] = pack2(la + ha, lb + hb);
            }
        }
        float* Pn = g_P + (size_t)n * 512;
#pragma unroll
        for (int mq = 0; mq < 8; mq++) {
            *(ulonglong2*)(Pn + mq * 64 + j * 8)     = make_ulonglong2(outp[mq][0], outp[mq][1]);
            *(ulonglong2*)(Pn + mq * 64 + j * 8 + 4) = make_ulonglong2(outp[mq][2], outp[mq][3]);
        }
    }
}

// ---------------- initial node prep (layer 0): persistent tiles ----------------
__global__ void __launch_bounds__(NLT)
k_nodeprep0(const float* __restrict__ Wq, const float* __restrict__ W3,
            const float* __restrict__ b3, const float* __restrict__ W1n,
            const float* __restrict__ b1n) {
    __shared__ __align__(16) float sW3[MIDD * W3S];
    __shared__ __align__(16) float sW1[CC * MIDD];
    __shared__ __align__(16) float sWq[HH * 18];
    __shared__ __align__(16) float sb3[16 * 18];
    __shared__ __align__(16) float sb1[MIDD];
    __shared__ __align__(16) float sXn[NLN * CC];
    __shared__ __align__(16) float sSn[NLN * CC];
    int tid = threadIdx.x;
    load_node_weights(tid, W3, b3, W1n, b1n, Wq, nullptr,
                      sW3, sW1, sWq, sb3, sb1, nullptr);
    int nloc = tid >> 3, j = tid & 7;
    for (int tile = blockIdx.x; tile < NTILES; tile += NGRID) {
        __syncthreads();   // protect sXn/sSn reuse + ensure weights visible (1st iter)
        int n = tile * NLN + nloc;
        sXn[nloc * CC + j] = g_x[n * CC + j];
        sXn[nloc * CC + 8 + j] = g_x[n * CC + 8 + j];
        sSn[nloc * CC + j] = 0.f;
        sSn[nloc * CC + 8 + j] = 0.f;
        __syncthreads();
        node_prep(n, nloc, j, true, false, sW3, sW1, sWq, sb3, sb1, nullptr, sXn, sSn);
    }
}

// ---------------- node layer: persistent tiles, online-softmax + Wproj + prep ----------------
__global__ void __launch_bounds__(NLT)
k_node_layer(int mode,
             const float* __restrict__ Wproj,
             const float* __restrict__ Wq,
             const float* __restrict__ W3,
             const float* __restrict__ b3,
             const float* __restrict__ W1n,
             const float* __restrict__ b1n,
             const float* __restrict__ Wself) {
    __shared__ __align__(16) float sW3[MIDD * W3S];
    __shared__ __align__(16) float sW1[CC * MIDD];
    __shared__ __align__(16) float sWq[HH * 18];
    __shared__ __align__(16) float sWproj[CC * 25];
    __shared__ __align__(16) float sb3[16 * 18];
    __shared__ __align__(16) float sb1[MIDD];
    __shared__ __align__(16) float sWself[16 * 18];
    __shared__ __align__(16) float sAgg[NLN * HH];
    __shared__ __align__(16) float sXold[NLN * CC];
    __shared__ __align__(16) float sXn[NLN * CC];
    __shared__ __align__(16) float sSn[NLN * CC];

    int tid = threadIdx.x;
    int nloc = tid >> 3, j = tid & 7;

    load_node_weights(tid, W3, b3, W1n, b1n,
                      mode != 2 ? Wq : nullptr,
                      mode == 2 ? Wself : nullptr,
                      sW3, sW1, sWq, sb3, sb1, sWself);
    for (int idx = tid; idx < CC * 24; idx += NLT)
        sWproj[(idx / 24) * 25 + (idx % 24)] = Wproj[idx];

    for (int tile = blockIdx.x; tile < NTILES; tile += NGRID) {
        __syncthreads();   // protect smem reuse across tiles (and weights on 1st iter)
        int n = tile * NLN + nloc;
        {
            int beg = g_rdst[n], end = g_rdst[n + 1];
            float qj = g_q[n * HH + j];
            float m = -INFINITY, num = 0.f, den = 0.f;
#pragma unroll 2
            for (int i = beg; i < end; i++) {
                int2 es = g_es[i];
                float2 vk = *(const float2*)(g_vk + (size_t)es.x * CC + j * 2);
                float sc = __int_as_float(es.y);
                float l = vk.y * qj;
                float mn = fmaxf(m, l);
                float corr = __expf(m - mn);
                float p = sc * __expf(l - mn);
                den = den * corr + p;
                num = fmaf(num, corr, p * vk.x);
                m = mn;
            }
            sAgg[nloc * HH + j] = num / fmaxf(den, 1e-20f);
            sXold[nloc * CC + j] = g_x[n * CC + j];
            sXold[nloc * CC + 8 + j] = g_x[n * CC + 8 + j];
            __syncthreads();
            float xn0 = 0.f, xn1 = 0.f;
#pragma unroll
            for (int k = 0; k < 8; k++) {
                float a = sAgg[nloc * HH + k];
                xn0 = fmaf(sWproj[j * 25 + k], a, xn0);
                xn1 = fmaf(sWproj[(j + 8) * 25 + k], a, xn1);
            }
#pragma unroll
            for (int k = 0; k < CC; k++) {
                float xo = sXold[nloc * CC + k];
                xn0 = fmaf(sWproj[j * 25 + 8 + k], xo, xn0);
                xn1 = fmaf(sWproj[(j + 8) * 25 + 8 + k], xo, xn1);
            }
            float s0 = g_S[n * CC + j] + xn0;
            float s1 = g_S[n * CC + 8 + j] + xn1;
            g_x[n * CC + j] = xn0;     g_x[n * CC + 8 + j] = xn1;
            g_S[n * CC + j] = s0;      g_S[n * CC + 8 + j] = s1;
            sXn[nloc * CC + j] = xn0;  sXn[nloc * CC + 8 + j] = xn1;
            sSn[nloc * CC + j] = s0;   sSn[nloc * CC + 8 + j] = s1;
            __syncthreads();
        }
        node_prep(n, nloc, j, mode != 2, mode == 2,
                  sW3, sW1, sWq, sb3, sb1, sWself, sXn, sSn);
    }
}

// ---------------- edge kernel (R8 best, unchanged) ----------------
__global__ void __launch_bounds__(128, 4)
k_edge(const float* __restrict__ W1, const float* __restrict__ W2,
       const float* __restrict__ b2) {
    __shared__ __align__(16) ull sW2p[512];
    __shared__ float sw15[MIDD];
    __shared__ __align__(16) ull sB2p[16];
    __shared__ __align__(16) float sSt[4][32 * 36];
    int tid = threadIdx.x;
    for (int i = tid; i < 512; i += 128) sW2p[i] = ((const ull*)W2)[i];
    if (tid < MIDD) sw15[tid] = W1[15 * MIDD + tid];
    if (tid < 16) sB2p[tid] = ((const ull*)b2)[tid];
    __syncthreads();

    int t = blockIdx.x * 128 + tid;
    int e0 = 2 * t;
    int s = g_srcS[e0];
    float2 dd = *(const float2*)(g_distS + e0);
    float2 sc = *(const float2*)(g_scaleS + e0);
    float da = dd.x, db = dd.y;
    float bsa = Y0F * sc.x, bsb = Y0F * sc.y;

    float u[MIDD];
    {
        const float4* up = (const float4*)(g_u + (size_t)s * MIDD);
#pragma unroll
        for (int k = 0; k < 8; k++) {
            float4 v = up[k];
            u[4 * k] = v.x; u[4 * k + 1] = v.y; u[4 * k + 2] = v.z; u[4 * k + 3] = v.w;
        }
    }

    ull acca[16], accb[16];
#pragma unroll
    for (int jp = 0; jp < 16; jp++) { acca[jp] = sB2p[jp]; accb[jp] = sB2p[jp]; }
#pragma unroll
    for (int i2 = 0; i2 < MIDD; i2++) {
        float w15v = sw15[i2];
        float ha = fmaxf(fmaf(da, w15v, u[i2]), 0.f);
        float hb = fmaxf(fmaf(db, w15v, u[i2]), 0.f);
        ull xa = pack2(ha, ha);
        ull xb = pack2(hb, hb);
#pragma unroll
        for (int jq = 0; jq < 8; jq++) {
            ulonglong2 w = *(const ulonglong2*)&sW2p[i2 * 16 + jq * 2];
            acca[2 * jq]     = fma2(xa, w.x, acca[2 * jq]);
            acca[2 * jq + 1] = fma2(xa, w.y, acca[2 * jq + 1]);
            accb[2 * jq]     = fma2(xb, w.x, accb[2 * jq]);
            accb[2 * jq + 1] = fma2(xb, w.y, accb[2 * jq + 1]);
        }
    }
    float h2a[MIDD], h2b[MIDD];
#pragma unroll
    for (int jp = 0; jp < 16; jp++) {
        float lo, hi;
        unpack2(acca[jp], lo, hi);
        h2a[2 * jp] = fmaxf(lo, 0.f); h2a[2 * jp + 1] = fmaxf(hi, 0.f);
        unpack2(accb[jp], lo, hi);
        h2b[2 * jp] = fmaxf(lo, 0.f); h2b[2 * jp + 1] = fmaxf(hi, 0.f);
    }

    ull ka[8], kb[8];
    {
        const ulonglong2* pbp = (const ulonglong2*)(g_PB + (size_t)s * CC);
#pragma unroll
        for (int q = 0; q < 4; q++) {
            ulonglong2 pb = pbp[q];
            ka[2 * q] = pb.x; ka[2 * q + 1] = pb.y;
            kb[2 * q] = pb.x; kb[2 * q + 1] = pb.y;
        }
    }
    const ull* Pp = (const ull*)(g_P + (size_t)s * 512);
#pragma unroll
    for (int mq = 0; mq < 8; mq++) {
        ull xa0 = pack2(h2a[mq * 4 + 0], h2a[mq * 4 + 0]);
        ull xa1 = pack2(h2a[mq * 4 + 1], h2a[mq * 4 + 1]);
        ull xa2 = pack2(h2a[mq * 4 + 2], h2a[mq * 4 + 2]);
        ull xa3 = pack2(h2a[mq * 4 + 3], h2a[mq * 4 + 3]);
        ull xb0 = pack2(h2b[mq * 4 + 0], h2b[mq * 4 + 0]);
        ull xb1 = pack2(h2b[mq * 4 + 1], h2b[mq * 4 + 1]);
        ull xb2 = pack2(h2b[mq * 4 + 2], h2b[mq * 4 + 2]);
        ull xb3 = pack2(h2b[mq * 4 + 3], h2b[mq * 4 + 3]);
#pragma unroll
        for (int j = 0; j < 8; j++) {
            ulonglong2 pA = *(const ulonglong2*)(Pp + mq * 32 + j * 4);
            ulonglong2 pB = *(const ulonglong2*)(Pp + mq * 32 + j * 4 + 2);
            ka[j] = fma2(xa0, pA.x, ka[j]);
            ka[j] = fma2(xa1, pA.y, ka[j]);
            ka[j] = fma2(xa2, pB.x, ka[j]);
            ka[j] = fma2(xa3, pB.y, ka[j]);
            kb[j] = fma2(xb0, pA.x, kb[j]);
            kb[j] = fma2(xb1, pA.y, kb[j]);
            kb[j] = fma2(xb2, pB.x, kb[j]);
            kb[j] = fma2(xb3, pB.y, kb[j]);
        }
    }

    int lane = tid & 31, w = tid >> 5;
    float* st = sSt[w];
#pragma unroll
    for (int q = 0; q < 4; q++) {
        float a0, a1, a2, a3;
        unpack2(ka[2 * q], a0, a1);
        unpack2(ka[2 * q + 1], a2, a3);
        *(float4*)&st[lane * 36 + q * 4] = make_float4(a0 * bsa, a1 * bsa, a2 * bsa, a3 * bsa);
    }
#pragma unroll
    for (int q = 0; q < 4; q++) {
        float a0, a1, a2, a3;
        unpack2(kb[2 * q], a0, a1);
        unpack2(kb[2 * q + 1], a2, a3);
        *(float4*)&st[lane * 36 + 16 + q * 4] = make_float4(a0 * bsb, a1 * bsb, a2 * bsb, a3 * bsb);
    }
    __syncwarp();
    float4* gbase = (float4*)(g_vk + (size_t)(blockIdx.x * 256 + w * 64) * CC);
#pragma unroll
    for (int g = 0; g < 8; g++) {
        int f = g * 32 + lane;
        int owner = f >> 3, q = f & 7;
        gbase[f] = *(const float4*)&st[owner * 36 + q * 4];
    }
}

// ---------------- final ----------------
__device__ __forceinline__ float siluf(float x) { return x / (1.f + __expf(-x)); }

__global__ void k_final(const int* __restrict__ species, const float* __restrict__ emb,
                        const float* __restrict__ W1, const float* __restrict__ b1,
                        const float* __restrict__ W2, const float* __restrict__ b2,
                        const float* __restrict__ W3, const float* __restrict__ b3,
                        float* __restrict__ out) {
    __shared__ float sFeat[16 * 17];
    __shared__ float sEmb[16 * 17];
    __shared__ float sH[16 * 17];
    __shared__ float sRed[16];
    int tid = threadIdx.x;
    int nloc = tid >> 4, o = tid & 15;
    int n = blockIdx.x * 16 + nloc;
    int beg = g_rdst[n], end = g_rdst[n + 1];
    int o2 = (o < 8) ? o * 2 : (o - 8) * 2 + 1;
    float f = g_feats[n * CC + o];
    for (int i = beg; i < end; i++) {
        int ei = g_es[i].x;
        f += g_vk[(size_t)ei * CC + o2];
    }
    sFeat[nloc * 17 + o] = f;
    int sp = species[n] - 1;
    sEmb[nloc * 17 + o] = emb[sp * CC + o];
    __syncthreads();

    float h1 = b1[o];
#pragma unroll
    for (int k = 0; k < CC; k++) h1 = fmaf(sEmb[nloc * 17 + k], W1[k * CC + o], h1);
#pragma unroll
    for (int k = 0; k < CC; k++) h1 = fmaf(sFeat[nloc * 17 + k], W1[(CC + k) * CC + o], h1);
    sH[nloc * 17 + o] = siluf(h1);
    __syncthreads();

    float h2 = b2[o];
#pragma unroll
    for (int k = 0; k < CC; k++) h2 = fmaf(sH[nloc * 17 + k], W2[k * CC + o], h2);
    h2 = siluf(h2);

    float part = h2 * W3[o];
#pragma unroll
    for (int off = 8; off > 0; off >>= 1)
        part += __shfl_down_sync(0xffffffffu, part, off, 16);
    if (o == 0) sRed[nloc] = part + b3[0] + g_coulN[n];
    __syncthreads();
    if (tid == 0) {
        float acc = 0.f;
#pragma unroll
        for (int k = 0; k < 16; k++) acc += sRed[k];
        atomicAdd(out, acc);
    }
}

// ---------------- host launch ----------------
extern "C" void kernel_launch(void* const* d_in, const int* in_sizes, int n_in,
                              void* d_out, int out_size) {
    const int* species  = (const int*)d_in[0];
    const int* src      = (const int*)d_in[1];
    const int* dst      = (const int*)d_in[2];
    const float* rel_pos = (const float*)d_in[3];
    const float* emb    = (const float*)d_in[4];
    const float* kv_W1  = (const float*)d_in[5];
    const float* kv_b1  = (const float*)d_in[6];
    const float* kv_W2  = (const float*)d_in[7];
    const float* kv_b2  = (const float*)d_in[8];
    const float* kv_W3  = (const float*)d_in[9];
    const float* kv_b3  = (const float*)d_in[10];
    const float* Wq     = (const float*)d_in[11];
    const float* Wproj  = (const float*)d_in[12];
    const float* fin_W1 = (const float*)d_in[13];
    const float* fin_b1 = (const float*)d_in[14];
    const float* fin_W2 = (const float*)d_in[15];
    const float* fin_b2 = (const float*)d_in[16];
    const float* fin_W3 = (const float*)d_in[17];
    const float* fin_b3 = (const float*)d_in[18];
    const float* Wself  = (const float*)d_in[19];
    const float* mlp_W1 = (const float*)d_in[20];
    const float* mlp_b1 = (const float*)d_in[21];
    const float* mlp_W2 = (const float*)d_in[22];
    const float* mlp_b2 = (const float*)d_in[23];
    const float* mlp_W3 = (const float*)d_in[24];
    const float* mlp_b3 = (const float*)d_in[25];
    float* out = (float*)d_out;

    const int EB = EE / 256;         // 2048
    const int EDGB = EENP / 256;     // 2176

    k_init<<<EB, 256>>>(species, emb, out, src, dst);
    k_scan<<<2, 1024>>>();
    k_scatter<<<EB, 256>>>(src, dst, rel_pos, species);
    k_nodeprep0<<<NGRID, NLT>>>(Wq, kv_W3, kv_b3, kv_W1, kv_b1);

    for (int l = 0; l < 4; l++) {
        k_edge<<<EDGB, 128>>>(kv_W1 + (size_t)l * CC * MIDD,
                              kv_W2 + (size_t)l * MIDD * MIDD,
                              kv_b2 + (size_t)l * MIDD);
        if (l < 3) {
            k_node_layer<<<NGRID, NLT>>>(1,
                Wproj + (size_t)l * CC * 24,
                Wq + (size_t)(l + 1) * HH * CC,
                kv_W3 + (size_t)(l + 1) * MIDD * 256,
                kv_b3 + (size_t)(l + 1) * 256,
                kv_W1 + (size_t)(l + 1) * CC * MIDD,
                kv_b1 + (size_t)(l + 1) * MIDD,
                nullptr);
        } else {
            k_node_layer<<<NGRID, NLT>>>(2,
                Wproj + (size_t)l * CC * 24,
                nullptr,
                fin_W3, fin_b3, fin_W1, fin_b1, Wself);
        }
    }
    k_edge<<<EDGB, 128>>>(fin_W1, fin_W2, fin_b2);
    k_final<<<NN / 16, 256>>>(species, emb, mlp_W1, mlp_b1, mlp_W2, mlp_b2,
                              mlp_W3, mlp_b3, out);
}

// round 13
// speedup vs baseline: 1.4142x; 1.2382x over previous
#include <cuda_runtime.h>
#include <math.h>

#define NN 32768
#define EE 524288
#define EENP (EE + NN)          // padded src-sorted capacity (557056 = 256*2176)
#define CC 16
#define MIDD 32
#define HH 8
#define Y0F 0.28209479177387814f
#define CUTOFFF 4.6f
#define KCOULF 0.529f

typedef unsigned long long ull;

// ---------------- device scratch ----------------
__device__ __align__(16) float g_x[NN * CC];
__device__ __align__(16) float g_S[NN * CC];
__device__ __align__(16) float g_q[NN * HH];
__device__ __align__(16) float g_u[NN * MIDD];
__device__ __align__(16) float g_P[NN * 512];     // pair-interleaved
__device__ __align__(16) float g_PB[NN * CC];     // pair-interleaved
__device__ __align__(16) float g_feats[NN * CC];
__device__ __align__(16) float g_vk[(size_t)EENP * CC]; // padded src-sorted {val,key}
__device__ float g_distS[EENP];
__device__ float g_scaleS[EENP];
__device__ __align__(8) int2 g_es[EE];            // dst-order: {src-order idx, scale bits}
__device__ float g_coulN[NN];
__device__ int g_srcS[EENP];
__device__ int g_csrc[NN], g_cdst[NN];
__device__ int g_rdst[NN + 1];
__device__ int g_cursrc[NN], g_curdst[NN];

// ---------------- f32x2 helpers ----------------
__device__ __forceinline__ ull pack2(float a, float b) {
    ull r;
    asm("mov.b64 %0, {%1, %2};" : "=l"(r) : "f"(a), "f"(b));
    return r;
}
__device__ __forceinline__ ull fma2(ull a, ull b, ull c) {
    ull d;
    asm("fma.rn.f32x2 %0, %1, %2, %3;" : "=l"(d) : "l"(a), "l"(b), "l"(c));
    return d;
}
__device__ __forceinline__ void unpack2(ull v, float& lo, float& hi) {
    asm("mov.b64 {%0, %1}, %2;" : "=f"(lo), "=f"(hi) : "l"(v));
}

// ---------------- init ----------------
__global__ void k_init(const int* __restrict__ species, const float* __restrict__ emb,
                       float* __restrict__ out,
                       const int* __restrict__ src, const int* __restrict__ dst) {
    int e = blockIdx.x * 256 + threadIdx.x;
    if (e < NN) {
        int sp = species[e] - 1;
#pragma unroll
        for (int c = 0; c < CC; c++) {
            g_x[e * CC + c] = emb[sp * CC + c];
            g_S[e * CC + c] = 0.f;
        }
        g_coulN[e] = 0.f;
        if (e == 0) out[0] = 0.f;
    }
    atomicAdd(&g_csrc[src[e]], 1);
    atomicAdd(&g_cdst[dst[e]], 1);
}

// ---------------- scan ----------------
__global__ void k_scan() {
    const int T = 1024, PER = NN / 1024;
    __shared__ int part[T];
    int t = threadIdx.x;
    int base = t * PER;
    if (blockIdx.x == 0) {
        int loc[PER], locp[PER];
        int s = 0;
#pragma unroll
        for (int i = 0; i < PER; i++) {
            loc[i] = g_csrc[base + i];
            g_csrc[base + i] = 0;
            locp[i] = (loc[i] + 1) & ~1;
            s += locp[i];
        }
        part[t] = s;
        __syncthreads();
        for (int off = 1; off < T; off <<= 1) {
            int v = (t >= off) ? part[t - off] : 0;
            __syncthreads();
            part[t] += v;
            __syncthreads();
        }
        int run = part[t] - s;
#pragma unroll
        for (int i = 0; i < PER; i++) {
            g_cursrc[base + i] = run;
            if (loc[i] & 1) g_srcS[run + loc[i]] = base + i;
            run += locp[i];
        }
    } else {
        int loc[PER];
        int s = 0;
#pragma unroll
        for (int i = 0; i < PER; i++) {
            loc[i] = g_cdst[base + i];
            g_cdst[base + i] = 0;
            s += loc[i];
        }
        part[t] = s;
        __syncthreads();
        for (int off = 1; off < T; off <<= 1) {
            int v = (t >= off) ? part[t - off] : 0;
            __syncthreads();
            part[t] += v;
            __syncthreads();
        }
        int run = part[t] - s;
#pragma unroll
        for (int i = 0; i < PER; i++) {
            g_rdst[base + i] = run;
            g_curdst[base + i] = run;
            run += loc[i];
        }
        if (t == T - 1) g_rdst[NN] = run;
    }
}

// ---------------- scatter ----------------
__global__ void __launch_bounds__(256)
k_scatter(const int* __restrict__ src, const int* __restrict__ dst,
          const float* __restrict__ rel_pos, const int* __restrict__ species) {
    int e = blockIdx.x * 256 + threadIdx.x;
    int s = src[e], d = dst[e];
    float px = rel_pos[e * 3 + 0], py = rel_pos[e * 3 + 1], pz = rel_pos[e * 3 + 2];
    float dist = sqrtf(px * px + py * py + pz * pz);
    float xc = dist / CUTOFFF;
    bool in_cut = dist < CUTOFFF;
    float x2 = in_cut ? fminf(xc * xc, 1.f - 1e-6f) : 0.f;
    float scale = in_cut ? expf(3.f - 3.f / (1.f - x2)) : 0.f;

    int ps = atomicAdd(&g_cursrc[s], 1);
    int pd = atomicAdd(&g_curdst[d], 1);
    g_srcS[ps] = s;
    g_distS[ps] = dist;
    g_scaleS[ps] = scale;
    g_es[pd] = make_int2(ps, __float_as_int(scale));

    float Zu = (float)species[s];
    float Zv = (float)species[d];
    float raw = KCOULF * Zu * Zv / (2.f * dist);
    float au = 0.8854f * 0.529f / (__powf(Zu, 0.23f) + __powf(Zv, 0.23f));
    float xx = dist / au;
    float screen = 0.1818f * __expf(-3.2f * xx) + 0.5099f * __expf(-0.9423f * xx)
                 + 0.2802f * __expf(-0.4028f * xx) + 0.02817f * __expf(-0.2016f * xx);
    float contrib = raw * screen * scale;
    if (contrib != 0.f) atomicAdd(&g_coulN[d], contrib);
}

// ---------------- node-prep helpers ----------------
#define NLT 256                 // node-layer threads
#define NLN 32                  // nodes per tile
#define NTILES (NN / NLN)       // 1024
#define NGRID 296               // 2 blocks/SM x 148

// small-weight staging (no W3 — that lives in registers now)
__device__ __forceinline__ void load_node_weights(
    int tid, const float* __restrict__ b3,
    const float* __restrict__ W1n, const float* __restrict__ b1n,
    const float* __restrict__ Wq, const float* __restrict__ Wself,
    float* sW1, float* sWq, float* sb3, float* sb1, float* sWself) {
    for (int idx = tid; idx < CC * MIDD; idx += NLT) sW1[idx] = W1n[idx];
    if (Wq && tid < HH * CC) sWq[(tid >> 4) * 18 + (tid & 15)] = Wq[tid];
    { int o = tid >> 4, i = tid & 15; sb3[o * 18 + i] = b3[tid]; }
    if (tid < MIDD) sb1[tid] = b1n[tid];
    if (Wself && tid < CC * CC) sWself[(tid >> 4) * 18 + (tid & 15)] = Wself[tid];
}

// per-thread W3 slice: thread tid owns (m = (tid>>5)*4 + (tid&3), op = (tid>>2)&7)
__device__ __forceinline__ void load_w3_regs(int tid, const float* __restrict__ W3,
                                             ull wA[8], ull wB[8]) {
    int mq = tid >> 5, op = (tid >> 2) & 7, r = tid & 3;
    int m = mq * 4 + r;
    const ulonglong2* pa = (const ulonglong2*)(W3 + m * 256 + op * 16);
    const ulonglong2* pb = (const ulonglong2*)(W3 + m * 256 + (op + 8) * 16);
#pragma unroll
    for (int t = 0; t < 4; t++) {
        ulonglong2 va = pa[t];
        wA[2 * t] = va.x; wA[2 * t + 1] = va.y;
        ulonglong2 vb = pb[t];
        wB[2 * t] = vb.x; wB[2 * t + 1] = vb.y;
    }
}

// phase B: P for all NLN nodes of the tile; write offset = tid*2 (matches k_edge layout)
__device__ __forceinline__ void prep_P_reg(int n0, int tid,
                                           const ull wA[8], const ull wB[8],
                                           const float* sXn) {
#pragma unroll 2
    for (int nloc = 0; nloc < NLN; nloc++) {
        const ulonglong2* xp = (const ulonglong2*)&sXn[nloc * CC];
        ulonglong2 x01 = xp[0], x23 = xp[1], x45 = xp[2], x67 = xp[3];
        ull aA = 0ULL, aB = 0ULL;
        aA = fma2(x01.x, wA[0], aA); aB = fma2(x01.x, wB[0], aB);
        aA = fma2(x01.y, wA[1], aA); aB = fma2(x01.y, wB[1], aB);
        aA = fma2(x23.x, wA[2], aA); aB = fma2(x23.x, wB[2], aB);
        aA = fma2(x23.y, wA[3], aA); aB = fma2(x23.y, wB[3], aB);
        aA = fma2(x45.x, wA[4], aA); aB = fma2(x45.x, wB[4], aB);
        aA = fma2(x45.y, wA[5], aA); aB = fma2(x45.y, wB[5], aB);
        aA = fma2(x67.x, wA[6], aA); aB = fma2(x67.x, wB[6], aB);
        aA = fma2(x67.y, wA[7], aA); aB = fma2(x67.y, wB[7], aB);
        float la, ha, lb, hb;
        unpack2(aA, la, ha);
        unpack2(aB, lb, hb);
        *(ull*)(g_P + (size_t)(n0 + nloc) * 512 + tid * 2) = pack2(la + ha, lb + hb);
    }
}

// phase A: q/u/PB/feats for node n; lane j owns o-pair (j, j+8)
__device__ __forceinline__ void node_prep_a(
    int n, int nloc, int j, bool do_q, bool do_feats,
    const float* sW1, const float* sWq,
    const float* sb3, const float* sb1, const float* sWself,
    const float* sXn, const float* sSn) {
    ull xx[8];
#pragma unroll
    for (int ip = 0; ip < 8; ip++)
        xx[ip] = *(const ull*)&sXn[nloc * CC + 2 * ip];

    if (do_q) {
        float qa = 0.f;
#pragma unroll
        for (int c = 0; c < CC; c++) qa = fmaf(sWq[j * 18 + c], sXn[nloc * CC + c], qa);
        g_q[n * HH + j] = qa;
    }
    {
        float u0 = sb1[j], u1 = sb1[j + 8], u2 = sb1[j + 16], u3 = sb1[j + 24];
#pragma unroll
        for (int c = 0; c < CC; c++) {
            float sv = sSn[nloc * CC + c];
            u0 = fmaf(sv, sW1[c * MIDD + j], u0);
            u1 = fmaf(sv, sW1[c * MIDD + j + 8], u1);
            u2 = fmaf(sv, sW1[c * MIDD + j + 16], u2);
            u3 = fmaf(sv, sW1[c * MIDD + j + 24], u3);
        }
        g_u[n * MIDD + j] = u0;
        g_u[n * MIDD + j + 8] = u1;
        g_u[n * MIDD + j + 16] = u2;
        g_u[n * MIDD + j + 24] = u3;
    }
    {
        ull a0 = 0ULL, a1 = 0ULL;
#pragma unroll
        for (int ip = 0; ip < 8; ip++) {
            a0 = fma2(xx[ip], *(const ull*)&sb3[j * 18 + 2 * ip], a0);
            a1 = fma2(xx[ip], *(const ull*)&sb3[(j + 8) * 18 + 2 * ip], a1);
        }
        float l0, h0, l1, h1;
        unpack2(a0, l0, h0);
        unpack2(a1, l1, h1);
        g_PB[n * CC + j * 2] = l0 + h0;
        g_PB[n * CC + j * 2 + 1] = l1 + h1;
    }
    if (do_feats) {
        ull a0 = 0ULL, a1 = 0ULL;
#pragma unroll
        for (int ip = 0; ip < 8; ip++) {
            a0 = fma2(xx[ip], *(const ull*)&sWself[j * 18 + 2 * ip], a0);
            a1 = fma2(xx[ip], *(const ull*)&sWself[(j + 8) * 18 + 2 * ip], a1);
        }
        float l0, h0, l1, h1;
        unpack2(a0, l0, h0);
        unpack2(a1, l1, h1);
        g_feats[n * CC + j] = l0 + h0;
        g_feats[n * CC + 8 + j] = l1 + h1;
    }
}

// ---------------- initial node prep (layer 0): persistent tiles ----------------
__global__ void __launch_bounds__(NLT)
k_nodeprep0(const float* __restrict__ Wq, const float* __restrict__ W3,
            const float* __restrict__ b3, const float* __restrict__ W1n,
            const float* __restrict__ b1n) {
    __shared__ __align__(16) float sW1[CC * MIDD];
    __shared__ __align__(16) float sWq[HH * 18];
    __shared__ __align__(16) float sb3[16 * 18];
    __shared__ __align__(16) float sb1[MIDD];
    __shared__ __align__(16) float sXn[NLN * CC];
    __shared__ __align__(16) float sSn[NLN * CC];
    int tid = threadIdx.x;
    ull wA[8], wB[8];
    load_w3_regs(tid, W3, wA, wB);
    load_node_weights(tid, b3, W1n, b1n, Wq, nullptr, sW1, sWq, sb3, sb1, nullptr);
    int nloc = tid >> 3, j = tid & 7;
    for (int tile = blockIdx.x; tile < NTILES; tile += NGRID) {
        __syncthreads();
        int n = tile * NLN + nloc;
        sXn[nloc * CC + j] = g_x[n * CC + j];
        sXn[nloc * CC + 8 + j] = g_x[n * CC + 8 + j];
        sSn[nloc * CC + j] = 0.f;
        sSn[nloc * CC + 8 + j] = 0.f;
        __syncthreads();
        node_prep_a(n, nloc, j, true, false, sW1, sWq, sb3, sb1, nullptr, sXn, sSn);
        prep_P_reg(tile * NLN, tid, wA, wB, sXn);
    }
}

// ---------------- node layer: persistent tiles, online-softmax + Wproj + prep ----------------
__global__ void __launch_bounds__(NLT)
k_node_layer(int mode,
             const float* __restrict__ Wproj,
             const float* __restrict__ Wq,
             const float* __restrict__ W3,
             const float* __restrict__ b3,
             const float* __restrict__ W1n,
             const float* __restrict__ b1n,
             const float* __restrict__ Wself) {
    __shared__ __align__(16) float sW1[CC * MIDD];
    __shared__ __align__(16) float sWq[HH * 18];
    __shared__ __align__(16) float sWproj[CC * 25];
    __shared__ __align__(16) float sb3[16 * 18];
    __shared__ __align__(16) float sb1[MIDD];
    __shared__ __align__(16) float sWself[16 * 18];
    __shared__ __align__(16) float sAgg[NLN * HH];
    __shared__ __align__(16) float sXold[NLN * CC];
    __shared__ __align__(16) float sXn[NLN * CC];
    __shared__ __align__(16) float sSn[NLN * CC];

    int tid = threadIdx.x;
    int nloc = tid >> 3, j = tid & 7;

    ull wA[8], wB[8];
    load_w3_regs(tid, W3, wA, wB);
    load_node_weights(tid, b3, W1n, b1n,
                      mode != 2 ? Wq : nullptr,
                      mode == 2 ? Wself : nullptr,
                      sW1, sWq, sb3, sb1, sWself);
    for (int idx = tid; idx < CC * 24; idx += NLT)
        sWproj[(idx / 24) * 25 + (idx % 24)] = Wproj[idx];

    for (int tile = blockIdx.x; tile < NTILES; tile += NGRID) {
        __syncthreads();
        int n = tile * NLN + nloc;
        {
            int beg = g_rdst[n], end = g_rdst[n + 1];
            float qj = g_q[n * HH + j];
            float m = -INFINITY, num = 0.f, den = 0.f;
#pragma unroll 2
            for (int i = beg; i < end; i++) {
                int2 es = g_es[i];
                float2 vk = *(const float2*)(g_vk + (size_t)es.x * CC + j * 2);
                float sc = __int_as_float(es.y);
                float l = vk.y * qj;
                float mn = fmaxf(m, l);
                float corr = __expf(m - mn);
                float p = sc * __expf(l - mn);
                den = den * corr + p;
                num = fmaf(num, corr, p * vk.x);
                m = mn;
            }
            sAgg[nloc * HH + j] = num / fmaxf(den, 1e-20f);
            sXold[nloc * CC + j] = g_x[n * CC + j];
            sXold[nloc * CC + 8 + j] = g_x[n * CC + 8 + j];
            __syncthreads();
            float xn0 = 0.f, xn1 = 0.f;
#pragma unroll
            for (int k = 0; k < 8; k++) {
                float a = sAgg[nloc * HH + k];
                xn0 = fmaf(sWproj[j * 25 + k], a, xn0);
                xn1 = fmaf(sWproj[(j + 8) * 25 + k], a, xn1);
            }
#pragma unroll
            for (int k = 0; k < CC; k++) {
                float xo = sXold[nloc * CC + k];
                xn0 = fmaf(sWproj[j * 25 + 8 + k], xo, xn0);
                xn1 = fmaf(sWproj[(j + 8) * 25 + 8 + k], xo, xn1);
            }
            float s0 = g_S[n * CC + j] + xn0;
            float s1 = g_S[n * CC + 8 + j] + xn1;
            g_x[n * CC + j] = xn0;     g_x[n * CC + 8 + j] = xn1;
            g_S[n * CC + j] = s0;      g_S[n * CC + 8 + j] = s1;
            sXn[nloc * CC + j] = xn0;  sXn[nloc * CC + 8 + j] = xn1;
            sSn[nloc * CC + j] = s0;   sSn[nloc * CC + 8 + j] = s1;
            __syncthreads();
        }
        node_prep_a(n, nloc, j, mode != 2, mode == 2,
                    sW1, sWq, sb3, sb1, sWself, sXn, sSn);
        prep_P_reg(tile * NLN, tid, wA, wB, sXn);
    }
}

// ---------------- edge kernel (R8 best, unchanged) ----------------
__global__ void __launch_bounds__(128, 4)
k_edge(const float* __restrict__ W1, const float* __restrict__ W2,
       const float* __restrict__ b2) {
    __shared__ __align__(16) ull sW2p[512];
    __shared__ float sw15[MIDD];
    __shared__ __align__(16) ull sB2p[16];
    __shared__ __align__(16) float sSt[4][32 * 36];
    int tid = threadIdx.x;
    for (int i = tid; i < 512; i += 128) sW2p[i] = ((const ull*)W2)[i];
    if (tid < MIDD) sw15[tid] = W1[15 * MIDD + tid];
    if (tid < 16) sB2p[tid] = ((const ull*)b2)[tid];
    __syncthreads();

    int t = blockIdx.x * 128 + tid;
    int e0 = 2 * t;
    int s = g_srcS[e0];
    float2 dd = *(const float2*)(g_distS + e0);
    float2 sc = *(const float2*)(g_scaleS + e0);
    float da = dd.x, db = dd.y;
    float bsa = Y0F * sc.x, bsb = Y0F * sc.y;

    float u[MIDD];
    {
        const float4* up = (const float4*)(g_u + (size_t)s * MIDD);
#pragma unroll
        for (int k = 0; k < 8; k++) {
            float4 v = up[k];
            u[4 * k] = v.x; u[4 * k + 1] = v.y; u[4 * k + 2] = v.z; u[4 * k + 3] = v.w;
        }
    }

    ull acca[16], accb[16];
#pragma unroll
    for (int jp = 0; jp < 16; jp++) { acca[jp] = sB2p[jp]; accb[jp] = sB2p[jp]; }
#pragma unroll
    for (int i2 = 0; i2 < MIDD; i2++) {
        float w15v = sw15[i2];
        float ha = fmaxf(fmaf(da, w15v, u[i2]), 0.f);
        float hb = fmaxf(fmaf(db, w15v, u[i2]), 0.f);
        ull xa = pack2(ha, ha);
        ull xb = pack2(hb, hb);
#pragma unroll
        for (int jq = 0; jq < 8; jq++) {
            ulonglong2 w = *(const ulonglong2*)&sW2p[i2 * 16 + jq * 2];
            acca[2 * jq]     = fma2(xa, w.x, acca[2 * jq]);
            acca[2 * jq + 1] = fma2(xa, w.y, acca[2 * jq + 1]);
            accb[2 * jq]     = fma2(xb, w.x, accb[2 * jq]);
            accb[2 * jq + 1] = fma2(xb, w.y, accb[2 * jq + 1]);
        }
    }
    float h2a[MIDD], h2b[MIDD];
#pragma unroll
    for (int jp = 0; jp < 16; jp++) {
        float lo, hi;
        unpack2(acca[jp], lo, hi);
        h2a[2 * jp] = fmaxf(lo, 0.f); h2a[2 * jp + 1] = fmaxf(hi, 0.f);
        unpack2(accb[jp], lo, hi);
        h2b[2 * jp] = fmaxf(lo, 0.f); h2b[2 * jp + 1] = fmaxf(hi, 0.f);
    }

    ull ka[8], kb[8];
    {
        const ulonglong2* pbp = (const ulonglong2*)(g_PB + (size_t)s * CC);
#pragma unroll
        for (int q = 0; q < 4; q++) {
            ulonglong2 pb = pbp[q];
            ka[2 * q] = pb.x; ka[2 * q + 1] = pb.y;
            kb[2 * q] = pb.x; kb[2 * q + 1] = pb.y;
        }
    }
    const ull* Pp = (const ull*)(g_P + (size_t)s * 512);
#pragma unroll
    for (int mq = 0; mq < 8; mq++) {
        ull xa0 = pack2(h2a[mq * 4 + 0], h2a[mq * 4 + 0]);
        ull xa1 = pack2(h2a[mq * 4 + 1], h2a[mq * 4 + 1]);
        ull xa2 = pack2(h2a[mq * 4 + 2], h2a[mq * 4 + 2]);
        ull xa3 = pack2(h2a[mq * 4 + 3], h2a[mq * 4 + 3]);
        ull xb0 = pack2(h2b[mq * 4 + 0], h2b[mq * 4 + 0]);
        ull xb1 = pack2(h2b[mq * 4 + 1], h2b[mq * 4 + 1]);
        ull xb2 = pack2(h2b[mq * 4 + 2], h2b[mq * 4 + 2]);
        ull xb3 = pack2(h2b[mq * 4 + 3], h2b[mq * 4 + 3]);
#pragma unroll
        for (int j = 0; j < 8; j++) {
            ulonglong2 pA = *(const ulonglong2*)(Pp + mq * 32 + j * 4);
            ulonglong2 pB = *(const ulonglong2*)(Pp + mq * 32 + j * 4 + 2);
            ka[j] = fma2(xa0, pA.x, ka[j]);
            ka[j] = fma2(xa1, pA.y, ka[j]);
            ka[j] = fma2(xa2, pB.x, ka[j]);
            ka[j] = fma2(xa3, pB.y, ka[j]);
            kb[j] = fma2(xb0, pA.x, kb[j]);
            kb[j] = fma2(xb1, pA.y, kb[j]);
            kb[j] = fma2(xb2, pB.x, kb[j]);
            kb[j] = fma2(xb3, pB.y, kb[j]);
        }
    }

    int lane = tid & 31, w = tid >> 5;
    float* st = sSt[w];
#pragma unroll
    for (int q = 0; q < 4; q++) {
        float a0, a1, a2, a3;
        unpack2(ka[2 * q], a0, a1);
        unpack2(ka[2 * q + 1], a2, a3);
        *(float4*)&st[lane * 36 + q * 4] = make_float4(a0 * bsa, a1 * bsa, a2 * bsa, a3 * bsa);
    }
#pragma unroll
    for (int q = 0; q < 4; q++) {
        float a0, a1, a2, a3;
        unpack2(kb[2 * q], a0, a1);
        unpack2(kb[2 * q + 1], a2, a3);
        *(float4*)&st[lane * 36 + 16 + q * 4] = make_float4(a0 * bsb, a1 * bsb, a2 * bsb, a3 * bsb);
    }
    __syncwarp();
    float4* gbase = (float4*)(g_vk + (size_t)(blockIdx.x * 256 + w * 64) * CC);
#pragma unroll
    for (int g = 0; g < 8; g++) {
        int f = g * 32 + lane;
        int owner = f >> 3, q = f & 7;
        gbase[f] = *(const float4*)&st[owner * 36 + q * 4];
    }
}

// ---------------- final ----------------
__device__ __forceinline__ float siluf(float x) { return x / (1.f + __expf(-x)); }

__global__ void k_final(const int* __restrict__ species, const float* __restrict__ emb,
                        const float* __restrict__ W1, const float* __restrict__ b1,
                        const float* __restrict__ W2, const float* __restrict__ b2,
                        const float* __restrict__ W3, const float* __restrict__ b3,
                        float* __restrict__ out) {
    __shared__ float sFeat[16 * 17];
    __shared__ float sEmb[16 * 17];
    __shared__ float sH[16 * 17];
    __shared__ float sRed[16];
    int tid = threadIdx.x;
    int nloc = tid >> 4, o = tid & 15;
    int n = blockIdx.x * 16 + nloc;
    int beg = g_rdst[n], end = g_rdst[n + 1];
    int o2 = (o < 8) ? o * 2 : (o - 8) * 2 + 1;
    float f = g_feats[n * CC + o];
    for (int i = beg; i < end; i++) {
        int ei = g_es[i].x;
        f += g_vk[(size_t)ei * CC + o2];
    }
    sFeat[nloc * 17 + o] = f;
    int sp = species[n] - 1;
    sEmb[nloc * 17 + o] = emb[sp * CC + o];
    __syncthreads();

    float h1 = b1[o];
#pragma unroll
    for (int k = 0; k < CC; k++) h1 = fmaf(sEmb[nloc * 17 + k], W1[k * CC + o], h1);
#pragma unroll
    for (int k = 0; k < CC; k++) h1 = fmaf(sFeat[nloc * 17 + k], W1[(CC + k) * CC + o], h1);
    sH[nloc * 17 + o] = siluf(h1);
    __syncthreads();

    float h2 = b2[o];
#pragma unroll
    for (int k = 0; k < CC; k++) h2 = fmaf(sH[nloc * 17 + k], W2[k * CC + o], h2);
    h2 = siluf(h2);

    float part = h2 * W3[o];
#pragma unroll
    for (int off = 8; off > 0; off >>= 1)
        part += __shfl_down_sync(0xffffffffu, part, off, 16);
    if (o == 0) sRed[nloc] = part + b3[0] + g_coulN[n];
    __syncthreads();
    if (tid == 0) {
        float acc = 0.f;
#pragma unroll
        for (int k = 0; k < 16; k++) acc += sRed[k];
        atomicAdd(out, acc);
    }
}

// ---------------- host launch ----------------
extern "C" void kernel_launch(void* const* d_in, const int* in_sizes, int n_in,
                              void* d_out, int out_size) {
    const int* species  = (const int*)d_in[0];
    const int* src      = (const int*)d_in[1];
    const int* dst      = (const int*)d_in[2];
    const float* rel_pos = (const float*)d_in[3];
    const float* emb    = (const float*)d_in[4];
    const float* kv_W1  = (const float*)d_in[5];
    const float* kv_b1  = (const float*)d_in[6];
    const float* kv_W2  = (const float*)d_in[7];
    const float* kv_b2  = (const float*)d_in[8];
    const float* kv_W3  = (const float*)d_in[9];
    const float* kv_b3  = (const float*)d_in[10];
    const float* Wq     = (const float*)d_in[11];
    const float* Wproj  = (const float*)d_in[12];
    const float* fin_W1 = (const float*)d_in[13];
    const float* fin_b1 = (const float*)d_in[14];
    const float* fin_W2 = (const float*)d_in[15];
    const float* fin_b2 = (const float*)d_in[16];
    const float* fin_W3 = (const float*)d_in[17];
    const float* fin_b3 = (const float*)d_in[18];
    const float* Wself  = (const float*)d_in[19];
    const float* mlp_W1 = (const float*)d_in[20];
    const float* mlp_b1 = (const float*)d_in[21];
    const float* mlp_W2 = (const float*)d_in[22];
    const float* mlp_b2 = (const float*)d_in[23];
    const float* mlp_W3 = (const float*)d_in[24];
    const float* mlp_b3 = (const float*)d_in[25];
    float* out = (float*)d_out;

    const int EB = EE / 256;         // 2048
    const int EDGB = EENP / 256;     // 2176

    k_init<<<EB, 256>>>(species, emb, out, src, dst);
    k_scan<<<2, 1024>>>();
    k_scatter<<<EB, 256>>>(src, dst, rel_pos, species);
    k_nodeprep0<<<NGRID, NLT>>>(Wq, kv_W3, kv_b3, kv_W1, kv_b1);

    for (int l = 0; l < 4; l++) {
        k_edge<<<EDGB, 128>>>(kv_W1 + (size_t)l * CC * MIDD,
                              kv_W2 + (size_t)l * MIDD * MIDD,
                              kv_b2 + (size_t)l * MIDD);
        if (l < 3) {
            k_node_layer<<<NGRID, NLT>>>(1,
                Wproj + (size_t)l * CC * 24,
                Wq + (size_t)(l + 1) * HH * CC,
                kv_W3 + (size_t)(l + 1) * MIDD * 256,
                kv_b3 + (size_t)(l + 1) * 256,
                kv_W1 + (size_t)(l + 1) * CC * MIDD,
                kv_b1 + (size_t)(l + 1) * MIDD,
                nullptr);
        } else {
            k_node_layer<<<NGRID, NLT>>>(2,
                Wproj + (size_t)l * CC * 24,
                nullptr,
                fin_W3, fin_b3, fin_W1, fin_b1, Wself);
        }
    }
    k_edge<<<EDGB, 128>>>(fin_W1, fin_W2, fin_b2);
    k_final<<<NN / 16, 256>>>(species, emb, mlp_W1, mlp_b1, mlp_W2, mlp_b2,
                              mlp_W3, mlp_b3, out);
}

// round 14
// speedup vs baseline: 1.4890x; 1.0529x over previous
#include <cuda_runtime.h>
#include <math.h>

#define NN 32768
#define EE 524288
#define EENP (EE + NN)          // padded src-sorted capacity (557056 = 256*2176)
#define CC 16
#define MIDD 32
#define HH 8
#define Y0F 0.28209479177387814f
#define CUTOFFF 4.6f
#define KCOULF 0.529f

typedef unsigned long long ull;

// ---------------- device scratch ----------------
__device__ __align__(16) float g_x[NN * CC];
__device__ __align__(16) float g_S[NN * CC];
__device__ __align__(16) float g_q[NN * HH];
__device__ __align__(16) float g_u[NN * MIDD];
__device__ __align__(16) float g_P[NN * 512];     // pair-interleaved
__device__ __align__(16) float g_PB[NN * CC];     // pair-interleaved
__device__ __align__(16) float g_feats[NN * CC];
__device__ __align__(16) float g_vk[(size_t)EENP * CC]; // padded src-sorted {val,key}
__device__ float g_distS[EENP];
__device__ float g_scaleS[EENP];
__device__ __align__(8) int2 g_es[EE];            // dst-order: {src-order idx, scale bits}
__device__ float g_coulN[NN];
__device__ int g_srcS[EENP];
__device__ int g_csrc[NN], g_cdst[NN];
__device__ int g_rdst[NN + 1];
__device__ int g_cursrc[NN], g_curdst[NN];

// ---------------- f32x2 helpers ----------------
__device__ __forceinline__ ull pack2(float a, float b) {
    ull r;
    asm("mov.b64 %0, {%1, %2};" : "=l"(r) : "f"(a), "f"(b));
    return r;
}
__device__ __forceinline__ ull fma2(ull a, ull b, ull c) {
    ull d;
    asm("fma.rn.f32x2 %0, %1, %2, %3;" : "=l"(d) : "l"(a), "l"(b), "l"(c));
    return d;
}
__device__ __forceinline__ void unpack2(ull v, float& lo, float& hi) {
    asm("mov.b64 {%0, %1}, %2;" : "=f"(lo), "=f"(hi) : "l"(v));
}

// ---------------- init ----------------
__global__ void k_init(const int* __restrict__ species, const float* __restrict__ emb,
                       float* __restrict__ out,
                       const int* __restrict__ src, const int* __restrict__ dst) {
    int e = blockIdx.x * 256 + threadIdx.x;
    if (e < NN) {
        int sp = species[e] - 1;
#pragma unroll
        for (int c = 0; c < CC; c++) {
            g_x[e * CC + c] = emb[sp * CC + c];
            g_S[e * CC + c] = 0.f;
        }
        g_coulN[e] = 0.f;
        if (e == 0) out[0] = 0.f;
    }
    atomicAdd(&g_csrc[src[e]], 1);
    atomicAdd(&g_cdst[dst[e]], 1);
}

// ---------------- scan ----------------
__global__ void k_scan() {
    const int T = 1024, PER = NN / 1024;
    __shared__ int part[T];
    int t = threadIdx.x;
    int base = t * PER;
    if (blockIdx.x == 0) {
        int loc[PER], locp[PER];
        int s = 0;
#pragma unroll
        for (int i = 0; i < PER; i++) {
            loc[i] = g_csrc[base + i];
            g_csrc[base + i] = 0;
            locp[i] = (loc[i] + 1) & ~1;
            s += locp[i];
        }
        part[t] = s;
        __syncthreads();
        for (int off = 1; off < T; off <<= 1) {
            int v = (t >= off) ? part[t - off] : 0;
            __syncthreads();
            part[t] += v;
            __syncthreads();
        }
        int run = part[t] - s;
#pragma unroll
        for (int i = 0; i < PER; i++) {
            g_cursrc[base + i] = run;
            if (loc[i] & 1) g_srcS[run + loc[i]] = base + i;
            run += locp[i];
        }
    } else {
        int loc[PER];
        int s = 0;
#pragma unroll
        for (int i = 0; i < PER; i++) {
            loc[i] = g_cdst[base + i];
            g_cdst[base + i] = 0;
            s += loc[i];
        }
        part[t] = s;
        __syncthreads();
        for (int off = 1; off < T; off <<= 1) {
            int v = (t >= off) ? part[t - off] : 0;
            __syncthreads();
            part[t] += v;
            __syncthreads();
        }
        int run = part[t] - s;
#pragma unroll
        for (int i = 0; i < PER; i++) {
            g_rdst[base + i] = run;
            g_curdst[base + i] = run;
            run += loc[i];
        }
        if (t == T - 1) g_rdst[NN] = run;
    }
}

// ---------------- node-prep helpers ----------------
#define NLT 256                 // node-layer threads
#define NLN 32                  // nodes per tile
#define NTILES (NN / NLN)       // 1024
#define NGRID0 592              // prep0: 4 blocks/SM
#define NGRID1 444              // node_layer: 3 blocks/SM
#define SCB 2048                // scatter blocks in fused k_prep

__device__ __forceinline__ void load_node_weights(
    int tid, const float* __restrict__ b3,
    const float* __restrict__ W1n, const float* __restrict__ b1n,
    const float* __restrict__ Wq, const float* __restrict__ Wself,
    float* sW1, float* sWq, float* sb3, float* sb1, float* sWself) {
    for (int idx = tid; idx < CC * MIDD; idx += NLT) sW1[idx] = W1n[idx];
    if (Wq && tid < HH * CC) sWq[(tid >> 4) * 18 + (tid & 15)] = Wq[tid];
    { int o = tid >> 4, i = tid & 15; sb3[o * 18 + i] = b3[tid]; }
    if (tid < MIDD) sb1[tid] = b1n[tid];
    if (Wself && tid < CC * CC) sWself[(tid >> 4) * 18 + (tid & 15)] = Wself[tid];
}

// per-thread W3 slice: thread tid owns (m = (tid>>5)*4 + (tid&3), op = (tid>>2)&7)
__device__ __forceinline__ void load_w3_regs(int tid, const float* __restrict__ W3,
                                             ull wA[8], ull wB[8]) {
    int mq = tid >> 5, op = (tid >> 2) & 7, r = tid & 3;
    int m = mq * 4 + r;
    const ulonglong2* pa = (const ulonglong2*)(W3 + m * 256 + op * 16);
    const ulonglong2* pb = (const ulonglong2*)(W3 + m * 256 + (op + 8) * 16);
#pragma unroll
    for (int t = 0; t < 4; t++) {
        ulonglong2 va = pa[t];
        wA[2 * t] = va.x; wA[2 * t + 1] = va.y;
        ulonglong2 vb = pb[t];
        wB[2 * t] = vb.x; wB[2 * t + 1] = vb.y;
    }
}

// phase B: P for all NLN nodes of the tile; write offset = tid*2 (matches k_edge layout)
__device__ __forceinline__ void prep_P_reg(int n0, int tid,
                                           const ull wA[8], const ull wB[8],
                                           const float* sXn) {
#pragma unroll 2
    for (int nloc = 0; nloc < NLN; nloc++) {
        const ulonglong2* xp = (const ulonglong2*)&sXn[nloc * CC];
        ulonglong2 x01 = xp[0], x23 = xp[1], x45 = xp[2], x67 = xp[3];
        ull aA = 0ULL, aB = 0ULL;
        aA = fma2(x01.x, wA[0], aA); aB = fma2(x01.x, wB[0], aB);
        aA = fma2(x01.y, wA[1], aA); aB = fma2(x01.y, wB[1], aB);
        aA = fma2(x23.x, wA[2], aA); aB = fma2(x23.x, wB[2], aB);
        aA = fma2(x23.y, wA[3], aA); aB = fma2(x23.y, wB[3], aB);
        aA = fma2(x45.x, wA[4], aA); aB = fma2(x45.x, wB[4], aB);
        aA = fma2(x45.y, wA[5], aA); aB = fma2(x45.y, wB[5], aB);
        aA = fma2(x67.x, wA[6], aA); aB = fma2(x67.x, wB[6], aB);
        aA = fma2(x67.y, wA[7], aA); aB = fma2(x67.y, wB[7], aB);
        float la, ha, lb, hb;
        unpack2(aA, la, ha);
        unpack2(aB, lb, hb);
        *(ull*)(g_P + (size_t)(n0 + nloc) * 512 + tid * 2) = pack2(la + ha, lb + hb);
    }
}

// phase A: q/u/PB/feats for node n; lane j owns o-pair (j, j+8)
__device__ __forceinline__ void node_prep_a(
    int n, int nloc, int j, bool do_q, bool do_feats,
    const float* sW1, const float* sWq,
    const float* sb3, const float* sb1, const float* sWself,
    const float* sXn, const float* sSn) {
    ull xx[8];
#pragma unroll
    for (int ip = 0; ip < 8; ip++)
        xx[ip] = *(const ull*)&sXn[nloc * CC + 2 * ip];

    if (do_q) {
        float qa = 0.f;
#pragma unroll
        for (int c = 0; c < CC; c++) qa = fmaf(sWq[j * 18 + c], sXn[nloc * CC + c], qa);
        g_q[n * HH + j] = qa;
    }
    {
        float u0 = sb1[j], u1 = sb1[j + 8], u2 = sb1[j + 16], u3 = sb1[j + 24];
#pragma unroll
        for (int c = 0; c < CC; c++) {
            float sv = sSn[nloc * CC + c];
            u0 = fmaf(sv, sW1[c * MIDD + j], u0);
            u1 = fmaf(sv, sW1[c * MIDD + j + 8], u1);
            u2 = fmaf(sv, sW1[c * MIDD + j + 16], u2);
            u3 = fmaf(sv, sW1[c * MIDD + j + 24], u3);
        }
        g_u[n * MIDD + j] = u0;
        g_u[n * MIDD + j + 8] = u1;
        g_u[n * MIDD + j + 16] = u2;
        g_u[n * MIDD + j + 24] = u3;
    }
    {
        ull a0 = 0ULL, a1 = 0ULL;
#pragma unroll
        for (int ip = 0; ip < 8; ip++) {
            a0 = fma2(xx[ip], *(const ull*)&sb3[j * 18 + 2 * ip], a0);
            a1 = fma2(xx[ip], *(const ull*)&sb3[(j + 8) * 18 + 2 * ip], a1);
        }
        float l0, h0, l1, h1;
        unpack2(a0, l0, h0);
        unpack2(a1, l1, h1);
        g_PB[n * CC + j * 2] = l0 + h0;
        g_PB[n * CC + j * 2 + 1] = l1 + h1;
    }
    if (do_feats) {
        ull a0 = 0ULL, a1 = 0ULL;
#pragma unroll
        for (int ip = 0; ip < 8; ip++) {
            a0 = fma2(xx[ip], *(const ull*)&sWself[j * 18 + 2 * ip], a0);
            a1 = fma2(xx[ip], *(const ull*)&sWself[(j + 8) * 18 + 2 * ip], a1);
        }
        float l0, h0, l1, h1;
        unpack2(a0, l0, h0);
        unpack2(a1, l1, h1);
        g_feats[n * CC + j] = l0 + h0;
        g_feats[n * CC + 8 + j] = l1 + h1;
    }
}

// ---------------- fused prep: blocks [0,SCB) scatter; [SCB, SCB+NGRID0) layer-0 node prep ----------------
__global__ void __launch_bounds__(NLT, 4)
k_prep(const int* __restrict__ src, const int* __restrict__ dst,
       const float* __restrict__ rel_pos, const int* __restrict__ species,
       const float* __restrict__ Wq, const float* __restrict__ W3,
       const float* __restrict__ b3, const float* __restrict__ W1n,
       const float* __restrict__ b1n) {
    __shared__ __align__(16) float sW1[CC * MIDD];
    __shared__ __align__(16) float sWq[HH * 18];
    __shared__ __align__(16) float sb3[16 * 18];
    __shared__ __align__(16) float sb1[MIDD];
    __shared__ __align__(16) float sXn[NLN * CC];
    __shared__ __align__(16) float sSn[NLN * CC];
    int tid = threadIdx.x;

    if (blockIdx.x < SCB) {
        int e = blockIdx.x * 256 + tid;
        int s = src[e], d = dst[e];
        float px = rel_pos[e * 3 + 0], py = rel_pos[e * 3 + 1], pz = rel_pos[e * 3 + 2];
        float dist = sqrtf(px * px + py * py + pz * pz);
        float xc = dist / CUTOFFF;
        bool in_cut = dist < CUTOFFF;
        float x2 = in_cut ? fminf(xc * xc, 1.f - 1e-6f) : 0.f;
        float scale = in_cut ? expf(3.f - 3.f / (1.f - x2)) : 0.f;

        int ps = atomicAdd(&g_cursrc[s], 1);
        int pd = atomicAdd(&g_curdst[d], 1);
        g_srcS[ps] = s;
        g_distS[ps] = dist;
        g_scaleS[ps] = scale;
        g_es[pd] = make_int2(ps, __float_as_int(scale));

        float Zu = (float)species[s];
        float Zv = (float)species[d];
        float raw = KCOULF * Zu * Zv / (2.f * dist);
        float au = 0.8854f * 0.529f / (__powf(Zu, 0.23f) + __powf(Zv, 0.23f));
        float xx = dist / au;
        float screen = 0.1818f * __expf(-3.2f * xx) + 0.5099f * __expf(-0.9423f * xx)
                     + 0.2802f * __expf(-0.4028f * xx) + 0.02817f * __expf(-0.2016f * xx);
        float contrib = raw * screen * scale;
        if (contrib != 0.f) atomicAdd(&g_coulN[d], contrib);
        return;
    }

    int blk = blockIdx.x - SCB;
    ull wA[8], wB[8];
    load_w3_regs(tid, W3, wA, wB);
    load_node_weights(tid, b3, W1n, b1n, Wq, nullptr, sW1, sWq, sb3, sb1, nullptr);
    int nloc = tid >> 3, j = tid & 7;
    for (int tile = blk; tile < NTILES; tile += NGRID0) {
        __syncthreads();
        int n = tile * NLN + nloc;
        sXn[nloc * CC + j] = g_x[n * CC + j];
        sXn[nloc * CC + 8 + j] = g_x[n * CC + 8 + j];
        sSn[nloc * CC + j] = 0.f;
        sSn[nloc * CC + 8 + j] = 0.f;
        __syncthreads();
        node_prep_a(n, nloc, j, true, false, sW1, sWq, sb3, sb1, nullptr, sXn, sSn);
        prep_P_reg(tile * NLN, tid, wA, wB, sXn);
    }
}

// ---------------- node layer: persistent tiles, online-softmax + Wproj + prep ----------------
__global__ void __launch_bounds__(NLT, 3)
k_node_layer(int mode,
             const float* __restrict__ Wproj,
             const float* __restrict__ Wq,
             const float* __restrict__ W3,
             const float* __restrict__ b3,
             const float* __restrict__ W1n,
             const float* __restrict__ b1n,
             const float* __restrict__ Wself) {
    __shared__ __align__(16) float sW1[CC * MIDD];
    __shared__ __align__(16) float sWq[HH * 18];
    __shared__ __align__(16) float sWproj[CC * 25];
    __shared__ __align__(16) float sb3[16 * 18];
    __shared__ __align__(16) float sb1[MIDD];
    __shared__ __align__(16) float sWself[16 * 18];
    __shared__ __align__(16) float sAgg[NLN * HH];
    __shared__ __align__(16) float sXold[NLN * CC];
    __shared__ __align__(16) float sXn[NLN * CC];
    __shared__ __align__(16) float sSn[NLN * CC];

    int tid = threadIdx.x;
    int nloc = tid >> 3, j = tid & 7;

    ull wA[8], wB[8];
    load_w3_regs(tid, W3, wA, wB);
    load_node_weights(tid, b3, W1n, b1n,
                      mode != 2 ? Wq : nullptr,
                      mode == 2 ? Wself : nullptr,
                      sW1, sWq, sb3, sb1, sWself);
    for (int idx = tid; idx < CC * 24; idx += NLT)
        sWproj[(idx / 24) * 25 + (idx % 24)] = Wproj[idx];

    for (int tile = blockIdx.x; tile < NTILES; tile += NGRID1) {
        __syncthreads();
        int n = tile * NLN + nloc;
        {
            int beg = g_rdst[n], end = g_rdst[n + 1];
            float qj = g_q[n * HH + j];
            float m = -INFINITY, num = 0.f, den = 0.f;
#pragma unroll 2
            for (int i = beg; i < end; i++) {
                int2 es = g_es[i];
                float2 vk = *(const float2*)(g_vk + (size_t)es.x * CC + j * 2);
                float sc = __int_as_float(es.y);
                float l = vk.y * qj;
                float mn = fmaxf(m, l);
                float corr = __expf(m - mn);
                float p = sc * __expf(l - mn);
                den = den * corr + p;
                num = fmaf(num, corr, p * vk.x);
                m = mn;
            }
            sAgg[nloc * HH + j] = num / fmaxf(den, 1e-20f);
            sXold[nloc * CC + j] = g_x[n * CC + j];
            sXold[nloc * CC + 8 + j] = g_x[n * CC + 8 + j];
            __syncthreads();
            float xn0 = 0.f, xn1 = 0.f;
#pragma unroll
            for (int k = 0; k < 8; k++) {
                float a = sAgg[nloc * HH + k];
                xn0 = fmaf(sWproj[j * 25 + k], a, xn0);
                xn1 = fmaf(sWproj[(j + 8) * 25 + k], a, xn1);
            }
#pragma unroll
            for (int k = 0; k < CC; k++) {
                float xo = sXold[nloc * CC + k];
                xn0 = fmaf(sWproj[j * 25 + 8 + k], xo, xn0);
                xn1 = fmaf(sWproj[(j + 8) * 25 + 8 + k], xo, xn1);
            }
            float s0 = g_S[n * CC + j] + xn0;
            float s1 = g_S[n * CC + 8 + j] + xn1;
            g_x[n * CC + j] = xn0;     g_x[n * CC + 8 + j] = xn1;
            g_S[n * CC + j] = s0;      g_S[n * CC + 8 + j] = s1;
            sXn[nloc * CC + j] = xn0;  sXn[nloc * CC + 8 + j] = xn1;
            sSn[nloc * CC + j] = s0;   sSn[nloc * CC + 8 + j] = s1;
            __syncthreads();
        }
        node_prep_a(n, nloc, j, mode != 2, mode == 2,
                    sW1, sWq, sb3, sb1, sWself, sXn, sSn);
        prep_P_reg(tile * NLN, tid, wA, wB, sXn);
    }
}

// ---------------- edge kernel (R8 best, unchanged) ----------------
__global__ void __launch_bounds__(128, 4)
k_edge(const float* __restrict__ W1, const float* __restrict__ W2,
       const float* __restrict__ b2) {
    __shared__ __align__(16) ull sW2p[512];
    __shared__ float sw15[MIDD];
    __shared__ __align__(16) ull sB2p[16];
    __shared__ __align__(16) float sSt[4][32 * 36];
    int tid = threadIdx.x;
    for (int i = tid; i < 512; i += 128) sW2p[i] = ((const ull*)W2)[i];
    if (tid < MIDD) sw15[tid] = W1[15 * MIDD + tid];
    if (tid < 16) sB2p[tid] = ((const ull*)b2)[tid];
    __syncthreads();

    int t = blockIdx.x * 128 + tid;
    int e0 = 2 * t;
    int s = g_srcS[e0];
    float2 dd = *(const float2*)(g_distS + e0);
    float2 sc = *(const float2*)(g_scaleS + e0);
    float da = dd.x, db = dd.y;
    float bsa = Y0F * sc.x, bsb = Y0F * sc.y;

    float u[MIDD];
    {
        const float4* up = (const float4*)(g_u + (size_t)s * MIDD);
#pragma unroll
        for (int k = 0; k < 8; k++) {
            float4 v = up[k];
            u[4 * k] = v.x; u[4 * k + 1] = v.y; u[4 * k + 2] = v.z; u[4 * k + 3] = v.w;
        }
    }

    ull acca[16], accb[16];
#pragma unroll
    for (int jp = 0; jp < 16; jp++) { acca[jp] = sB2p[jp]; accb[jp] = sB2p[jp]; }
#pragma unroll
    for (int i2 = 0; i2 < MIDD; i2++) {
        float w15v = sw15[i2];
        float ha = fmaxf(fmaf(da, w15v, u[i2]), 0.f);
        float hb = fmaxf(fmaf(db, w15v, u[i2]), 0.f);
        ull xa = pack2(ha, ha);
        ull xb = pack2(hb, hb);
#pragma unroll
        for (int jq = 0; jq < 8; jq++) {
            ulonglong2 w = *(const ulonglong2*)&sW2p[i2 * 16 + jq * 2];
            acca[2 * jq]     = fma2(xa, w.x, acca[2 * jq]);
            acca[2 * jq + 1] = fma2(xa, w.y, acca[2 * jq + 1]);
            accb[2 * jq]     = fma2(xb, w.x, accb[2 * jq]);
            accb[2 * jq + 1] = fma2(xb, w.y, accb[2 * jq + 1]);
        }
    }
    float h2a[MIDD], h2b[MIDD];
#pragma unroll
    for (int jp = 0; jp < 16; jp++) {
        float lo, hi;
        unpack2(acca[jp], lo, hi);
        h2a[2 * jp] = fmaxf(lo, 0.f); h2a[2 * jp + 1] = fmaxf(hi, 0.f);
        unpack2(accb[jp], lo, hi);
        h2b[2 * jp] = fmaxf(lo, 0.f); h2b[2 * jp + 1] = fmaxf(hi, 0.f);
    }

    ull ka[8], kb[8];
    {
        const ulonglong2* pbp = (const ulonglong2*)(g_PB + (size_t)s * CC);
#pragma unroll
        for (int q = 0; q < 4; q++) {
            ulonglong2 pb = pbp[q];
            ka[2 * q] = pb.x; ka[2 * q + 1] = pb.y;
            kb[2 * q] = pb.x; kb[2 * q + 1] = pb.y;
        }
    }
    const ull* Pp = (const ull*)(g_P + (size_t)s * 512);
#pragma unroll
    for (int mq = 0; mq < 8; mq++) {
        ull xa0 = pack2(h2a[mq * 4 + 0], h2a[mq * 4 + 0]);
        ull xa1 = pack2(h2a[mq * 4 + 1], h2a[mq * 4 + 1]);
        ull xa2 = pack2(h2a[mq * 4 + 2], h2a[mq * 4 + 2]);
        ull xa3 = pack2(h2a[mq * 4 + 3], h2a[mq * 4 + 3]);
        ull xb0 = pack2(h2b[mq * 4 + 0], h2b[mq * 4 + 0]);
        ull xb1 = pack2(h2b[mq * 4 + 1], h2b[mq * 4 + 1]);
        ull xb2 = pack2(h2b[mq * 4 + 2], h2b[mq * 4 + 2]);
        ull xb3 = pack2(h2b[mq * 4 + 3], h2b[mq * 4 + 3]);
#pragma unroll
        for (int j = 0; j < 8; j++) {
            ulonglong2 pA = *(const ulonglong2*)(Pp + mq * 32 + j * 4);
            ulonglong2 pB = *(const ulonglong2*)(Pp + mq * 32 + j * 4 + 2);
            ka[j] = fma2(xa0, pA.x, ka[j]);
            ka[j] = fma2(xa1, pA.y, ka[j]);
            ka[j] = fma2(xa2, pB.x, ka[j]);
            ka[j] = fma2(xa3, pB.y, ka[j]);
            kb[j] = fma2(xb0, pA.x, kb[j]);
            kb[j] = fma2(xb1, pA.y, kb[j]);
            kb[j] = fma2(xb2, pB.x, kb[j]);
            kb[j] = fma2(xb3, pB.y, kb[j]);
        }
    }

    int lane = tid & 31, w = tid >> 5;
    float* st = sSt[w];
#pragma unroll
    for (int q = 0; q < 4; q++) {
        float a0, a1, a2, a3;
        unpack2(ka[2 * q], a0, a1);
        unpack2(ka[2 * q + 1], a2, a3);
        *(float4*)&st[lane * 36 + q * 4] = make_float4(a0 * bsa, a1 * bsa, a2 * bsa, a3 * bsa);
    }
#pragma unroll
    for (int q = 0; q < 4; q++) {
        float a0, a1, a2, a3;
        unpack2(kb[2 * q], a0, a1);
        unpack2(kb[2 * q + 1], a2, a3);
        *(float4*)&st[lane * 36 + 16 + q * 4] = make_float4(a0 * bsb, a1 * bsb, a2 * bsb, a3 * bsb);
    }
    __syncwarp();
    float4* gbase = (float4*)(g_vk + (size_t)(blockIdx.x * 256 + w * 64) * CC);
#pragma unroll
    for (int g = 0; g < 8; g++) {
        int f = g * 32 + lane;
        int owner = f >> 3, q = f & 7;
        gbase[f] = *(const float4*)&st[owner * 36 + q * 4];
    }
}

// ---------------- final ----------------
__device__ __forceinline__ float siluf(float x) { return x / (1.f + __expf(-x)); }

__global__ void k_final(const int* __restrict__ species, const float* __restrict__ emb,
                        const float* __restrict__ W1, const float* __restrict__ b1,
                        const float* __restrict__ W2, const float* __restrict__ b2,
                        const float* __restrict__ W3, const float* __restrict__ b3,
                        float* __restrict__ out) {
    __shared__ float sFeat[16 * 17];
    __shared__ float sEmb[16 * 17];
    __shared__ float sH[16 * 17];
    __shared__ float sRed[16];
    int tid = threadIdx.x;
    int nloc = tid >> 4, o = tid & 15;
    int n = blockIdx.x * 16 + nloc;
    int beg = g_rdst[n], end = g_rdst[n + 1];
    int o2 = (o < 8) ? o * 2 : (o - 8) * 2 + 1;
    float f = g_feats[n * CC + o];
    for (int i = beg; i < end; i++) {
        int ei = g_es[i].x;
        f += g_vk[(size_t)ei * CC + o2];
    }
    sFeat[nloc * 17 + o] = f;
    int sp = species[n] - 1;
    sEmb[nloc * 17 + o] = emb[sp * CC + o];
    __syncthreads();

    float h1 = b1[o];
#pragma unroll
    for (int k = 0; k < CC; k++) h1 = fmaf(sEmb[nloc * 17 + k], W1[k * CC + o], h1);
#pragma unroll
    for (int k = 0; k < CC; k++) h1 = fmaf(sFeat[nloc * 17 + k], W1[(CC + k) * CC + o], h1);
    sH[nloc * 17 + o] = siluf(h1);
    __syncthreads();

    float h2 = b2[o];
#pragma unroll
    for (int k = 0; k < CC; k++) h2 = fmaf(sH[nloc * 17 + k], W2[k * CC + o], h2);
    h2 = siluf(h2);

    float part = h2 * W3[o];
#pragma unroll
    for (int off = 8; off > 0; off >>= 1)
        part += __shfl_down_sync(0xffffffffu, part, off, 16);
    if (o == 0) sRed[nloc] = part + b3[0] + g_coulN[n];
    __syncthreads();
    if (tid == 0) {
        float acc = 0.f;
#pragma unroll
        for (int k = 0; k < 16; k++) acc += sRed[k];
        atomicAdd(out, acc);
    }
}

// ---------------- host launch ----------------
extern "C" void kernel_launch(void* const* d_in, const int* in_sizes, int n_in,
                              void* d_out, int out_size) {
    const int* species  = (const int*)d_in[0];
    const int* src      = (const int*)d_in[1];
    const int* dst      = (const int*)d_in[2];
    const float* rel_pos = (const float*)d_in[3];
    const float* emb    = (const float*)d_in[4];
    const float* kv_W1  = (const float*)d_in[5];
    const float* kv_b1  = (const float*)d_in[6];
    const float* kv_W2  = (const float*)d_in[7];
    const float* kv_b2  = (const float*)d_in[8];
    const float* kv_W3  = (const float*)d_in[9];
    const float* kv_b3  = (const float*)d_in[10];
    const float* Wq     = (const float*)d_in[11];
    const float* Wproj  = (const float*)d_in[12];
    const float* fin_W1 = (const float*)d_in[13];
    const float* fin_b1 = (const float*)d_in[14];
    const float* fin_W2 = (const float*)d_in[15];
    const float* fin_b2 = (const float*)d_in[16];
    const float* fin_W3 = (const float*)d_in[17];
    const float* fin_b3 = (const float*)d_in[18];
    const float* Wself  = (const float*)d_in[19];
    const float* mlp_W1 = (const float*)d_in[20];
    const float* mlp_b1 = (const float*)d_in[21];
    const float* mlp_W2 = (const float*)d_in[22];
    const float* mlp_b2 = (const float*)d_in[23];
    const float* mlp_W3 = (const float*)d_in[24];
    const float* mlp_b3 = (const float*)d_in[25];
    float* out = (float*)d_out;

    const int EB = EE / 256;         // 2048
    const int EDGB = EENP / 256;     // 2176

    k_init<<<EB, 256>>>(species, emb, out, src, dst);
    k_scan<<<2, 1024>>>();
    k_prep<<<SCB + NGRID0, NLT>>>(src, dst, rel_pos, species,
                                  Wq, kv_W3, kv_b3, kv_W1, kv_b1);

    for (int l = 0; l < 4; l++) {
        k_edge<<<EDGB, 128>>>(kv_W1 + (size_t)l * CC * MIDD,
                              kv_W2 + (size_t)l * MIDD * MIDD,
                              kv_b2 + (size_t)l * MIDD);
        if (l < 3) {
            k_node_layer<<<NGRID1, NLT>>>(1,
                Wproj + (size_t)l * CC * 24,
                Wq + (size_t)(l + 1) * HH * CC,
                kv_W3 + (size_t)(l + 1) * MIDD * 256,
                kv_b3 + (size_t)(l + 1) * 256,
                kv_W1 + (size_t)(l + 1) * CC * MIDD,
                kv_b1 + (size_t)(l + 1) * MIDD,
                nullptr);
        } else {
            k_node_layer<<<NGRID1, NLT>>>(2,
                Wproj + (size_t)l * CC * 24,
                nullptr,
                fin_W3, fin_b3, fin_W1, fin_b1, Wself);
        }
    }
    k_edge<<<EDGB, 128>>>(fin_W1, fin_W2, fin_b2);
    k_final<<<NN / 16, 256>>>(species, emb, mlp_W1, mlp_b1, mlp_W2, mlp_b2,
                              mlp_W3, mlp_b3, out);
}

// round 15
// speedup vs baseline: 1.5913x; 1.0687x over previous
#include <cuda_runtime.h>
#include <math.h>

#define NN 32768
#define EE 524288
#define EENP (EE + NN)          // padded src-sorted capacity (557056 = 256*2176)
#define CC 16
#define MIDD 32
#define HH 8
#define Y0F 0.28209479177387814f
#define CUTOFFF 4.6f
#define KCOULF 0.529f

typedef unsigned long long ull;

// ---------------- device scratch ----------------
__device__ __align__(16) float g_x[NN * CC];
__device__ __align__(16) float g_S[NN * CC];
__device__ __align__(16) float g_q[NN * HH];
__device__ __align__(16) float g_u[NN * MIDD];
__device__ __align__(16) float g_P[NN * 512];     // pair-interleaved
__device__ __align__(16) float g_PB[NN * CC];     // pair-interleaved
__device__ __align__(16) float g_feats[NN * CC];
__device__ __align__(16) float g_vk[(size_t)EENP * CC]; // padded src-sorted {val,key}
__device__ float g_distS[EENP];
__device__ float g_scaleS[EENP];
__device__ __align__(8) int2 g_es[EE];            // dst-order: {src-order idx, scale bits}
__device__ float g_coulN[NN];
__device__ int g_srcS[EENP];
__device__ int g_csrc[NN], g_cdst[NN];
__device__ int g_rdst[NN + 1];
__device__ int g_cursrc[NN], g_curdst[NN];

// ---------------- f32x2 helpers ----------------
__device__ __forceinline__ ull pack2(float a, float b) {
    ull r;
    asm("mov.b64 %0, {%1, %2};" : "=l"(r) : "f"(a), "f"(b));
    return r;
}
__device__ __forceinline__ ull fma2(ull a, ull b, ull c) {
    ull d;
    asm("fma.rn.f32x2 %0, %1, %2, %3;" : "=l"(d) : "l"(a), "l"(b), "l"(c));
    return d;
}
__device__ __forceinline__ void unpack2(ull v, float& lo, float& hi) {
    asm("mov.b64 {%0, %1}, %2;" : "=f"(lo), "=f"(hi) : "l"(v));
}

// ---------------- init ----------------
__global__ void k_init(const int* __restrict__ species, const float* __restrict__ emb,
                       float* __restrict__ out,
                       const int* __restrict__ src, const int* __restrict__ dst) {
    int e = blockIdx.x * 256 + threadIdx.x;
    if (e < NN) {
        int sp = species[e] - 1;
#pragma unroll
        for (int c = 0; c < CC; c++) {
            g_x[e * CC + c] = emb[sp * CC + c];
            g_S[e * CC + c] = 0.f;
        }
        g_coulN[e] = 0.f;
        if (e == 0) out[0] = 0.f;
    }
    atomicAdd(&g_csrc[src[e]], 1);
    atomicAdd(&g_cdst[dst[e]], 1);
}

// ---------------- scan ----------------
__global__ void k_scan() {
    const int T = 1024, PER = NN / 1024;
    __shared__ int part[T];
    int t = threadIdx.x;
    int base = t * PER;
    if (blockIdx.x == 0) {
        int loc[PER], locp[PER];
        int s = 0;
#pragma unroll
        for (int i = 0; i < PER; i++) {
            loc[i] = g_csrc[base + i];
            g_csrc[base + i] = 0;
            locp[i] = (loc[i] + 1) & ~1;
            s += locp[i];
        }
        part[t] = s;
        __syncthreads();
        for (int off = 1; off < T; off <<= 1) {
            int v = (t >= off) ? part[t - off] : 0;
            __syncthreads();
            part[t] += v;
            __syncthreads();
        }
        int run = part[t] - s;
#pragma unroll
        for (int i = 0; i < PER; i++) {
            g_cursrc[base + i] = run;
            if (loc[i] & 1) g_srcS[run + loc[i]] = base + i;
            run += locp[i];
        }
    } else {
        int loc[PER];
        int s = 0;
#pragma unroll
        for (int i = 0; i < PER; i++) {
            loc[i] = g_cdst[base + i];
            g_cdst[base + i] = 0;
            s += loc[i];
        }
        part[t] = s;
        __syncthreads();
        for (int off = 1; off < T; off <<= 1) {
            int v = (t >= off) ? part[t - off] : 0;
            __syncthreads();
            part[t] += v;
            __syncthreads();
        }
        int run = part[t] - s;
#pragma unroll
        for (int i = 0; i < PER; i++) {
            g_rdst[base + i] = run;
            g_curdst[base + i] = run;
            run += loc[i];
        }
        if (t == T - 1) g_rdst[NN] = run;
    }
}

// ---------------- node-prep helpers ----------------
#define NLT 256                 // node-layer threads
#define NLN 32                  // nodes per tile
#define NTILES (NN / NLN)       // 1024
#define NGRID0 592              // prep0: 4 blocks/SM
#define NGRID1 444              // node_layer: 3 blocks/SM
#define SCB 2048                // scatter blocks in fused k_prep

__device__ __forceinline__ void load_node_weights(
    int tid, const float* __restrict__ b3,
    const float* __restrict__ W1n, const float* __restrict__ b1n,
    const float* __restrict__ Wq, const float* __restrict__ Wself,
    float* sW1, float* sWq, float* sb3, float* sb1, float* sWself) {
    for (int idx = tid; idx < CC * MIDD; idx += NLT) sW1[idx] = W1n[idx];
    if (Wq && tid < HH * CC) sWq[(tid >> 4) * 18 + (tid & 15)] = Wq[tid];
    { int o = tid >> 4, i = tid & 15; sb3[o * 18 + i] = b3[tid]; }
    if (tid < MIDD) sb1[tid] = b1n[tid];
    if (Wself && tid < CC * CC) sWself[(tid >> 4) * 18 + (tid & 15)] = Wself[tid];
}

// per-thread W3 slice: thread tid owns (m = (tid>>5)*4 + (tid&3), op = (tid>>2)&7)
__device__ __forceinline__ void load_w3_regs(int tid, const float* __restrict__ W3,
                                             ull wA[8], ull wB[8]) {
    int mq = tid >> 5, op = (tid >> 2) & 7, r = tid & 3;
    int m = mq * 4 + r;
    const ulonglong2* pa = (const ulonglong2*)(W3 + m * 256 + op * 16);
    const ulonglong2* pb = (const ulonglong2*)(W3 + m * 256 + (op + 8) * 16);
#pragma unroll
    for (int t = 0; t < 4; t++) {
        ulonglong2 va = pa[t];
        wA[2 * t] = va.x; wA[2 * t + 1] = va.y;
        ulonglong2 vb = pb[t];
        wB[2 * t] = vb.x; wB[2 * t + 1] = vb.y;
    }
}

// phase B: P for all NLN nodes of the tile; write offset = tid*2 (matches k_edge layout)
__device__ __forceinline__ void prep_P_reg(int n0, int tid,
                                           const ull wA[8], const ull wB[8],
                                           const float* sXn) {
#pragma unroll 2
    for (int nloc = 0; nloc < NLN; nloc++) {
        const ulonglong2* xp = (const ulonglong2*)&sXn[nloc * CC];
        ulonglong2 x01 = xp[0], x23 = xp[1], x45 = xp[2], x67 = xp[3];
        ull aA = 0ULL, aB = 0ULL;
        aA = fma2(x01.x, wA[0], aA); aB = fma2(x01.x, wB[0], aB);
        aA = fma2(x01.y, wA[1], aA); aB = fma2(x01.y, wB[1], aB);
        aA = fma2(x23.x, wA[2], aA); aB = fma2(x23.x, wB[2], aB);
        aA = fma2(x23.y, wA[3], aA); aB = fma2(x23.y, wB[3], aB);
        aA = fma2(x45.x, wA[4], aA); aB = fma2(x45.x, wB[4], aB);
        aA = fma2(x45.y, wA[5], aA); aB = fma2(x45.y, wB[5], aB);
        aA = fma2(x67.x, wA[6], aA); aB = fma2(x67.x, wB[6], aB);
        aA = fma2(x67.y, wA[7], aA); aB = fma2(x67.y, wB[7], aB);
        float la, ha, lb, hb;
        unpack2(aA, la, ha);
        unpack2(aB, lb, hb);
        *(ull*)(g_P + (size_t)(n0 + nloc) * 512 + tid * 2) = pack2(la + ha, lb + hb);
    }
}

// phase A: q/u/PB/feats for node n; lane j owns o-pair (j, j+8)
__device__ __forceinline__ void node_prep_a(
    int n, int nloc, int j, bool do_q, bool do_feats,
    const float* sW1, const float* sWq,
    const float* sb3, const float* sb1, const float* sWself,
    const float* sXn, const float* sSn) {
    ull xx[8];
#pragma unroll
    for (int ip = 0; ip < 8; ip++)
        xx[ip] = *(const ull*)&sXn[nloc * CC + 2 * ip];

    if (do_q) {
        float qa = 0.f;
#pragma unroll
        for (int c = 0; c < CC; c++) qa = fmaf(sWq[j * 18 + c], sXn[nloc * CC + c], qa);
        g_q[n * HH + j] = qa;
    }
    {
        float u0 = sb1[j], u1 = sb1[j + 8], u2 = sb1[j + 16], u3 = sb1[j + 24];
#pragma unroll
        for (int c = 0; c < CC; c++) {
            float sv = sSn[nloc * CC + c];
            u0 = fmaf(sv, sW1[c * MIDD + j], u0);
            u1 = fmaf(sv, sW1[c * MIDD + j + 8], u1);
            u2 = fmaf(sv, sW1[c * MIDD + j + 16], u2);
            u3 = fmaf(sv, sW1[c * MIDD + j + 24], u3);
        }
        g_u[n * MIDD + j] = u0;
        g_u[n * MIDD + j + 8] = u1;
        g_u[n * MIDD + j + 16] = u2;
        g_u[n * MIDD + j + 24] = u3;
    }
    {
        ull a0 = 0ULL, a1 = 0ULL;
#pragma unroll
        for (int ip = 0; ip < 8; ip++) {
            a0 = fma2(xx[ip], *(const ull*)&sb3[j * 18 + 2 * ip], a0);
            a1 = fma2(xx[ip], *(const ull*)&sb3[(j + 8) * 18 + 2 * ip], a1);
        }
        float l0, h0, l1, h1;
        unpack2(a0, l0, h0);
        unpack2(a1, l1, h1);
        g_PB[n * CC + j * 2] = l0 + h0;
        g_PB[n * CC + j * 2 + 1] = l1 + h1;
    }
    if (do_feats) {
        ull a0 = 0ULL, a1 = 0ULL;
#pragma unroll
        for (int ip = 0; ip < 8; ip++) {
            a0 = fma2(xx[ip], *(const ull*)&sWself[j * 18 + 2 * ip], a0);
            a1 = fma2(xx[ip], *(const ull*)&sWself[(j + 8) * 18 + 2 * ip], a1);
        }
        float l0, h0, l1, h1;
        unpack2(a0, l0, h0);
        unpack2(a1, l1, h1);
        g_feats[n * CC + j] = l0 + h0;
        g_feats[n * CC + 8 + j] = l1 + h1;
    }
}

// ---------------- fused prep: blocks [0,SCB) scatter; [SCB, SCB+NGRID0) layer-0 node prep ----------------
__global__ void __launch_bounds__(NLT, 4)
k_prep(const int* __restrict__ src, const int* __restrict__ dst,
       const float* __restrict__ rel_pos, const int* __restrict__ species,
       const float* __restrict__ Wq, const float* __restrict__ W3,
       const float* __restrict__ b3, const float* __restrict__ W1n,
       const float* __restrict__ b1n) {
    __shared__ __align__(16) float sW1[CC * MIDD];
    __shared__ __align__(16) float sWq[HH * 18];
    __shared__ __align__(16) float sb3[16 * 18];
    __shared__ __align__(16) float sb1[MIDD];
    __shared__ __align__(16) float sXn[NLN * CC];
    __shared__ __align__(16) float sSn[NLN * CC];
    int tid = threadIdx.x;

    if (blockIdx.x < SCB) {
        int e = blockIdx.x * 256 + tid;
        int s = src[e], d = dst[e];
        float px = rel_pos[e * 3 + 0], py = rel_pos[e * 3 + 1], pz = rel_pos[e * 3 + 2];
        float dist = sqrtf(px * px + py * py + pz * pz);
        float xc = dist / CUTOFFF;
        bool in_cut = dist < CUTOFFF;
        float x2 = in_cut ? fminf(xc * xc, 1.f - 1e-6f) : 0.f;
        float scale = in_cut ? expf(3.f - 3.f / (1.f - x2)) : 0.f;

        int ps = atomicAdd(&g_cursrc[s], 1);
        int pd = atomicAdd(&g_curdst[d], 1);
        g_srcS[ps] = s;
        g_distS[ps] = dist;
        g_scaleS[ps] = scale;
        g_es[pd] = make_int2(ps, __float_as_int(scale));

        float Zu = (float)species[s];
        float Zv = (float)species[d];
        float raw = KCOULF * Zu * Zv / (2.f * dist);
        float au = 0.8854f * 0.529f / (__powf(Zu, 0.23f) + __powf(Zv, 0.23f));
        float xx = dist / au;
        float screen = 0.1818f * __expf(-3.2f * xx) + 0.5099f * __expf(-0.9423f * xx)
                     + 0.2802f * __expf(-0.4028f * xx) + 0.02817f * __expf(-0.2016f * xx);
        float contrib = raw * screen * scale;
        if (contrib != 0.f) atomicAdd(&g_coulN[d], contrib);
        return;
    }

    int blk = blockIdx.x - SCB;
    ull wA[8], wB[8];
    load_w3_regs(tid, W3, wA, wB);
    load_node_weights(tid, b3, W1n, b1n, Wq, nullptr, sW1, sWq, sb3, sb1, nullptr);
    int nloc = tid >> 3, j = tid & 7;
    for (int tile = blk; tile < NTILES; tile += NGRID0) {
        __syncthreads();
        int n = tile * NLN + nloc;
        sXn[nloc * CC + j] = g_x[n * CC + j];
        sXn[nloc * CC + 8 + j] = g_x[n * CC + 8 + j];
        sSn[nloc * CC + j] = 0.f;
        sSn[nloc * CC + 8 + j] = 0.f;
        __syncthreads();
        node_prep_a(n, nloc, j, true, false, sW1, sWq, sb3, sb1, nullptr, sXn, sSn);
        prep_P_reg(tile * NLN, tid, wA, wB, sXn);
    }
}

// ---------------- node layer: persistent tiles, pipelined online-softmax + Wproj + prep ----------------
__global__ void __launch_bounds__(NLT, 3)
k_node_layer(int mode,
             const float* __restrict__ Wproj,
             const float* __restrict__ Wq,
             const float* __restrict__ W3,
             const float* __restrict__ b3,
             const float* __restrict__ W1n,
             const float* __restrict__ b1n,
             const float* __restrict__ Wself) {
    __shared__ __align__(16) float sW1[CC * MIDD];
    __shared__ __align__(16) float sWq[HH * 18];
    __shared__ __align__(16) float sWproj[CC * 25];
    __shared__ __align__(16) float sb3[16 * 18];
    __shared__ __align__(16) float sb1[MIDD];
    __shared__ __align__(16) float sWself[16 * 18];
    __shared__ __align__(16) float sAgg[NLN * HH];
    __shared__ __align__(16) float sXold[NLN * CC];
    __shared__ __align__(16) float sXn[NLN * CC];
    __shared__ __align__(16) float sSn[NLN * CC];

    int tid = threadIdx.x;
    int nloc = tid >> 3, j = tid & 7;

    ull wA[8], wB[8];
    load_w3_regs(tid, W3, wA, wB);
    load_node_weights(tid, b3, W1n, b1n,
                      mode != 2 ? Wq : nullptr,
                      mode == 2 ? Wself : nullptr,
                      sW1, sWq, sb3, sb1, sWself);
    for (int idx = tid; idx < CC * 24; idx += NLT)
        sWproj[(idx / 24) * 25 + (idx % 24)] = Wproj[idx];

    for (int tile = blockIdx.x; tile < NTILES; tile += NGRID1) {
        __syncthreads();
        int n = tile * NLN + nloc;
        {
            int beg = g_rdst[n], end = g_rdst[n + 1];
            float qj = g_q[n * HH + j];
            float m = -INFINITY, num = 0.f, den = 0.f;
            if (beg < end) {
                // software pipeline: es[i+1] prefetched before math of i; vk load
                // issued as soon as its es is available
                int2 es = g_es[beg];
                float2 vk = *(const float2*)(g_vk + (size_t)es.x * CC + j * 2);
                float sc = __int_as_float(es.y);
#pragma unroll 4
                for (int i = beg + 1; i < end; i++) {
                    int2 es_n = g_es[i];
                    float2 vk_n = *(const float2*)(g_vk + (size_t)es_n.x * CC + j * 2);
                    float sc_n = __int_as_float(es_n.y);
                    float l = vk.y * qj;
                    float mn = fmaxf(m, l);
                    float corr = __expf(m - mn);
                    float p = sc * __expf(l - mn);
                    den = den * corr + p;
                    num = fmaf(num, corr, p * vk.x);
                    m = mn;
                    vk = vk_n;
                    sc = sc_n;
                }
                float l = vk.y * qj;
                float mn = fmaxf(m, l);
                float corr = __expf(m - mn);
                float p = sc * __expf(l - mn);
                den = den * corr + p;
                num = fmaf(num, corr, p * vk.x);
            }
            sAgg[nloc * HH + j] = num / fmaxf(den, 1e-20f);
            sXold[nloc * CC + j] = g_x[n * CC + j];
            sXold[nloc * CC + 8 + j] = g_x[n * CC + 8 + j];
            __syncthreads();
            float xn0 = 0.f, xn1 = 0.f;
#pragma unroll
            for (int k = 0; k < 8; k++) {
                float a = sAgg[nloc * HH + k];
                xn0 = fmaf(sWproj[j * 25 + k], a, xn0);
                xn1 = fmaf(sWproj[(j + 8) * 25 + k], a, xn1);
            }
#pragma unroll
            for (int k = 0; k < CC; k++) {
                float xo = sXold[nloc * CC + k];
                xn0 = fmaf(sWproj[j * 25 + 8 + k], xo, xn0);
                xn1 = fmaf(sWproj[(j + 8) * 25 + 8 + k], xo, xn1);
            }
            float s0 = g_S[n * CC + j] + xn0;
            float s1 = g_S[n * CC + 8 + j] + xn1;
            g_x[n * CC + j] = xn0;     g_x[n * CC + 8 + j] = xn1;
            g_S[n * CC + j] = s0;      g_S[n * CC + 8 + j] = s1;
            sXn[nloc * CC + j] = xn0;  sXn[nloc * CC + 8 + j] = xn1;
            sSn[nloc * CC + j] = s0;   sSn[nloc * CC + 8 + j] = s1;
            __syncthreads();
        }
        node_prep_a(n, nloc, j, mode != 2, mode == 2,
                    sW1, sWq, sb3, sb1, sWself, sXn, sSn);
        prep_P_reg(tile * NLN, tid, wA, wB, sXn);
    }
}

// ---------------- edge kernel (R8 best, unchanged) ----------------
__global__ void __launch_bounds__(128, 4)
k_edge(const float* __restrict__ W1, const float* __restrict__ W2,
       const float* __restrict__ b2) {
    __shared__ __align__(16) ull sW2p[512];
    __shared__ float sw15[MIDD];
    __shared__ __align__(16) ull sB2p[16];
    __shared__ __align__(16) float sSt[4][32 * 36];
    int tid = threadIdx.x;
    for (int i = tid; i < 512; i += 128) sW2p[i] = ((const ull*)W2)[i];
    if (tid < MIDD) sw15[tid] = W1[15 * MIDD + tid];
    if (tid < 16) sB2p[tid] = ((const ull*)b2)[tid];
    __syncthreads();

    int t = blockIdx.x * 128 + tid;
    int e0 = 2 * t;
    int s = g_srcS[e0];
    float2 dd = *(const float2*)(g_distS + e0);
    float2 sc = *(const float2*)(g_scaleS + e0);
    float da = dd.x, db = dd.y;
    float bsa = Y0F * sc.x, bsb = Y0F * sc.y;

    float u[MIDD];
    {
        const float4* up = (const float4*)(g_u + (size_t)s * MIDD);
#pragma unroll
        for (int k = 0; k < 8; k++) {
            float4 v = up[k];
            u[4 * k] = v.x; u[4 * k + 1] = v.y; u[4 * k + 2] = v.z; u[4 * k + 3] = v.w;
        }
    }

    ull acca[16], accb[16];
#pragma unroll
    for (int jp = 0; jp < 16; jp++) { acca[jp] = sB2p[jp]; accb[jp] = sB2p[jp]; }
#pragma unroll
    for (int i2 = 0; i2 < MIDD; i2++) {
        float w15v = sw15[i2];
        float ha = fmaxf(fmaf(da, w15v, u[i2]), 0.f);
        float hb = fmaxf(fmaf(db, w15v, u[i2]), 0.f);
        ull xa = pack2(ha, ha);
        ull xb = pack2(hb, hb);
#pragma unroll
        for (int jq = 0; jq < 8; jq++) {
            ulonglong2 w = *(const ulonglong2*)&sW2p[i2 * 16 + jq * 2];
            acca[2 * jq]     = fma2(xa, w.x, acca[2 * jq]);
            acca[2 * jq + 1] = fma2(xa, w.y, acca[2 * jq + 1]);
            accb[2 * jq]     = fma2(xb, w.x, accb[2 * jq]);
            accb[2 * jq + 1] = fma2(xb, w.y, accb[2 * jq + 1]);
        }
    }
    float h2a[MIDD], h2b[MIDD];
#pragma unroll
    for (int jp = 0; jp < 16; jp++) {
        float lo, hi;
        unpack2(acca[jp], lo, hi);
        h2a[2 * jp] = fmaxf(lo, 0.f); h2a[2 * jp + 1] = fmaxf(hi, 0.f);
        unpack2(accb[jp], lo, hi);
        h2b[2 * jp] = fmaxf(lo, 0.f); h2b[2 * jp + 1] = fmaxf(hi, 0.f);
    }

    ull ka[8], kb[8];
    {
        const ulonglong2* pbp = (const ulonglong2*)(g_PB + (size_t)s * CC);
#pragma unroll
        for (int q = 0; q < 4; q++) {
            ulonglong2 pb = pbp[q];
            ka[2 * q] = pb.x; ka[2 * q + 1] = pb.y;
            kb[2 * q] = pb.x; kb[2 * q + 1] = pb.y;
        }
    }
    const ull* Pp = (const ull*)(g_P + (size_t)s * 512);
#pragma unroll
    for (int mq = 0; mq < 8; mq++) {
        ull xa0 = pack2(h2a[mq * 4 + 0], h2a[mq * 4 + 0]);
        ull xa1 = pack2(h2a[mq * 4 + 1], h2a[mq * 4 + 1]);
        ull xa2 = pack2(h2a[mq * 4 + 2], h2a[mq * 4 + 2]);
        ull xa3 = pack2(h2a[mq * 4 + 3], h2a[mq * 4 + 3]);
        ull xb0 = pack2(h2b[mq * 4 + 0], h2b[mq * 4 + 0]);
        ull xb1 = pack2(h2b[mq * 4 + 1], h2b[mq * 4 + 1]);
        ull xb2 = pack2(h2b[mq * 4 + 2], h2b[mq * 4 + 2]);
        ull xb3 = pack2(h2b[mq * 4 + 3], h2b[mq * 4 + 3]);
#pragma unroll
        for (int j = 0; j < 8; j++) {
            ulonglong2 pA = *(const ulonglong2*)(Pp + mq * 32 + j * 4);
            ulonglong2 pB = *(const ulonglong2*)(Pp + mq * 32 + j * 4 + 2);
            ka[j] = fma2(xa0, pA.x, ka[j]);
            ka[j] = fma2(xa1, pA.y, ka[j]);
            ka[j] = fma2(xa2, pB.x, ka[j]);
            ka[j] = fma2(xa3, pB.y, ka[j]);
            kb[j] = fma2(xb0, pA.x, kb[j]);
            kb[j] = fma2(xb1, pA.y, kb[j]);
            kb[j] = fma2(xb2, pB.x, kb[j]);
            kb[j] = fma2(xb3, pB.y, kb[j]);
        }
    }

    int lane = tid & 31, w = tid >> 5;
    float* st = sSt[w];
#pragma unroll
    for (int q = 0; q < 4; q++) {
        float a0, a1, a2, a3;
        unpack2(ka[2 * q], a0, a1);
        unpack2(ka[2 * q + 1], a2, a3);
        *(float4*)&st[lane * 36 + q * 4] = make_float4(a0 * bsa, a1 * bsa, a2 * bsa, a3 * bsa);
    }
#pragma unroll
    for (int q = 0; q < 4; q++) {
        float a0, a1, a2, a3;
        unpack2(kb[2 * q], a0, a1);
        unpack2(kb[2 * q + 1], a2, a3);
        *(float4*)&st[lane * 36 + 16 + q * 4] = make_float4(a0 * bsb, a1 * bsb, a2 * bsb, a3 * bsb);
    }
    __syncwarp();
    float4* gbase = (float4*)(g_vk + (size_t)(blockIdx.x * 256 + w * 64) * CC);
#pragma unroll
    for (int g = 0; g < 8; g++) {
        int f = g * 32 + lane;
        int owner = f >> 3, q = f & 7;
        gbase[f] = *(const float4*)&st[owner * 36 + q * 4];
    }
}

// ---------------- final ----------------
__device__ __forceinline__ float siluf(float x) { return x / (1.f + __expf(-x)); }

__global__ void k_final(const int* __restrict__ species, const float* __restrict__ emb,
                        const float* __restrict__ W1, const float* __restrict__ b1,
                        const float* __restrict__ W2, const float* __restrict__ b2,
                        const float* __restrict__ W3, const float* __restrict__ b3,
                        float* __restrict__ out) {
    __shared__ float sFeat[16 * 17];
    __shared__ float sEmb[16 * 17];
    __shared__ float sH[16 * 17];
    __shared__ float sRed[16];
    int tid = threadIdx.x;
    int nloc = tid >> 4, o = tid & 15;
    int n = blockIdx.x * 16 + nloc;
    int beg = g_rdst[n], end = g_rdst[n + 1];
    int o2 = (o < 8) ? o * 2 : (o - 8) * 2 + 1;
    float f = g_feats[n * CC + o];
    if (beg < end) {
        int ei = g_es[beg].x;
        float v = g_vk[(size_t)ei * CC + o2];
#pragma unroll 4
        for (int i = beg + 1; i < end; i++) {
            int ei_n = g_es[i].x;
            float v_n = g_vk[(size_t)ei_n * CC + o2];
            f += v;
            v = v_n;
        }
        f += v;
    }
    sFeat[nloc * 17 + o] = f;
    int sp = species[n] - 1;
    sEmb[nloc * 17 + o] = emb[sp * CC + o];
    __syncthreads();

    float h1 = b1[o];
#pragma unroll
    for (int k = 0; k < CC; k++) h1 = fmaf(sEmb[nloc * 17 + k], W1[k * CC + o], h1);
#pragma unroll
    for (int k = 0; k < CC; k++) h1 = fmaf(sFeat[nloc * 17 + k], W1[(CC + k) * CC + o], h1);
    sH[nloc * 17 + o] = siluf(h1);
    __syncthreads();

    float h2 = b2[o];
#pragma unroll
    for (int k = 0; k < CC; k++) h2 = fmaf(sH[nloc * 17 + k], W2[k * CC + o], h2);
    h2 = siluf(h2);

    float part = h2 * W3[o];
#pragma unroll
    for (int off = 8; off > 0; off >>= 1)
        part += __shfl_down_sync(0xffffffffu, part, off, 16);
    if (o == 0) sRed[nloc] = part + b3[0] + g_coulN[n];
    __syncthreads();
    if (tid == 0) {
        float acc = 0.f;
#pragma unroll
        for (int k = 0; k < 16; k++) acc += sRed[k];
        atomicAdd(out, acc);
    }
}

// ---------------- host launch ----------------
extern "C" void kernel_launch(void* const* d_in, const int* in_sizes, int n_in,
                              void* d_out, int out_size) {
    const int* species  = (const int*)d_in[0];
    const int* src      = (const int*)d_in[1];
    const int* dst      = (const int*)d_in[2];
    const float* rel_pos = (const float*)d_in[3];
    const float* emb    = (const float*)d_in[4];
    const float* kv_W1  = (const float*)d_in[5];
    const float* kv_b1  = (const float*)d_in[6];
    const float* kv_W2  = (const float*)d_in[7];
    const float* kv_b2  = (const float*)d_in[8];
    const float* kv_W3  = (const float*)d_in[9];
    const float* kv_b3  = (const float*)d_in[10];
    const float* Wq     = (const float*)d_in[11];
    const float* Wproj  = (const float*)d_in[12];
    const float* fin_W1 = (const float*)d_in[13];
    const float* fin_b1 = (const float*)d_in[14];
    const float* fin_W2 = (const float*)d_in[15];
    const float* fin_b2 = (const float*)d_in[16];
    const float* fin_W3 = (const float*)d_in[17];
    const float* fin_b3 = (const float*)d_in[18];
    const float* Wself  = (const float*)d_in[19];
    const float* mlp_W1 = (const float*)d_in[20];
    const float* mlp_b1 = (const float*)d_in[21];
    const float* mlp_W2 = (const float*)d_in[22];
    const float* mlp_b2 = (const float*)d_in[23];
    const float* mlp_W3 = (const float*)d_in[24];
    const float* mlp_b3 = (const float*)d_in[25];
    float* out = (float*)d_out;

    const int EB = EE / 256;         // 2048
    const int EDGB = EENP / 256;     // 2176

    k_init<<<EB, 256>>>(species, emb, out, src, dst);
    k_scan<<<2, 1024>>>();
    k_prep<<<SCB + NGRID0, NLT>>>(src, dst, rel_pos, species,
                                  Wq, kv_W3, kv_b3, kv_W1, kv_b1);

    for (int l = 0; l < 4; l++) {
        k_edge<<<EDGB, 128>>>(kv_W1 + (size_t)l * CC * MIDD,
                              kv_W2 + (size_t)l * MIDD * MIDD,
                              kv_b2 + (size_t)l * MIDD);
        if (l < 3) {
            k_node_layer<<<NGRID1, NLT>>>(1,
                Wproj + (size_t)l * CC * 24,
                Wq + (size_t)(l + 1) * HH * CC,
                kv_W3 + (size_t)(l + 1) * MIDD * 256,
                kv_b3 + (size_t)(l + 1) * 256,
                kv_W1 + (size_t)(l + 1) * CC * MIDD,
                kv_b1 + (size_t)(l + 1) * MIDD,
                nullptr);
        } else {
            k_node_layer<<<NGRID1, NLT>>>(2,
                Wproj + (size_t)l * CC * 24,
                nullptr,
                fin_W3, fin_b3, fin_W1, fin_b1, Wself);
        }
    }
    k_edge<<<EDGB, 128>>>(fin_W1, fin_W2, fin_b2);
    k_final<<<NN / 16, 256>>>(species, emb, mlp_W1, mlp_b1, mlp_W2, mlp_b2,
                              mlp_W3, mlp_b3, out);
}

// round 16
// speedup vs baseline: 1.6402x; 1.0307x over previous
#include <cuda_runtime.h>
#include <math.h>

#define NN 32768
#define EE 524288
#define EENP (EE + NN)          // padded src-sorted capacity (557056 = 256*2176)
#define CC 16
#define MIDD 32
#define HH 8
#define Y0F 0.28209479177387814f
#define CUTOFFF 4.6f
#define KCOULF 0.529f

typedef unsigned long long ull;

// ---------------- device scratch ----------------
__device__ __align__(16) float g_x[NN * CC];
__device__ __align__(16) float g_S[NN * CC];
__device__ __align__(16) float g_q[NN * HH];
__device__ __align__(16) float g_u[NN * MIDD];
__device__ __align__(16) float g_P[NN * 512];     // pair-interleaved
__device__ __align__(16) float g_PB[NN * CC];     // pair-interleaved
__device__ __align__(16) float g_feats[NN * CC];
__device__ __align__(16) float g_vk[(size_t)EENP * CC]; // padded src-sorted {val,key}
__device__ float g_distS[EENP];
__device__ float g_scaleS[EENP];
__device__ __align__(8) int2 g_es[EE];            // dst-order: {src-order idx, scale bits}
__device__ float g_coulN[NN];
__device__ int g_srcS[EENP];
__device__ int g_csrc[NN], g_cdst[NN];
__device__ int g_rdst[NN + 1];
__device__ int g_cursrc[NN], g_curdst[NN];

// ---------------- f32x2 helpers ----------------
__device__ __forceinline__ ull pack2(float a, float b) {
    ull r;
    asm("mov.b64 %0, {%1, %2};" : "=l"(r) : "f"(a), "f"(b));
    return r;
}
__device__ __forceinline__ ull fma2(ull a, ull b, ull c) {
    ull d;
    asm("fma.rn.f32x2 %0, %1, %2, %3;" : "=l"(d) : "l"(a), "l"(b), "l"(c));
    return d;
}
__device__ __forceinline__ void unpack2(ull v, float& lo, float& hi) {
    asm("mov.b64 {%0, %1}, %2;" : "=f"(lo), "=f"(hi) : "l"(v));
}

// ---------------- init ----------------
__global__ void k_init(const int* __restrict__ species, const float* __restrict__ emb,
                       float* __restrict__ out,
                       const int* __restrict__ src, const int* __restrict__ dst) {
    int e = blockIdx.x * 256 + threadIdx.x;
    if (e < NN) {
        int sp = species[e] - 1;
#pragma unroll
        for (int c = 0; c < CC; c++) {
            g_x[e * CC + c] = emb[sp * CC + c];
            g_S[e * CC + c] = 0.f;
        }
        g_coulN[e] = 0.f;
        if (e == 0) out[0] = 0.f;
    }
    atomicAdd(&g_csrc[src[e]], 1);
    atomicAdd(&g_cdst[dst[e]], 1);
}

// ---------------- scan ----------------
__global__ void k_scan() {
    const int T = 1024, PER = NN / 1024;
    __shared__ int part[T];
    int t = threadIdx.x;
    int base = t * PER;
    if (blockIdx.x == 0) {
        int loc[PER], locp[PER];
        int s = 0;
#pragma unroll
        for (int i = 0; i < PER; i++) {
            loc[i] = g_csrc[base + i];
            g_csrc[base + i] = 0;
            locp[i] = (loc[i] + 1) & ~1;
            s += locp[i];
        }
        part[t] = s;
        __syncthreads();
        for (int off = 1; off < T; off <<= 1) {
            int v = (t >= off) ? part[t - off] : 0;
            __syncthreads();
            part[t] += v;
            __syncthreads();
        }
        int run = part[t] - s;
#pragma unroll
        for (int i = 0; i < PER; i++) {
            g_cursrc[base + i] = run;
            if (loc[i] & 1) g_srcS[run + loc[i]] = base + i;
            run += locp[i];
        }
    } else {
        int loc[PER];
        int s = 0;
#pragma unroll
        for (int i = 0; i < PER; i++) {
            loc[i] = g_cdst[base + i];
            g_cdst[base + i] = 0;
            s += loc[i];
        }
        part[t] = s;
        __syncthreads();
        for (int off = 1; off < T; off <<= 1) {
            int v = (t >= off) ? part[t - off] : 0;
            __syncthreads();
            part[t] += v;
            __syncthreads();
        }
        int run = part[t] - s;
#pragma unroll
        for (int i = 0; i < PER; i++) {
            g_rdst[base + i] = run;
            g_curdst[base + i] = run;
            run += loc[i];
        }
        if (t == T - 1) g_rdst[NN] = run;
    }
}

// ---------------- node-prep helpers ----------------
#define NLT 256                 // node-layer threads
#define NLN 32                  // nodes per tile
#define NTILES (NN / NLN)       // 1024
#define NGRID0 592              // prep0: 4 blocks/SM
#define NGRID1 444              // node_layer: 3 blocks/SM
#define SCB 2048                // scatter blocks in fused k_prep

__device__ __forceinline__ void load_node_weights(
    int tid, const float* __restrict__ b3,
    const float* __restrict__ W1n, const float* __restrict__ b1n,
    const float* __restrict__ Wq, const float* __restrict__ Wself,
    float* sW1, float* sWq, float* sb3, float* sb1, float* sWself) {
    for (int idx = tid; idx < CC * MIDD; idx += NLT) sW1[idx] = W1n[idx];
    if (Wq && tid < HH * CC) sWq[(tid >> 4) * 18 + (tid & 15)] = Wq[tid];
    { int o = tid >> 4, i = tid & 15; sb3[o * 18 + i] = b3[tid]; }
    if (tid < MIDD) sb1[tid] = b1n[tid];
    if (Wself && tid < CC * CC) sWself[(tid >> 4) * 18 + (tid & 15)] = Wself[tid];
}

// per-thread W3 slice: thread tid owns (m = (tid>>5)*4 + (tid&3), op = (tid>>2)&7)
__device__ __forceinline__ void load_w3_regs(int tid, const float* __restrict__ W3,
                                             ull wA[8], ull wB[8]) {
    int mq = tid >> 5, op = (tid >> 2) & 7, r = tid & 3;
    int m = mq * 4 + r;
    const ulonglong2* pa = (const ulonglong2*)(W3 + m * 256 + op * 16);
    const ulonglong2* pb = (const ulonglong2*)(W3 + m * 256 + (op + 8) * 16);
#pragma unroll
    for (int t = 0; t < 4; t++) {
        ulonglong2 va = pa[t];
        wA[2 * t] = va.x; wA[2 * t + 1] = va.y;
        ulonglong2 vb = pb[t];
        wB[2 * t] = vb.x; wB[2 * t + 1] = vb.y;
    }
}

// phase B: P for all NLN nodes of the tile; write offset = tid*2 (matches k_edge layout)
__device__ __forceinline__ void prep_P_reg(int n0, int tid,
                                           const ull wA[8], const ull wB[8],
                                           const float* sXn) {
#pragma unroll 2
    for (int nloc = 0; nloc < NLN; nloc++) {
        const ulonglong2* xp = (const ulonglong2*)&sXn[nloc * CC];
        ulonglong2 x01 = xp[0], x23 = xp[1], x45 = xp[2], x67 = xp[3];
        ull aA = 0ULL, aB = 0ULL;
        aA = fma2(x01.x, wA[0], aA); aB = fma2(x01.x, wB[0], aB);
        aA = fma2(x01.y, wA[1], aA); aB = fma2(x01.y, wB[1], aB);
        aA = fma2(x23.x, wA[2], aA); aB = fma2(x23.x, wB[2], aB);
        aA = fma2(x23.y, wA[3], aA); aB = fma2(x23.y, wB[3], aB);
        aA = fma2(x45.x, wA[4], aA); aB = fma2(x45.x, wB[4], aB);
        aA = fma2(x45.y, wA[5], aA); aB = fma2(x45.y, wB[5], aB);
        aA = fma2(x67.x, wA[6], aA); aB = fma2(x67.x, wB[6], aB);
        aA = fma2(x67.y, wA[7], aA); aB = fma2(x67.y, wB[7], aB);
        float la, ha, lb, hb;
        unpack2(aA, la, ha);
        unpack2(aB, lb, hb);
        *(ull*)(g_P + (size_t)(n0 + nloc) * 512 + tid * 2) = pack2(la + ha, lb + hb);
    }
}

// phase A: q/u/PB/feats for node n; lane j owns o-pair (j, j+8)
__device__ __forceinline__ void node_prep_a(
    int n, int nloc, int j, bool do_q, bool do_feats,
    const float* sW1, const float* sWq,
    const float* sb3, const float* sb1, const float* sWself,
    const float* sXn, const float* sSn) {
    ull xx[8];
#pragma unroll
    for (int ip = 0; ip < 8; ip++)
        xx[ip] = *(const ull*)&sXn[nloc * CC + 2 * ip];

    if (do_q) {
        float qa = 0.f;
#pragma unroll
        for (int c = 0; c < CC; c++) qa = fmaf(sWq[j * 18 + c], sXn[nloc * CC + c], qa);
        g_q[n * HH + j] = qa;
    }
    {
        float u0 = sb1[j], u1 = sb1[j + 8], u2 = sb1[j + 16], u3 = sb1[j + 24];
#pragma unroll
        for (int c = 0; c < CC; c++) {
            float sv = sSn[nloc * CC + c];
            u0 = fmaf(sv, sW1[c * MIDD + j], u0);
            u1 = fmaf(sv, sW1[c * MIDD + j + 8], u1);
            u2 = fmaf(sv, sW1[c * MIDD + j + 16], u2);
            u3 = fmaf(sv, sW1[c * MIDD + j + 24], u3);
        }
        g_u[n * MIDD + j] = u0;
        g_u[n * MIDD + j + 8] = u1;
        g_u[n * MIDD + j + 16] = u2;
        g_u[n * MIDD + j + 24] = u3;
    }
    {
        ull a0 = 0ULL, a1 = 0ULL;
#pragma unroll
        for (int ip = 0; ip < 8; ip++) {
            a0 = fma2(xx[ip], *(const ull*)&sb3[j * 18 + 2 * ip], a0);
            a1 = fma2(xx[ip], *(const ull*)&sb3[(j + 8) * 18 + 2 * ip], a1);
        }
        float l0, h0, l1, h1;
        unpack2(a0, l0, h0);
        unpack2(a1, l1, h1);
        g_PB[n * CC + j * 2] = l0 + h0;
        g_PB[n * CC + j * 2 + 1] = l1 + h1;
    }
    if (do_feats) {
        ull a0 = 0ULL, a1 = 0ULL;
#pragma unroll
        for (int ip = 0; ip < 8; ip++) {
            a0 = fma2(xx[ip], *(const ull*)&sWself[j * 18 + 2 * ip], a0);
            a1 = fma2(xx[ip], *(const ull*)&sWself[(j + 8) * 18 + 2 * ip], a1);
        }
        float l0, h0, l1, h1;
        unpack2(a0, l0, h0);
        unpack2(a1, l1, h1);
        g_feats[n * CC + j] = l0 + h0;
        g_feats[n * CC + 8 + j] = l1 + h1;
    }
}

// ---------------- fused prep: blocks [0,SCB) scatter; [SCB, SCB+NGRID0) layer-0 node prep ----------------
__global__ void __launch_bounds__(NLT, 4)
k_prep(const int* __restrict__ src, const int* __restrict__ dst,
       const float* __restrict__ rel_pos, const int* __restrict__ species,
       const float* __restrict__ Wq, const float* __restrict__ W3,
       const float* __restrict__ b3, const float* __restrict__ W1n,
       const float* __restrict__ b1n) {
    __shared__ __align__(16) float sW1[CC * MIDD];
    __shared__ __align__(16) float sWq[HH * 18];
    __shared__ __align__(16) float sb3[16 * 18];
    __shared__ __align__(16) float sb1[MIDD];
    __shared__ __align__(16) float sXn[NLN * CC];
    __shared__ __align__(16) float sSn[NLN * CC];
    int tid = threadIdx.x;

    if (blockIdx.x < SCB) {
        int e = blockIdx.x * 256 + tid;
        int s = src[e], d = dst[e];
        float px = rel_pos[e * 3 + 0], py = rel_pos[e * 3 + 1], pz = rel_pos[e * 3 + 2];
        float dist = sqrtf(px * px + py * py + pz * pz);
        float xc = dist / CUTOFFF;
        bool in_cut = dist < CUTOFFF;
        float x2 = in_cut ? fminf(xc * xc, 1.f - 1e-6f) : 0.f;
        float scale = in_cut ? expf(3.f - 3.f / (1.f - x2)) : 0.f;

        int ps = atomicAdd(&g_cursrc[s], 1);
        int pd = atomicAdd(&g_curdst[d], 1);
        g_srcS[ps] = s;
        g_distS[ps] = dist;
        g_scaleS[ps] = scale;
        g_es[pd] = make_int2(ps, __float_as_int(scale));

        float Zu = (float)species[s];
        float Zv = (float)species[d];
        float raw = KCOULF * Zu * Zv / (2.f * dist);
        float au = 0.8854f * 0.529f / (__powf(Zu, 0.23f) + __powf(Zv, 0.23f));
        float xx = dist / au;
        float screen = 0.1818f * __expf(-3.2f * xx) + 0.5099f * __expf(-0.9423f * xx)
                     + 0.2802f * __expf(-0.4028f * xx) + 0.02817f * __expf(-0.2016f * xx);
        float contrib = raw * screen * scale;
        if (contrib != 0.f) atomicAdd(&g_coulN[d], contrib);
        return;
    }

    int blk = blockIdx.x - SCB;
    ull wA[8], wB[8];
    load_w3_regs(tid, W3, wA, wB);
    load_node_weights(tid, b3, W1n, b1n, Wq, nullptr, sW1, sWq, sb3, sb1, nullptr);
    int nloc = tid >> 3, j = tid & 7;
    for (int tile = blk; tile < NTILES; tile += NGRID0) {
        __syncthreads();
        int n = tile * NLN + nloc;
        sXn[nloc * CC + j] = g_x[n * CC + j];
        sXn[nloc * CC + 8 + j] = g_x[n * CC + 8 + j];
        sSn[nloc * CC + j] = 0.f;
        sSn[nloc * CC + 8 + j] = 0.f;
        __syncthreads();
        node_prep_a(n, nloc, j, true, false, sW1, sWq, sb3, sb1, nullptr, sXn, sSn);
        prep_P_reg(tile * NLN, tid, wA, wB, sXn);
    }
}

// ---------------- node layer: persistent tiles, pipelined online-softmax + Wproj + prep ----------------
__global__ void __launch_bounds__(NLT, 3)
k_node_layer(int mode,
             const float* __restrict__ Wproj,
             const float* __restrict__ Wq,
             const float* __restrict__ W3,
             const float* __restrict__ b3,
             const float* __restrict__ W1n,
             const float* __restrict__ b1n,
             const float* __restrict__ Wself) {
    __shared__ __align__(16) float sW1[CC * MIDD];
    __shared__ __align__(16) float sWq[HH * 18];
    __shared__ __align__(16) float sWproj[CC * 25];
    __shared__ __align__(16) float sb3[16 * 18];
    __shared__ __align__(16) float sb1[MIDD];
    __shared__ __align__(16) float sWself[16 * 18];
    __shared__ __align__(16) float sAgg[NLN * HH];
    __shared__ __align__(16) float sXold[NLN * CC];
    __shared__ __align__(16) float sXn[NLN * CC];
    __shared__ __align__(16) float sSn[NLN * CC];

    int tid = threadIdx.x;
    int nloc = tid >> 3, j = tid & 7;

    ull wA[8], wB[8];
    load_w3_regs(tid, W3, wA, wB);
    load_node_weights(tid, b3, W1n, b1n,
                      mode != 2 ? Wq : nullptr,
                      mode == 2 ? Wself : nullptr,
                      sW1, sWq, sb3, sb1, sWself);
    for (int idx = tid; idx < CC * 24; idx += NLT)
        sWproj[(idx / 24) * 25 + (idx % 24)] = Wproj[idx];

    for (int tile = blockIdx.x; tile < NTILES; tile += NGRID1) {
        __syncthreads();
        int n = tile * NLN + nloc;
        {
            int beg = g_rdst[n], end = g_rdst[n + 1];
            float qj = g_q[n * HH + j];
            float m = -INFINITY, num = 0.f, den = 0.f;
            if (beg < end) {
                int2 es = g_es[beg];
                float2 vk = *(const float2*)(g_vk + (size_t)es.x * CC + j * 2);
                float sc = __int_as_float(es.y);
#pragma unroll 4
                for (int i = beg + 1; i < end; i++) {
                    int2 es_n = g_es[i];
                    float2 vk_n = *(const float2*)(g_vk + (size_t)es_n.x * CC + j * 2);
                    float sc_n = __int_as_float(es_n.y);
                    float l = vk.y * qj;
                    float mn = fmaxf(m, l);
                    float corr = __expf(m - mn);
                    float p = sc * __expf(l - mn);
                    den = den * corr + p;
                    num = fmaf(num, corr, p * vk.x);
                    m = mn;
                    vk = vk_n;
                    sc = sc_n;
                }
                float l = vk.y * qj;
                float mn = fmaxf(m, l);
                float corr = __expf(m - mn);
                float p = sc * __expf(l - mn);
                den = den * corr + p;
                num = fmaf(num, corr, p * vk.x);
            }
            sAgg[nloc * HH + j] = num / fmaxf(den, 1e-20f);
            sXold[nloc * CC + j] = g_x[n * CC + j];
            sXold[nloc * CC + 8 + j] = g_x[n * CC + 8 + j];
            __syncthreads();
            float xn0 = 0.f, xn1 = 0.f;
#pragma unroll
            for (int k = 0; k < 8; k++) {
                float a = sAgg[nloc * HH + k];
                xn0 = fmaf(sWproj[j * 25 + k], a, xn0);
                xn1 = fmaf(sWproj[(j + 8) * 25 + k], a, xn1);
            }
#pragma unroll
            for (int k = 0; k < CC; k++) {
                float xo = sXold[nloc * CC + k];
                xn0 = fmaf(sWproj[j * 25 + 8 + k], xo, xn0);
                xn1 = fmaf(sWproj[(j + 8) * 25 + 8 + k], xo, xn1);
            }
            float s0 = g_S[n * CC + j] + xn0;
            float s1 = g_S[n * CC + 8 + j] + xn1;
            g_x[n * CC + j] = xn0;     g_x[n * CC + 8 + j] = xn1;
            g_S[n * CC + j] = s0;      g_S[n * CC + 8 + j] = s1;
            sXn[nloc * CC + j] = xn0;  sXn[nloc * CC + 8 + j] = xn1;
            sSn[nloc * CC + j] = s0;   sSn[nloc * CC + 8 + j] = s1;
            __syncthreads();
        }
        node_prep_a(n, nloc, j, mode != 2, mode == 2,
                    sW1, sWq, sb3, sb1, sWself, sXn, sSn);
        prep_P_reg(tile * NLN, tid, wA, wB, sXn);
    }
}

// ---------------- edge kernel: pair/thread + warp-cooperative P staging in smem ----------------
#define PSLOTS 6
#define PROWS 516               // row stride (floats): 16B-aligned, slots on distinct banks

__global__ void __launch_bounds__(128, 3)
k_edge(const float* __restrict__ W1, const float* __restrict__ W2,
       const float* __restrict__ b2) {
    __shared__ __align__(16) ull sW2p[512];
    __shared__ float sw15[MIDD];
    __shared__ __align__(16) ull sB2p[16];
    __shared__ __align__(16) float sSt[4][32 * 36];
    extern __shared__ __align__(16) float sPst[];   // [4 warps][PSLOTS * PROWS]
    int tid = threadIdx.x;
    int lane = tid & 31, w = tid >> 5;
    for (int i = tid; i < 512; i += 128) sW2p[i] = ((const ull*)W2)[i];
    if (tid < MIDD) sw15[tid] = W1[15 * MIDD + tid];
    if (tid < 16) sB2p[tid] = ((const ull*)b2)[tid];
    __syncthreads();

    int t = blockIdx.x * 128 + tid;
    int e0 = 2 * t;
    int s = g_srcS[e0];
    float2 dd = *(const float2*)(g_distS + e0);
    float2 sc = *(const float2*)(g_scaleS + e0);
    float da = dd.x, db = dd.y;
    float bsa = Y0F * sc.x, bsb = Y0F * sc.y;

    // ---- warp src-dedup + cooperative P staging ----
    const unsigned full = 0xffffffffu;
    int sprev = __shfl_up_sync(full, s, 1);
    bool leader = (lane == 0) || (s != sprev);
    unsigned lmask = __ballot_sync(full, leader);
    int nlead = __popc(lmask);
    unsigned lml;
    asm("mov.u32 %0, %%lanemask_le;" : "=r"(lml));
    int slot = __popc(lmask & lml) - 1;
    bool use_s = (nlead <= PSLOTS);
    float* wst = sPst + w * (PSLOTS * PROWS);
    if (use_s) {
        unsigned rem = lmask;
        for (int sl = 0; sl < nlead; sl++) {
            int ldr = __ffs(rem) - 1;
            rem &= rem - 1;
            int rs = __shfl_sync(full, s, ldr);
            const float4* gp = (const float4*)(g_P + (size_t)rs * 512);
            float* sp = wst + sl * PROWS;
#pragma unroll
            for (int it = 0; it < 4; it++) {
                float4 v = gp[it * 32 + lane];
                *(float4*)&sp[(it * 32 + lane) * 4] = v;
            }
        }
    }

    // u (shared by both edges)
    float u[MIDD];
    {
        const float4* up = (const float4*)(g_u + (size_t)s * MIDD);
#pragma unroll
        for (int k = 0; k < 8; k++) {
            float4 v = up[k];
            u[4 * k] = v.x; u[4 * k + 1] = v.y; u[4 * k + 2] = v.z; u[4 * k + 3] = v.w;
        }
    }

    ull acca[16], accb[16];
#pragma unroll
    for (int jp = 0; jp < 16; jp++) { acca[jp] = sB2p[jp]; accb[jp] = sB2p[jp]; }
#pragma unroll
    for (int i2 = 0; i2 < MIDD; i2++) {
        float w15v = sw15[i2];
        float ha = fmaxf(fmaf(da, w15v, u[i2]), 0.f);
        float hb = fmaxf(fmaf(db, w15v, u[i2]), 0.f);
        ull xa = pack2(ha, ha);
        ull xb = pack2(hb, hb);
#pragma unroll
        for (int jq = 0; jq < 8; jq++) {
            ulonglong2 wv = *(const ulonglong2*)&sW2p[i2 * 16 + jq * 2];
            acca[2 * jq]     = fma2(xa, wv.x, acca[2 * jq]);
            acca[2 * jq + 1] = fma2(xa, wv.y, acca[2 * jq + 1]);
            accb[2 * jq]     = fma2(xb, wv.x, accb[2 * jq]);
            accb[2 * jq + 1] = fma2(xb, wv.y, accb[2 * jq + 1]);
        }
    }
    float h2a[MIDD], h2b[MIDD];
#pragma unroll
    for (int jp = 0; jp < 16; jp++) {
        float lo, hi;
        unpack2(acca[jp], lo, hi);
        h2a[2 * jp] = fmaxf(lo, 0.f); h2a[2 * jp + 1] = fmaxf(hi, 0.f);
        unpack2(accb[jp], lo, hi);
        h2b[2 * jp] = fmaxf(lo, 0.f); h2b[2 * jp + 1] = fmaxf(hi, 0.f);
    }

    ull ka[8], kb[8];
    {
        const ulonglong2* pbp = (const ulonglong2*)(g_PB + (size_t)s * CC);
#pragma unroll
        for (int q = 0; q < 4; q++) {
            ulonglong2 pb = pbp[q];
            ka[2 * q] = pb.x; ka[2 * q + 1] = pb.y;
            kb[2 * q] = pb.x; kb[2 * q + 1] = pb.y;
        }
    }
    __syncwarp();
    const ull* Pp = use_s ? (const ull*)(wst + slot * PROWS)
                          : (const ull*)(g_P + (size_t)s * 512);
#pragma unroll
    for (int mq = 0; mq < 8; mq++) {
        ull xa0 = pack2(h2a[mq * 4 + 0], h2a[mq * 4 + 0]);
        ull xa1 = pack2(h2a[mq * 4 + 1], h2a[mq * 4 + 1]);
        ull xa2 = pack2(h2a[mq * 4 + 2], h2a[mq * 4 + 2]);
        ull xa3 = pack2(h2a[mq * 4 + 3], h2a[mq * 4 + 3]);
        ull xb0 = pack2(h2b[mq * 4 + 0], h2b[mq * 4 + 0]);
        ull xb1 = pack2(h2b[mq * 4 + 1], h2b[mq * 4 + 1]);
        ull xb2 = pack2(h2b[mq * 4 + 2], h2b[mq * 4 + 2]);
        ull xb3 = pack2(h2b[mq * 4 + 3], h2b[mq * 4 + 3]);
#pragma unroll
        for (int j = 0; j < 8; j++) {
            ulonglong2 pA = *(const ulonglong2*)(Pp + mq * 32 + j * 4);
            ulonglong2 pB = *(const ulonglong2*)(Pp + mq * 32 + j * 4 + 2);
            ka[j] = fma2(xa0, pA.x, ka[j]);
            ka[j] = fma2(xa1, pA.y, ka[j]);
            ka[j] = fma2(xa2, pB.x, ka[j]);
            ka[j] = fma2(xa3, pB.y, ka[j]);
            kb[j] = fma2(xb0, pA.x, kb[j]);
            kb[j] = fma2(xb1, pA.y, kb[j]);
            kb[j] = fma2(xb2, pB.x, kb[j]);
            kb[j] = fma2(xb3, pB.y, kb[j]);
        }
    }

    float* st = sSt[w];
#pragma unroll
    for (int q = 0; q < 4; q++) {
        float a0, a1, a2, a3;
        unpack2(ka[2 * q], a0, a1);
        unpack2(ka[2 * q + 1], a2, a3);
        *(float4*)&st[lane * 36 + q * 4] = make_float4(a0 * bsa, a1 * bsa, a2 * bsa, a3 * bsa);
    }
#pragma unroll
    for (int q = 0; q < 4; q++) {
        float a0, a1, a2, a3;
        unpack2(kb[2 * q], a0, a1);
        unpack2(kb[2 * q + 1], a2, a3);
        *(float4*)&st[lane * 36 + 16 + q * 4] = make_float4(a0 * bsb, a1 * bsb, a2 * bsb, a3 * bsb);
    }
    __syncwarp();
    float4* gbase = (float4*)(g_vk + (size_t)(blockIdx.x * 256 + w * 64) * CC);
#pragma unroll
    for (int g = 0; g < 8; g++) {
        int f = g * 32 + lane;
        int owner = f >> 3, q = f & 7;
        gbase[f] = *(const float4*)&st[owner * 36 + q * 4];
    }
}

// ---------------- final ----------------
__device__ __forceinline__ float siluf(float x) { return x / (1.f + __expf(-x)); }

__global__ void k_final(const int* __restrict__ species, const float* __restrict__ emb,
                        const float* __restrict__ W1, const float* __restrict__ b1,
                        const float* __restrict__ W2, const float* __restrict__ b2,
                        const float* __restrict__ W3, const float* __restrict__ b3,
                        float* __restrict__ out) {
    __shared__ float sFeat[16 * 17];
    __shared__ float sEmb[16 * 17];
    __shared__ float sH[16 * 17];
    __shared__ float sRed[16];
    int tid = threadIdx.x;
    int nloc = tid >> 4, o = tid & 15;
    int n = blockIdx.x * 16 + nloc;
    int beg = g_rdst[n], end = g_rdst[n + 1];
    int o2 = (o < 8) ? o * 2 : (o - 8) * 2 + 1;
    float f = g_feats[n * CC + o];
    if (beg < end) {
        int ei = g_es[beg].x;
        float v = g_vk[(size_t)ei * CC + o2];
#pragma unroll 4
        for (int i = beg + 1; i < end; i++) {
            int ei_n = g_es[i].x;
            float v_n = g_vk[(size_t)ei_n * CC + o2];
            f += v;
            v = v_n;
        }
        f += v;
    }
    sFeat[nloc * 17 + o] = f;
    int sp = species[n] - 1;
    sEmb[nloc * 17 + o] = emb[sp * CC + o];
    __syncthreads();

    float h1 = b1[o];
#pragma unroll
    for (int k = 0; k < CC; k++) h1 = fmaf(sEmb[nloc * 17 + k], W1[k * CC + o], h1);
#pragma unroll
    for (int k = 0; k < CC; k++) h1 = fmaf(sFeat[nloc * 17 + k], W1[(CC + k) * CC + o], h1);
    sH[nloc * 17 + o] = siluf(h1);
    __syncthreads();

    float h2 = b2[o];
#pragma unroll
    for (int k = 0; k < CC; k++) h2 = fmaf(sH[nloc * 17 + k], W2[k * CC + o], h2);
    h2 = siluf(h2);

    float part = h2 * W3[o];
#pragma unroll
    for (int off = 8; off > 0; off >>= 1)
        part += __shfl_down_sync(0xffffffffu, part, off, 16);
    if (o == 0) sRed[nloc] = part + b3[0] + g_coulN[n];
    __syncthreads();
    if (tid == 0) {
        float acc = 0.f;
#pragma unroll
        for (int k = 0; k < 16; k++) acc += sRed[k];
        atomicAdd(out, acc);
    }
}

// ---------------- host launch ----------------
extern "C" void kernel_launch(void* const* d_in, const int* in_sizes, int n_in,
                              void* d_out, int out_size) {
    const int* species  = (const int*)d_in[0];
    const int* src      = (const int*)d_in[1];
    const int* dst      = (const int*)d_in[2];
    const float* rel_pos = (const float*)d_in[3];
    const float* emb    = (const float*)d_in[4];
    const float* kv_W1  = (const float*)d_in[5];
    const float* kv_b1  = (const float*)d_in[6];
    const float* kv_W2  = (const float*)d_in[7];
    const float* kv_b2  = (const float*)d_in[8];
    const float* kv_W3  = (const float*)d_in[9];
    const float* kv_b3  = (const float*)d_in[10];
    const float* Wq     = (const float*)d_in[11];
    const float* Wproj  = (const float*)d_in[12];
    const float* fin_W1 = (const float*)d_in[13];
    const float* fin_b1 = (const float*)d_in[14];
    const float* fin_W2 = (const float*)d_in[15];
    const float* fin_b2 = (const float*)d_in[16];
    const float* fin_W3 = (const float*)d_in[17];
    const float* fin_b3 = (const float*)d_in[18];
    const float* Wself  = (const float*)d_in[19];
    const float* mlp_W1 = (const float*)d_in[20];
    const float* mlp_b1 = (const float*)d_in[21];
    const float* mlp_W2 = (const float*)d_in[22];
    const float* mlp_b2 = (const float*)d_in[23];
    const float* mlp_W3 = (const float*)d_in[24];
    const float* mlp_b3 = (const float*)d_in[25];
    float* out = (float*)d_out;

    const int EB = EE / 256;         // 2048
    const int EDGB = EENP / 256;     // 2176
    const int PSTB = 4 * PSLOTS * PROWS * sizeof(float);   // dynamic smem for k_edge

    static int attr_set = 0;
    if (!attr_set) {
        cudaFuncSetAttribute(k_edge, cudaFuncAttributeMaxDynamicSharedMemorySize, PSTB);
        attr_set = 1;
    }

    k_init<<<EB, 256>>>(species, emb, out, src, dst);
    k_scan<<<2, 1024>>>();
    k_prep<<<SCB + NGRID0, NLT>>>(src, dst, rel_pos, species,
                                  Wq, kv_W3, kv_b3, kv_W1, kv_b1);

    for (int l = 0; l < 4; l++) {
        k_edge<<<EDGB, 128, PSTB>>>(kv_W1 + (size_t)l * CC * MIDD,
                                    kv_W2 + (size_t)l * MIDD * MIDD,
                                    kv_b2 + (size_t)l * MIDD);
        if (l < 3) {
            k_node_layer<<<NGRID1, NLT>>>(1,
                Wproj + (size_t)l * CC * 24,
                Wq + (size_t)(l + 1) * HH * CC,
                kv_W3 + (size_t)(l + 1) * MIDD * 256,
                kv_b3 + (size_t)(l + 1) * 256,
                kv_W1 + (size_t)(l + 1) * CC * MIDD,
                kv_b1 + (size_t)(l + 1) * MIDD,
                nullptr);
        } else {
            k_node_layer<<<NGRID1, NLT>>>(2,
                Wproj + (size_t)l * CC * 24,
                nullptr,
                fin_W3, fin_b3, fin_W1, fin_b1, Wself);
        }
    }
    k_edge<<<EDGB, 128, PSTB>>>(fin_W1, fin_W2, fin_b2);
    k_final<<<NN / 16, 256>>>(species, emb, mlp_W1, mlp_b1, mlp_W2, mlp_b2,
                              mlp_W3, mlp_b3, out);
}

// round 17
// speedup vs baseline: 1.6501x; 1.0060x over previous
#include <cuda_runtime.h>
#include <math.h>

#define NN 32768
#define EE 524288
#define EENP (EE + NN)          // padded src-sorted capacity (557056 = 256*2176)
#define CC 16
#define MIDD 32
#define HH 8
#define Y0F 0.28209479177387814f
#define CUTOFFF 4.6f
#define KCOULF 0.529f

typedef unsigned long long ull;

// ---------------- device scratch ----------------
__device__ __align__(16) float g_x[NN * CC];
__device__ __align__(16) float g_S[NN * CC];
__device__ __align__(16) float g_q[NN * HH];
__device__ __align__(16) float g_u[NN * MIDD];
__device__ __align__(16) float g_P[NN * 512];     // pair-interleaved
__device__ __align__(16) float g_PB[NN * CC];     // pair-interleaved
__device__ __align__(16) float g_feats[NN * CC];
__device__ __align__(16) float g_vk[(size_t)EENP * CC]; // padded src-sorted {val,key}
__device__ float g_distS[EENP];
__device__ float g_scaleS[EENP];
__device__ __align__(8) int2 g_es[EE];            // dst-order: {src-order idx, scale bits}
__device__ float g_coulN[NN];
__device__ int g_srcS[EENP];
__device__ int g_csrc[NN], g_cdst[NN];
__device__ int g_rdst[NN + 1];
__device__ int g_cursrc[NN], g_curdst[NN];

// ---------------- f32x2 helpers ----------------
__device__ __forceinline__ ull pack2(float a, float b) {
    ull r;
    asm("mov.b64 %0, {%1, %2};" : "=l"(r) : "f"(a), "f"(b));
    return r;
}
__device__ __forceinline__ ull fma2(ull a, ull b, ull c) {
    ull d;
    asm("fma.rn.f32x2 %0, %1, %2, %3;" : "=l"(d) : "l"(a), "l"(b), "l"(c));
    return d;
}
__device__ __forceinline__ void unpack2(ull v, float& lo, float& hi) {
    asm("mov.b64 {%0, %1}, %2;" : "=f"(lo), "=f"(hi) : "l"(v));
}

// ---------------- init ----------------
__global__ void k_init(const int* __restrict__ species, const float* __restrict__ emb,
                       float* __restrict__ out,
                       const int* __restrict__ src, const int* __restrict__ dst) {
    int e = blockIdx.x * 256 + threadIdx.x;
    if (e < NN) {
        int sp = species[e] - 1;
#pragma unroll
        for (int c = 0; c < CC; c++) {
            g_x[e * CC + c] = emb[sp * CC + c];
            g_S[e * CC + c] = 0.f;
        }
        g_coulN[e] = 0.f;
        if (e == 0) out[0] = 0.f;
    }
    atomicAdd(&g_csrc[src[e]], 1);
    atomicAdd(&g_cdst[dst[e]], 1);
}

// ---------------- scan ----------------
__global__ void k_scan() {
    const int T = 1024, PER = NN / 1024;
    __shared__ int part[T];
    int t = threadIdx.x;
    int base = t * PER;
    if (blockIdx.x == 0) {
        int loc[PER], locp[PER];
        int s = 0;
#pragma unroll
        for (int i = 0; i < PER; i++) {
            loc[i] = g_csrc[base + i];
            g_csrc[base + i] = 0;
            locp[i] = (loc[i] + 1) & ~1;
            s += locp[i];
        }
        part[t] = s;
        __syncthreads();
        for (int off = 1; off < T; off <<= 1) {
            int v = (t >= off) ? part[t - off] : 0;
            __syncthreads();
            part[t] += v;
            __syncthreads();
        }
        int run = part[t] - s;
#pragma unroll
        for (int i = 0; i < PER; i++) {
            g_cursrc[base + i] = run;
            if (loc[i] & 1) g_srcS[run + loc[i]] = base + i;
            run += locp[i];
        }
    } else {
        int loc[PER];
        int s = 0;
#pragma unroll
        for (int i = 0; i < PER; i++) {
            loc[i] = g_cdst[base + i];
            g_cdst[base + i] = 0;
            s += loc[i];
        }
        part[t] = s;
        __syncthreads();
        for (int off = 1; off < T; off <<= 1) {
            int v = (t >= off) ? part[t - off] : 0;
            __syncthreads();
            part[t] += v;
            __syncthreads();
        }
        int run = part[t] - s;
#pragma unroll
        for (int i = 0; i < PER; i++) {
            g_rdst[base + i] = run;
            g_curdst[base + i] = run;
            run += loc[i];
        }
        if (t == T - 1) g_rdst[NN] = run;
    }
}

// ---------------- node-prep helpers ----------------
#define NLT 256                 // node-layer threads
#define NLN 32                  // nodes per tile
#define NTILES (NN / NLN)       // 1024
#define NGRID0 592              // prep0: 4 blocks/SM
#define NGRID1 444              // node_layer: 3 blocks/SM
#define SCB 2048                // scatter blocks in fused k_prep

__device__ __forceinline__ void load_node_weights(
    int tid, const float* __restrict__ b3,
    const float* __restrict__ W1n, const float* __restrict__ b1n,
    const float* __restrict__ Wq, const float* __restrict__ Wself,
    float* sW1, float* sWq, float* sb3, float* sb1, float* sWself) {
    for (int idx = tid; idx < CC * MIDD; idx += NLT) sW1[idx] = W1n[idx];
    if (Wq && tid < HH * CC) sWq[(tid >> 4) * 18 + (tid & 15)] = Wq[tid];
    { int o = tid >> 4, i = tid & 15; sb3[o * 18 + i] = b3[tid]; }
    if (tid < MIDD) sb1[tid] = b1n[tid];
    if (Wself && tid < CC * CC) sWself[(tid >> 4) * 18 + (tid & 15)] = Wself[tid];
}

// per-thread W3 slice: thread tid owns (m = (tid>>5)*4 + (tid&3), op = (tid>>2)&7)
__device__ __forceinline__ void load_w3_regs(int tid, const float* __restrict__ W3,
                                             ull wA[8], ull wB[8]) {
    int mq = tid >> 5, op = (tid >> 2) & 7, r = tid & 3;
    int m = mq * 4 + r;
    const ulonglong2* pa = (const ulonglong2*)(W3 + m * 256 + op * 16);
    const ulonglong2* pb = (const ulonglong2*)(W3 + m * 256 + (op + 8) * 16);
#pragma unroll
    for (int t = 0; t < 4; t++) {
        ulonglong2 va = pa[t];
        wA[2 * t] = va.x; wA[2 * t + 1] = va.y;
        ulonglong2 vb = pb[t];
        wB[2 * t] = vb.x; wB[2 * t + 1] = vb.y;
    }
}

// phase B: P for all NLN nodes of the tile; write offset = tid*2 (matches k_edge layout)
__device__ __forceinline__ void prep_P_reg(int n0, int tid,
                                           const ull wA[8], const ull wB[8],
                                           const float* sXn) {
#pragma unroll 2
    for (int nloc = 0; nloc < NLN; nloc++) {
        const ulonglong2* xp = (const ulonglong2*)&sXn[nloc * CC];
        ulonglong2 x01 = xp[0], x23 = xp[1], x45 = xp[2], x67 = xp[3];
        ull aA = 0ULL, aB = 0ULL;
        aA = fma2(x01.x, wA[0], aA); aB = fma2(x01.x, wB[0], aB);
        aA = fma2(x01.y, wA[1], aA); aB = fma2(x01.y, wB[1], aB);
        aA = fma2(x23.x, wA[2], aA); aB = fma2(x23.x, wB[2], aB);
        aA = fma2(x23.y, wA[3], aA); aB = fma2(x23.y, wB[3], aB);
        aA = fma2(x45.x, wA[4], aA); aB = fma2(x45.x, wB[4], aB);
        aA = fma2(x45.y, wA[5], aA); aB = fma2(x45.y, wB[5], aB);
        aA = fma2(x67.x, wA[6], aA); aB = fma2(x67.x, wB[6], aB);
        aA = fma2(x67.y, wA[7], aA); aB = fma2(x67.y, wB[7], aB);
        float la, ha, lb, hb;
        unpack2(aA, la, ha);
        unpack2(aB, lb, hb);
        *(ull*)(g_P + (size_t)(n0 + nloc) * 512 + tid * 2) = pack2(la + ha, lb + hb);
    }
}

// phase A: q/u/PB/feats for node n; lane j owns o-pair (j, j+8)
__device__ __forceinline__ void node_prep_a(
    int n, int nloc, int j, bool do_q, bool do_feats,
    const float* sW1, const float* sWq,
    const float* sb3, const float* sb1, const float* sWself,
    const float* sXn, const float* sSn) {
    ull xx[8];
#pragma unroll
    for (int ip = 0; ip < 8; ip++)
        xx[ip] = *(const ull*)&sXn[nloc * CC + 2 * ip];

    if (do_q) {
        float qa = 0.f;
#pragma unroll
        for (int c = 0; c < CC; c++) qa = fmaf(sWq[j * 18 + c], sXn[nloc * CC + c], qa);
        g_q[n * HH + j] = qa;
    }
    {
        float u0 = sb1[j], u1 = sb1[j + 8], u2 = sb1[j + 16], u3 = sb1[j + 24];
#pragma unroll
        for (int c = 0; c < CC; c++) {
            float sv = sSn[nloc * CC + c];
            u0 = fmaf(sv, sW1[c * MIDD + j], u0);
            u1 = fmaf(sv, sW1[c * MIDD + j + 8], u1);
            u2 = fmaf(sv, sW1[c * MIDD + j + 16], u2);
            u3 = fmaf(sv, sW1[c * MIDD + j + 24], u3);
        }
        g_u[n * MIDD + j] = u0;
        g_u[n * MIDD + j + 8] = u1;
        g_u[n * MIDD + j + 16] = u2;
        g_u[n * MIDD + j + 24] = u3;
    }
    {
        ull a0 = 0ULL, a1 = 0ULL;
#pragma unroll
        for (int ip = 0; ip < 8; ip++) {
            a0 = fma2(xx[ip], *(const ull*)&sb3[j * 18 + 2 * ip], a0);
            a1 = fma2(xx[ip], *(const ull*)&sb3[(j + 8) * 18 + 2 * ip], a1);
        }
        float l0, h0, l1, h1;
        unpack2(a0, l0, h0);
        unpack2(a1, l1, h1);
        g_PB[n * CC + j * 2] = l0 + h0;
        g_PB[n * CC + j * 2 + 1] = l1 + h1;
    }
    if (do_feats) {
        ull a0 = 0ULL, a1 = 0ULL;
#pragma unroll
        for (int ip = 0; ip < 8; ip++) {
            a0 = fma2(xx[ip], *(const ull*)&sWself[j * 18 + 2 * ip], a0);
            a1 = fma2(xx[ip], *(const ull*)&sWself[(j + 8) * 18 + 2 * ip], a1);
        }
        float l0, h0, l1, h1;
        unpack2(a0, l0, h0);
        unpack2(a1, l1, h1);
        g_feats[n * CC + j] = l0 + h0;
        g_feats[n * CC + 8 + j] = l1 + h1;
    }
}

// ---------------- fused prep: blocks [0,SCB) scatter; [SCB, SCB+NGRID0) layer-0 node prep ----------------
__global__ void __launch_bounds__(NLT, 4)
k_prep(const int* __restrict__ src, const int* __restrict__ dst,
       const float* __restrict__ rel_pos, const int* __restrict__ species,
       const float* __restrict__ Wq, const float* __restrict__ W3,
       const float* __restrict__ b3, const float* __restrict__ W1n,
       const float* __restrict__ b1n) {
    __shared__ __align__(16) float sW1[CC * MIDD];
    __shared__ __align__(16) float sWq[HH * 18];
    __shared__ __align__(16) float sb3[16 * 18];
    __shared__ __align__(16) float sb1[MIDD];
    __shared__ __align__(16) float sXn[NLN * CC];
    __shared__ __align__(16) float sSn[NLN * CC];
    int tid = threadIdx.x;

    if (blockIdx.x < SCB) {
        int e = blockIdx.x * 256 + tid;
        int s = src[e], d = dst[e];
        float px = rel_pos[e * 3 + 0], py = rel_pos[e * 3 + 1], pz = rel_pos[e * 3 + 2];
        float dist = sqrtf(px * px + py * py + pz * pz);
        float xc = dist / CUTOFFF;
        bool in_cut = dist < CUTOFFF;
        float x2 = in_cut ? fminf(xc * xc, 1.f - 1e-6f) : 0.f;
        float scale = in_cut ? expf(3.f - 3.f / (1.f - x2)) : 0.f;

        int ps = atomicAdd(&g_cursrc[s], 1);
        int pd = atomicAdd(&g_curdst[d], 1);
        g_srcS[ps] = s;
        g_distS[ps] = dist;
        g_scaleS[ps] = scale;
        g_es[pd] = make_int2(ps, __float_as_int(scale));

        float Zu = (float)species[s];
        float Zv = (float)species[d];
        float raw = KCOULF * Zu * Zv / (2.f * dist);
        float au = 0.8854f * 0.529f / (__powf(Zu, 0.23f) + __powf(Zv, 0.23f));
        float xx = dist / au;
        float screen = 0.1818f * __expf(-3.2f * xx) + 0.5099f * __expf(-0.9423f * xx)
                     + 0.2802f * __expf(-0.4028f * xx) + 0.02817f * __expf(-0.2016f * xx);
        float contrib = raw * screen * scale;
        if (contrib != 0.f) atomicAdd(&g_coulN[d], contrib);
        return;
    }

    int blk = blockIdx.x - SCB;
    ull wA[8], wB[8];
    load_w3_regs(tid, W3, wA, wB);
    load_node_weights(tid, b3, W1n, b1n, Wq, nullptr, sW1, sWq, sb3, sb1, nullptr);
    int nloc = tid >> 3, j = tid & 7;
    for (int tile = blk; tile < NTILES; tile += NGRID0) {
        __syncthreads();
        int n = tile * NLN + nloc;
        sXn[nloc * CC + j] = g_x[n * CC + j];
        sXn[nloc * CC + 8 + j] = g_x[n * CC + 8 + j];
        sSn[nloc * CC + j] = 0.f;
        sSn[nloc * CC + 8 + j] = 0.f;
        __syncthreads();
        node_prep_a(n, nloc, j, true, false, sW1, sWq, sb3, sb1, nullptr, sXn, sSn);
        prep_P_reg(tile * NLN, tid, wA, wB, sXn);
    }
}

// ---------------- node layer: persistent tiles, pipelined online-softmax + Wproj + prep ----------------
__global__ void __launch_bounds__(NLT, 3)
k_node_layer(int mode,
             const float* __restrict__ Wproj,
             const float* __restrict__ Wq,
             const float* __restrict__ W3,
             const float* __restrict__ b3,
             const float* __restrict__ W1n,
             const float* __restrict__ b1n,
             const float* __restrict__ Wself) {
    __shared__ __align__(16) float sW1[CC * MIDD];
    __shared__ __align__(16) float sWq[HH * 18];
    __shared__ __align__(16) float sWproj[CC * 25];
    __shared__ __align__(16) float sb3[16 * 18];
    __shared__ __align__(16) float sb1[MIDD];
    __shared__ __align__(16) float sWself[16 * 18];
    __shared__ __align__(16) float sAgg[NLN * HH];
    __shared__ __align__(16) float sXold[NLN * CC];
    __shared__ __align__(16) float sXn[NLN * CC];
    __shared__ __align__(16) float sSn[NLN * CC];

    int tid = threadIdx.x;
    int nloc = tid >> 3, j = tid & 7;

    ull wA[8], wB[8];
    load_w3_regs(tid, W3, wA, wB);
    load_node_weights(tid, b3, W1n, b1n,
                      mode != 2 ? Wq : nullptr,
                      mode == 2 ? Wself : nullptr,
                      sW1, sWq, sb3, sb1, sWself);
    for (int idx = tid; idx < CC * 24; idx += NLT)
        sWproj[(idx / 24) * 25 + (idx % 24)] = Wproj[idx];

    for (int tile = blockIdx.x; tile < NTILES; tile += NGRID1) {
        __syncthreads();
        int n = tile * NLN + nloc;
        {
            int beg = g_rdst[n], end = g_rdst[n + 1];
            float qj = g_q[n * HH + j];
            float m = -INFINITY, num = 0.f, den = 0.f;
            if (beg < end) {
                int2 es = g_es[beg];
                float2 vk = *(const float2*)(g_vk + (size_t)es.x * CC + j * 2);
                float sc = __int_as_float(es.y);
#pragma unroll 4
                for (int i = beg + 1; i < end; i++) {
                    int2 es_n = g_es[i];
                    float2 vk_n = *(const float2*)(g_vk + (size_t)es_n.x * CC + j * 2);
                    float sc_n = __int_as_float(es_n.y);
                    float l = vk.y * qj;
                    float mn = fmaxf(m, l);
                    float corr = __expf(m - mn);
                    float p = sc * __expf(l - mn);
                    den = den * corr + p;
                    num = fmaf(num, corr, p * vk.x);
                    m = mn;
                    vk = vk_n;
                    sc = sc_n;
                }
                float l = vk.y * qj;
                float mn = fmaxf(m, l);
                float corr = __expf(m - mn);
                float p = sc * __expf(l - mn);
                den = den * corr + p;
                num = fmaf(num, corr, p * vk.x);
            }
            sAgg[nloc * HH + j] = num / fmaxf(den, 1e-20f);
            sXold[nloc * CC + j] = g_x[n * CC + j];
            sXold[nloc * CC + 8 + j] = g_x[n * CC + 8 + j];
            __syncthreads();
            float xn0 = 0.f, xn1 = 0.f;
#pragma unroll
            for (int k = 0; k < 8; k++) {
                float a = sAgg[nloc * HH + k];
                xn0 = fmaf(sWproj[j * 25 + k], a, xn0);
                xn1 = fmaf(sWproj[(j + 8) * 25 + k], a, xn1);
            }
#pragma unroll
            for (int k = 0; k < CC; k++) {
                float xo = sXold[nloc * CC + k];
                xn0 = fmaf(sWproj[j * 25 + 8 + k], xo, xn0);
                xn1 = fmaf(sWproj[(j + 8) * 25 + 8 + k], xo, xn1);
            }
            float s0 = g_S[n * CC + j] + xn0;
            float s1 = g_S[n * CC + 8 + j] + xn1;
            g_x[n * CC + j] = xn0;     g_x[n * CC + 8 + j] = xn1;
            g_S[n * CC + j] = s0;      g_S[n * CC + 8 + j] = s1;
            sXn[nloc * CC + j] = xn0;  sXn[nloc * CC + 8 + j] = xn1;
            sSn[nloc * CC + j] = s0;   sSn[nloc * CC + 8 + j] = s1;
            __syncthreads();
        }
        node_prep_a(n, nloc, j, mode != 2, mode == 2,
                    sW1, sWq, sb3, sb1, sWself, sXn, sSn);
        prep_P_reg(tile * NLN, tid, wA, wB, sXn);
    }
}

// ---------------- edge kernel: pair/thread + warp P staging + packed-h2 register diet ----------------
#define PSLOTS 6
#define PROWS 516               // row stride (floats)

__global__ void __launch_bounds__(128, 3)
k_edge(const float* __restrict__ W1, const float* __restrict__ W2,
       const float* __restrict__ b2) {
    __shared__ __align__(16) ull sW2p[512];
    __shared__ float sw15[MIDD];
    __shared__ __align__(16) ull sB2p[16];
    __shared__ __align__(16) float sSt[4][32 * 36];
    extern __shared__ __align__(16) float sPst[];   // [4 warps][PSLOTS * PROWS]
    int tid = threadIdx.x;
    int lane = tid & 31, w = tid >> 5;
    for (int i = tid; i < 512; i += 128) sW2p[i] = ((const ull*)W2)[i];
    if (tid < MIDD) sw15[tid] = W1[15 * MIDD + tid];
    if (tid < 16) sB2p[tid] = ((const ull*)b2)[tid];
    __syncthreads();

    int t = blockIdx.x * 128 + tid;
    int e0 = 2 * t;
    int s = g_srcS[e0];
    float2 dd = *(const float2*)(g_distS + e0);
    float2 sc = *(const float2*)(g_scaleS + e0);
    float da = dd.x, db = dd.y;
    float bsa = Y0F * sc.x, bsb = Y0F * sc.y;

    // ---- warp src-dedup + cooperative P staging ----
    const unsigned full = 0xffffffffu;
    int sprev = __shfl_up_sync(full, s, 1);
    bool leader = (lane == 0) || (s != sprev);
    unsigned lmask = __ballot_sync(full, leader);
    int nlead = __popc(lmask);
    unsigned lml;
    asm("mov.u32 %0, %%lanemask_le;" : "=r"(lml));
    int slot = __popc(lmask & lml) - 1;
    bool use_s = (nlead <= PSLOTS);
    float* wst = sPst + w * (PSLOTS * PROWS);
    if (use_s) {
        unsigned rem = lmask;
        for (int sl = 0; sl < nlead; sl++) {
            int ldr = __ffs(rem) - 1;
            rem &= rem - 1;
            int rs = __shfl_sync(full, s, ldr);
            const float4* gp = (const float4*)(g_P + (size_t)rs * 512);
            float* sp = wst + sl * PROWS;
#pragma unroll
            for (int it = 0; it < 4; it++) {
                float4 v = gp[it * 32 + lane];
                *(float4*)&sp[(it * 32 + lane) * 4] = v;
            }
        }
    }

    // u (shared by both edges)
    float u[MIDD];
    {
        const float4* up = (const float4*)(g_u + (size_t)s * MIDD);
#pragma unroll
        for (int k = 0; k < 8; k++) {
            float4 v = up[k];
            u[4 * k] = v.x; u[4 * k + 1] = v.y; u[4 * k + 2] = v.z; u[4 * k + 3] = v.w;
        }
    }

    // W2 matvec; accumulators stay PACKED (no h2 arrays)
    ull acca[16], accb[16];
#pragma unroll
    for (int jp = 0; jp < 16; jp++) { acca[jp] = sB2p[jp]; accb[jp] = sB2p[jp]; }
#pragma unroll
    for (int i2 = 0; i2 < MIDD; i2++) {
        float w15v = sw15[i2];
        float ha = fmaxf(fmaf(da, w15v, u[i2]), 0.f);
        float hb = fmaxf(fmaf(db, w15v, u[i2]), 0.f);
        ull xa = pack2(ha, ha);
        ull xb = pack2(hb, hb);
#pragma unroll
        for (int jq = 0; jq < 8; jq++) {
            ulonglong2 wv = *(const ulonglong2*)&sW2p[i2 * 16 + jq * 2];
            acca[2 * jq]     = fma2(xa, wv.x, acca[2 * jq]);
            acca[2 * jq + 1] = fma2(xa, wv.y, acca[2 * jq + 1]);
            accb[2 * jq]     = fma2(xb, wv.x, accb[2 * jq]);
            accb[2 * jq + 1] = fma2(xb, wv.y, accb[2 * jq + 1]);
        }
    }

    ull ka[8], kb[8];
    {
        const ulonglong2* pbp = (const ulonglong2*)(g_PB + (size_t)s * CC);
#pragma unroll
        for (int q = 0; q < 4; q++) {
            ulonglong2 pb = pbp[q];
            ka[2 * q] = pb.x; ka[2 * q + 1] = pb.y;
            kb[2 * q] = pb.x; kb[2 * q + 1] = pb.y;
        }
    }
    __syncwarp();
    const ull* Pp = use_s ? (const ull*)(wst + slot * PROWS)
                          : (const ull*)(g_P + (size_t)s * 512);
#pragma unroll
    for (int mq = 0; mq < 8; mq++) {
        // unpack + relu the h2 quad for this mq on the fly (consumes acc registers)
        float a0, a1, a2, a3, b0, b1, b2v, b3v;
        unpack2(acca[2 * mq], a0, a1);
        unpack2(acca[2 * mq + 1], a2, a3);
        unpack2(accb[2 * mq], b0, b1);
        unpack2(accb[2 * mq + 1], b2v, b3v);
        a0 = fmaxf(a0, 0.f); a1 = fmaxf(a1, 0.f);
        a2 = fmaxf(a2, 0.f); a3 = fmaxf(a3, 0.f);
        b0 = fmaxf(b0, 0.f); b1 = fmaxf(b1, 0.f);
        b2v = fmaxf(b2v, 0.f); b3v = fmaxf(b3v, 0.f);
        ull xa0 = pack2(a0, a0), xa1 = pack2(a1, a1);
        ull xa2 = pack2(a2, a2), xa3 = pack2(a3, a3);
        ull xb0 = pack2(b0, b0), xb1 = pack2(b1, b1);
        ull xb2 = pack2(b2v, b2v), xb3 = pack2(b3v, b3v);
#pragma unroll
        for (int j = 0; j < 8; j++) {
            ulonglong2 pA = *(const ulonglong2*)(Pp + mq * 32 + j * 4);
            ulonglong2 pB = *(const ulonglong2*)(Pp + mq * 32 + j * 4 + 2);
            ka[j] = fma2(xa0, pA.x, ka[j]);
            ka[j] = fma2(xa1, pA.y, ka[j]);
            ka[j] = fma2(xa2, pB.x, ka[j]);
            ka[j] = fma2(xa3, pB.y, ka[j]);
            kb[j] = fma2(xb0, pA.x, kb[j]);
            kb[j] = fma2(xb1, pA.y, kb[j]);
            kb[j] = fma2(xb2, pB.x, kb[j]);
            kb[j] = fma2(xb3, pB.y, kb[j]);
        }
    }

    float* st = sSt[w];
#pragma unroll
    for (int q = 0; q < 4; q++) {
        float a0, a1, a2, a3;
        unpack2(ka[2 * q], a0, a1);
        unpack2(ka[2 * q + 1], a2, a3);
        *(float4*)&st[lane * 36 + q * 4] = make_float4(a0 * bsa, a1 * bsa, a2 * bsa, a3 * bsa);
    }
#pragma unroll
    for (int q = 0; q < 4; q++) {
        float a0, a1, a2, a3;
        unpack2(kb[2 * q], a0, a1);
        unpack2(kb[2 * q + 1], a2, a3);
        *(float4*)&st[lane * 36 + 16 + q * 4] = make_float4(a0 * bsb, a1 * bsb, a2 * bsb, a3 * bsb);
    }
    __syncwarp();
    float4* gbase = (float4*)(g_vk + (size_t)(blockIdx.x * 256 + w * 64) * CC);
#pragma unroll
    for (int g = 0; g < 8; g++) {
        int f = g * 32 + lane;
        int owner = f >> 3, q = f & 7;
        gbase[f] = *(const float4*)&st[owner * 36 + q * 4];
    }
}

// ---------------- final ----------------
__device__ __forceinline__ float siluf(float x) { return x / (1.f + __expf(-x)); }

__global__ void k_final(const int* __restrict__ species, const float* __restrict__ emb,
                        const float* __restrict__ W1, const float* __restrict__ b1,
                        const float* __restrict__ W2, const float* __restrict__ b2,
                        const float* __restrict__ W3, const float* __restrict__ b3,
                        float* __restrict__ out) {
    __shared__ float sFeat[16 * 17];
    __shared__ float sEmb[16 * 17];
    __shared__ float sH[16 * 17];
    __shared__ float sRed[16];
    int tid = threadIdx.x;
    int nloc = tid >> 4, o = tid & 15;
    int n = blockIdx.x * 16 + nloc;
    int beg = g_rdst[n], end = g_rdst[n + 1];
    int o2 = (o < 8) ? o * 2 : (o - 8) * 2 + 1;
    float f = g_feats[n * CC + o];
    if (beg < end) {
        int ei = g_es[beg].x;
        float v = g_vk[(size_t)ei * CC + o2];
#pragma unroll 4
        for (int i = beg + 1; i < end; i++) {
            int ei_n = g_es[i].x;
            float v_n = g_vk[(size_t)ei_n * CC + o2];
            f += v;
            v = v_n;
        }
        f += v;
    }
    sFeat[nloc * 17 + o] = f;
    int sp = species[n] - 1;
    sEmb[nloc * 17 + o] = emb[sp * CC + o];
    __syncthreads();

    float h1 = b1[o];
#pragma unroll
    for (int k = 0; k < CC; k++) h1 = fmaf(sEmb[nloc * 17 + k], W1[k * CC + o], h1);
#pragma unroll
    for (int k = 0; k < CC; k++) h1 = fmaf(sFeat[nloc * 17 + k], W1[(CC + k) * CC + o], h1);
    sH[nloc * 17 + o] = siluf(h1);
    __syncthreads();

    float h2 = b2[o];
#pragma unroll
    for (int k = 0; k < CC; k++) h2 = fmaf(sH[nloc * 17 + k], W2[k * CC + o], h2);
    h2 = siluf(h2);

    float part = h2 * W3[o];
#pragma unroll
    for (int off = 8; off > 0; off >>= 1)
        part += __shfl_down_sync(0xffffffffu, part, off, 16);
    if (o == 0) sRed[nloc] = part + b3[0] + g_coulN[n];
    __syncthreads();
    if (tid == 0) {
        float acc = 0.f;
#pragma unroll
        for (int k = 0; k < 16; k++) acc += sRed[k];
        atomicAdd(out, acc);
    }
}

// ---------------- host launch ----------------
extern "C" void kernel_launch(void* const* d_in, const int* in_sizes, int n_in,
                              void* d_out, int out_size) {
    const int* species  = (const int*)d_in[0];
    const int* src      = (const int*)d_in[1];
    const int* dst      = (const int*)d_in[2];
    const float* rel_pos = (const float*)d_in[3];
    const float* emb    = (const float*)d_in[4];
    const float* kv_W1  = (const float*)d_in[5];
    const float* kv_b1  = (const float*)d_in[6];
    const float* kv_W2  = (const float*)d_in[7];
    const float* kv_b2  = (const float*)d_in[8];
    const float* kv_W3  = (const float*)d_in[9];
    const float* kv_b3  = (const float*)d_in[10];
    const float* Wq     = (const float*)d_in[11];
    const float* Wproj  = (const float*)d_in[12];
    const float* fin_W1 = (const float*)d_in[13];
    const float* fin_b1 = (const float*)d_in[14];
    const float* fin_W2 = (const float*)d_in[15];
    const float* fin_b2 = (const float*)d_in[16];
    const float* fin_W3 = (const float*)d_in[17];
    const float* fin_b3 = (const float*)d_in[18];
    const float* Wself  = (const float*)d_in[19];
    const float* mlp_W1 = (const float*)d_in[20];
    const float* mlp_b1 = (const float*)d_in[21];
    const float* mlp_W2 = (const float*)d_in[22];
    const float* mlp_b2 = (const float*)d_in[23];
    const float* mlp_W3 = (const float*)d_in[24];
    const float* mlp_b3 = (const float*)d_in[25];
    float* out = (float*)d_out;

    const int EB = EE / 256;         // 2048
    const int EDGB = EENP / 256;     // 2176
    const int PSTB = 4 * PSLOTS * PROWS * sizeof(float);

    static int attr_set = 0;
    if (!attr_set) {
        cudaFuncSetAttribute(k_edge, cudaFuncAttributeMaxDynamicSharedMemorySize, PSTB);
        attr_set = 1;
    }

    k_init<<<EB, 256>>>(species, emb, out, src, dst);
    k_scan<<<2, 1024>>>();
    k_prep<<<SCB + NGRID0, NLT>>>(src, dst, rel_pos, species,
                                  Wq, kv_W3, kv_b3, kv_W1, kv_b1);

    for (int l = 0; l < 4; l++) {
        k_edge<<<EDGB, 128, PSTB>>>(kv_W1 + (size_t)l * CC * MIDD,
                                    kv_W2 + (size_t)l * MIDD * MIDD,
                                    kv_b2 + (size_t)l * MIDD);
        if (l < 3) {
            k_node_layer<<<NGRID1, NLT>>>(1,
                Wproj + (size_t)l * CC * 24,
                Wq + (size_t)(l + 1) * HH * CC,
                kv_W3 + (size_t)(l + 1) * MIDD * 256,
                kv_b3 + (size_t)(l + 1) * 256,
                kv_W1 + (size_t)(l + 1) * CC * MIDD,
                kv_b1 + (size_t)(l + 1) * MIDD,
                nullptr);
        } else {
            k_node_layer<<<NGRID1, NLT>>>(2,
                Wproj + (size_t)l * CC * 24,
                nullptr,
                fin_W3, fin_b3, fin_W1, fin_b1, Wself);
        }
    }
    k_edge<<<EDGB, 128, PSTB>>>(fin_W1, fin_W2, fin_b2);
    k_final<<<NN / 16, 256>>>(species, emb, mlp_W1, mlp_b1, mlp_W2, mlp_b2,
                              mlp_W3, mlp_b3, out);
}